// round 3
// baseline (speedup 1.0000x reference)
#include <cuda_runtime.h>
#include <math.h>

#define DINLINE __device__ __forceinline__
typedef unsigned long long ull;

// ---------------------------------------------------------------------------
// Fixed problem dimensions (B=4, grid 513, coef 512, epoch=101 -> K=2)
// ---------------------------------------------------------------------------
namespace fns {
constexpr int NB = 4;
constexpr int NG = 513;
constexpr int NI = 511;
constexpr int NC = 512;
constexpr long long NN  = (long long)NG * NG;
constexpr long long NCC = (long long)NC * NC;
constexpr long long NII = (long long)NI * NI;
constexpr long long NIG = (long long)NI * NG;
constexpr int NBLK_A = 128;
constexpr int NBLK_N = 256;
constexpr int KSTEPS = 2;
}
using namespace fns;

// ---------------------------------------------------------------------------
// Packed f32x2 helpers (Blackwell FFMA2 path)
// ---------------------------------------------------------------------------
DINLINE ull ffma2(ull a, ull b, ull c)
{
    ull d;
    asm("fma.rn.f32x2 %0, %1, %2, %3;" : "=l"(d) : "l"(a), "l"(b), "l"(c));
    return d;
}
DINLINE ull pack2(float x, float y)
{
    ull d;
    asm("mov.b64 %0, {%1, %2};" : "=l"(d) : "f"(x), "f"(y));
    return d;
}
DINLINE float2 unpack2(ull v)
{
    float2 r;
    asm("mov.b64 {%0, %1}, %2;" : "=f"(r.x), "=f"(r.y) : "l"(v));
    return r;
}

// ---------------------------------------------------------------------------
// Static device scratch
// ---------------------------------------------------------------------------
__device__ float  g_x   [NB * NN];
__device__ float  g_x2  [NB * NN];
__device__ float  g_r   [NB * NN];
__device__ float  g_e   [NB * NN];
__device__ float  g_rh  [NB * NN];
__device__ float  g_dinv[NB * NII];
__device__ float  g_S   [NG * (long long)NI];  // S[p][j], ld=NI
__device__ float  g_St  [NIG];                 // St[j][p], ld=NG
__device__ float2 g_G   [NIG];                 // G[s][u],  ld=NG
__device__ float2 g_Gt  [NIG];                 // Gt[u][s], ld=NI
__device__ float  g_U   [NB * NIG];            // V = r_int * St, 511x513, ld=NG
__device__ float2 g_cA  [NB * 4 * NN];
__device__ float2 g_cB  [NB * 4 * NN];
__device__ float2 g_cC  [NB * NN];
__device__ float2 g_W   [NB * NIG];            // 513x511, ld=NI
__device__ double g_pd1 [2048];
__device__ double g_pd2 [2048];
__device__ float  g_alpha[NB];

// ---------------------------------------------------------------------------
// Darcy FEM 9-point stencil
// ---------------------------------------------------------------------------
DINLINE float darcy_at(const float* __restrict__ x,
                       const float* __restrict__ a, int i, int j)
{
    const float c23 = 2.f / 3.f, c16 = -1.f / 6.f, c13 = -1.f / 3.f;
    float s = 0.f;
#pragma unroll
    for (int u = 0; u < 2; u++) {
#pragma unroll
        for (int v = 0; v < 2; v++) {
            int I = i - 1 + u, J = j - 1 + v;
            float av = a[(long long)I * NC + J];
            float k0, k1, k2, k3;
            if (u == 0 && v == 0) { k0 = c16; k1 = c23; k2 = c16; k3 = c13; }
            else if (u == 0 && v == 1) { k0 = c23; k1 = c16; k2 = c13; k3 = c16; }
            else if (u == 1 && v == 0) { k0 = c13; k1 = c16; k2 = c23; k3 = c16; }
            else                        { k0 = c16; k1 = c13; k2 = c16; k3 = c23; }
            s += av * (k3 * x[(long long)I * NG + J]
                     + k2 * x[(long long)I * NG + J + 1]
                     + k0 * x[(long long)(I + 1) * NG + J]
                     + k1 * x[(long long)(I + 1) * NG + J + 1]);
        }
    }
    return s;
}

// ---------------------------------------------------------------------------
// Setup kernels
// ---------------------------------------------------------------------------
__global__ void k_precS(float* __restrict__ S, float* __restrict__ St)
{
    int idx = blockIdx.x * blockDim.x + threadIdx.x;
    if (idx >= NG * NI) return;
    int p = idx / NI, j = idx - p * NI;
    int m = (j + 1) * (p - 256);
    int mm = ((m % 1024) + 1024) % 1024;
    float v = sinpif((float)mm / 512.f);
    S[idx] = v;
    St[(long long)j * NG + p] = v;
}

__global__ void k_precG(float2* __restrict__ G, float2* __restrict__ Gt)
{
    int idx = blockIdx.x * blockDim.x + threadIdx.x;
    if (idx >= NI * NG) return;
    int s = idx / NG, u = idx - s * NG;
    int t = (u - 255) * s;
    int tm = ((t % 1025) + 1025) % 1025;
    float xr = 2.f * (float)tm / 1025.f;
    float2 g = make_float2(cospif(xr), -sinpif(xr));
    G[idx] = g;
    Gt[(long long)u * NI + s] = g;
}

__global__ void k_dinv(const float* __restrict__ a, float* __restrict__ dinv)
{
    int b = blockIdx.z;
    int q = blockIdx.x * 16 + threadIdx.x;
    int p = blockIdx.y * 16 + threadIdx.y;
    if (p >= NI || q >= NI) return;
    const float* ap = a + (long long)b * NCC;
    float s = ap[(long long)p * NC + q] + ap[(long long)p * NC + q + 1]
            + ap[(long long)(p + 1) * NC + q] + ap[(long long)(p + 1) * NC + q + 1];
    dinv[(long long)b * NII + (long long)p * NI + q] = 1.f / ((2.f / 3.f) * s);
}

__global__ void k_zero3(float* __restrict__ x, float* __restrict__ x2,
                        float* __restrict__ e)
{
    long long idx = (long long)blockIdx.x * blockDim.x + threadIdx.x;
    long long tot = (long long)NB * NN;
    if (idx >= tot) return;
    x[idx] = 0.f; x2[idx] = 0.f; e[idx] = 0.f;
}

// ---------------------------------------------------------------------------
// Jacobi sweep + residual
// ---------------------------------------------------------------------------
__global__ __launch_bounds__(256)
void k_jacobi(const float* __restrict__ xin, float* __restrict__ xout,
              const float* __restrict__ f, const float* __restrict__ a,
              const float* __restrict__ dinv)
{
    int b = blockIdx.z;
    int j = blockIdx.x * 16 + threadIdx.x + 1;
    int i = blockIdx.y * 16 + threadIdx.y + 1;
    if (i > NI || j > NI) return;
    const float* xp = xin + (long long)b * NN;
    const float* ap = a + (long long)b * NCC;
    long long o = (long long)b * NN + (long long)i * NG + j;
    float d = darcy_at(xp, ap, i, j);
    float r = f[o] - d;
    xout[o] = xp[(long long)i * NG + j]
            + 0.75f * dinv[(long long)b * NII + (long long)(i - 1) * NI + (j - 1)] * r;
}

__global__ __launch_bounds__(256)
void k_resid(const float* __restrict__ x, const float* __restrict__ f,
             const float* __restrict__ a, float* __restrict__ r)
{
    int b = blockIdx.z;
    int j = blockIdx.x * 16 + threadIdx.x;
    int i = blockIdx.y * 16 + threadIdx.y;
    if (i >= NG || j >= NG) return;
    long long o = (long long)b * NN + (long long)i * NG + j;
    float d = 0.f;
    if (i > 0 && j > 0 && i < NG - 1 && j < NG - 1)
        d = darcy_at(x + (long long)b * NN, a + (long long)b * NCC, i, j);
    r[o] = f[o] - d;
}

// ---------------------------------------------------------------------------
// Real SGEMM (f32x2): C = alpha * A(MxK) * B(KxN). Tile 64x128, BK=16,
// 256 threads, microtile 4x8 (N packed in f32x2 pairs).
// ---------------------------------------------------------------------------
__global__ __launch_bounds__(256)
void k_sgemm2(const float* __restrict__ A, int lda, long long sA,
              const float* __restrict__ B, int ldb, long long sB,
              float* __restrict__ C, int ldc, long long sC,
              int M, int N, int K, float alpha)
{
    __shared__ __align__(16) float As[16][64];
    __shared__ __align__(16) float Bs[16][128];
    int b = blockIdx.z;
    A += (long long)b * sA; B += (long long)b * sB; C += (long long)b * sC;
    int m0 = blockIdx.y * 64, n0 = blockIdx.x * 128;
    int tid = threadIdx.x;
    int ty = tid >> 4, tx = tid & 15;
    int mt = ty * 4, nt = tx * 8;
    ull acc[4][4];
#pragma unroll
    for (int i = 0; i < 4; i++)
#pragma unroll
        for (int p = 0; p < 4; p++) acc[i][p] = 0ULL;

    for (int kt = 0; kt < K; kt += 16) {
#pragma unroll
        for (int e = 0; e < 4; e++) {
            int idx = tid + e * 256;
            int m = idx >> 4, k = idx & 15;
            int gm = m0 + m, gk = kt + k;
            As[k][m] = (gm < M && gk < K) ? A[(long long)gm * lda + gk] : 0.f;
        }
#pragma unroll
        for (int e = 0; e < 8; e++) {
            int idx = tid + e * 256;
            int k = idx >> 7, n = idx & 127;
            int gk = kt + k, gn = n0 + n;
            Bs[k][n] = (gk < K && gn < N) ? B[(long long)gk * ldb + gn] : 0.f;
        }
        __syncthreads();
#pragma unroll
        for (int k = 0; k < 16; k++) {
            float4 a4 = *(const float4*)&As[k][mt];
            ull ad0 = pack2(a4.x, a4.x), ad1 = pack2(a4.y, a4.y);
            ull ad2 = pack2(a4.z, a4.z), ad3 = pack2(a4.w, a4.w);
            const ull* bp = (const ull*)&Bs[k][nt];
            ull b0 = bp[0], b1 = bp[1], b2 = bp[2], b3 = bp[3];
            acc[0][0] = ffma2(ad0, b0, acc[0][0]); acc[0][1] = ffma2(ad0, b1, acc[0][1]);
            acc[0][2] = ffma2(ad0, b2, acc[0][2]); acc[0][3] = ffma2(ad0, b3, acc[0][3]);
            acc[1][0] = ffma2(ad1, b0, acc[1][0]); acc[1][1] = ffma2(ad1, b1, acc[1][1]);
            acc[1][2] = ffma2(ad1, b2, acc[1][2]); acc[1][3] = ffma2(ad1, b3, acc[1][3]);
            acc[2][0] = ffma2(ad2, b0, acc[2][0]); acc[2][1] = ffma2(ad2, b1, acc[2][1]);
            acc[2][2] = ffma2(ad2, b2, acc[2][2]); acc[2][3] = ffma2(ad2, b3, acc[2][3]);
            acc[3][0] = ffma2(ad3, b0, acc[3][0]); acc[3][1] = ffma2(ad3, b1, acc[3][1]);
            acc[3][2] = ffma2(ad3, b2, acc[3][2]); acc[3][3] = ffma2(ad3, b3, acc[3][3]);
        }
        __syncthreads();
    }

#pragma unroll
    for (int i = 0; i < 4; i++) {
        int gm = m0 + mt + i;
        if (gm >= M) continue;
#pragma unroll
        for (int p = 0; p < 4; p++) {
            float2 v = unpack2(acc[i][p]);
            int gn = n0 + nt + 2 * p;
            if (gn < N)     C[(long long)gm * ldc + gn]     = alpha * v.x;
            if (gn + 1 < N) C[(long long)gm * ldc + gn + 1] = alpha * v.y;
        }
    }
}

// ---------------------------------------------------------------------------
// Full complex GEMM (f32x2): C(MxN cplx) = A(MxK cplx) * B(KxN cplx).
// Tile 64x64, BK=16, 256 threads, 4x4 complex microtile.
// Smem holds pre-transformed operand forms: (ar,ar),(ai,ai),(br,bi),(-bi,br).
// ---------------------------------------------------------------------------
__global__ __launch_bounds__(256)
void k_cgemm_full(const float2* __restrict__ A, int lda, long long sA,
                  const float2* __restrict__ B, int ldb, long long sB,
                  float2* __restrict__ C, int ldc, long long sC,
                  int M, int N, int K)
{
    __shared__ __align__(16) ull As1[16][64];
    __shared__ __align__(16) ull As2[16][64];
    __shared__ __align__(16) ull Bs1[16][64];
    __shared__ __align__(16) ull Bs2[16][64];
    int b = blockIdx.z;
    A += (long long)b * sA; B += (long long)b * sB; C += (long long)b * sC;
    int m0 = blockIdx.y * 64, n0 = blockIdx.x * 64;
    int tid = threadIdx.x;
    int ty = tid >> 4, tx = tid & 15;
    int mt = ty * 4, nt = tx * 4;
    ull acc[4][4];
#pragma unroll
    for (int i = 0; i < 4; i++)
#pragma unroll
        for (int j = 0; j < 4; j++) acc[i][j] = 0ULL;

    for (int kt = 0; kt < K; kt += 16) {
#pragma unroll
        for (int e = 0; e < 4; e++) {
            int idx = tid + e * 256;
            int m = idx >> 4, k = idx & 15;
            int gm = m0 + m, gk = kt + k;
            float2 a = (gm < M && gk < K) ? A[(long long)gm * lda + gk]
                                          : make_float2(0.f, 0.f);
            As1[k][m] = pack2(a.x, a.x);
            As2[k][m] = pack2(a.y, a.y);
            int k2 = idx >> 6, n = idx & 63;
            int gk2 = kt + k2, gn = n0 + n;
            float2 bb = (gk2 < K && gn < N) ? B[(long long)gk2 * ldb + gn]
                                            : make_float2(0.f, 0.f);
            Bs1[k2][n] = pack2(bb.x, bb.y);
            Bs2[k2][n] = pack2(-bb.y, bb.x);
        }
        __syncthreads();
#pragma unroll
        for (int k = 0; k < 16; k++) {
            ull a1[4], a2[4], b1[4], b2[4];
            *(ulonglong2*)&a1[0] = *(const ulonglong2*)&As1[k][mt];
            *(ulonglong2*)&a1[2] = *(const ulonglong2*)&As1[k][mt + 2];
            *(ulonglong2*)&a2[0] = *(const ulonglong2*)&As2[k][mt];
            *(ulonglong2*)&a2[2] = *(const ulonglong2*)&As2[k][mt + 2];
            *(ulonglong2*)&b1[0] = *(const ulonglong2*)&Bs1[k][nt];
            *(ulonglong2*)&b1[2] = *(const ulonglong2*)&Bs1[k][nt + 2];
            *(ulonglong2*)&b2[0] = *(const ulonglong2*)&Bs2[k][nt];
            *(ulonglong2*)&b2[2] = *(const ulonglong2*)&Bs2[k][nt + 2];
#pragma unroll
            for (int i = 0; i < 4; i++)
#pragma unroll
                for (int j = 0; j < 4; j++) {
                    acc[i][j] = ffma2(a1[i], b1[j], acc[i][j]);
                    acc[i][j] = ffma2(a2[i], b2[j], acc[i][j]);
                }
        }
        __syncthreads();
    }

#pragma unroll
    for (int i = 0; i < 4; i++) {
        int gm = m0 + mt + i;
        if (gm >= M) continue;
#pragma unroll
        for (int j = 0; j < 4; j++) {
            int gn = n0 + nt + j;
            if (gn >= N) continue;
            C[(long long)gm * ldc + gn] = unpack2(acc[i][j]);
        }
    }
}

// ---------------------------------------------------------------------------
// Re-only complex GEMM (f32x2): C(MxN real) = Re(A(MxK cplx) * B(KxN cplx)).
// One FFMA2 per complex MAC: (ar,ai)*(br,-bi), horizontal add at epilogue.
// Tile 64x128, BK=16, 256 threads, microtile 4x8.
// ---------------------------------------------------------------------------
__global__ __launch_bounds__(256)
void k_cgemm_re(const float2* __restrict__ A, int lda, long long sA,
                const float2* __restrict__ B, int ldb, long long sB,
                float* __restrict__ C, int ldc, long long sC,
                int M, int N, int K)
{
    __shared__ __align__(16) ull As[16][64];
    __shared__ __align__(16) ull Bs[16][128];
    int b = blockIdx.z;
    A += (long long)b * sA; B += (long long)b * sB; C += (long long)b * sC;
    int m0 = blockIdx.y * 64, n0 = blockIdx.x * 128;
    int tid = threadIdx.x;
    int ty = tid >> 4, tx = tid & 15;
    int mt = ty * 4, nt = tx * 8;
    ull acc[4][8];
#pragma unroll
    for (int i = 0; i < 4; i++)
#pragma unroll
        for (int j = 0; j < 8; j++) acc[i][j] = 0ULL;

    for (int kt = 0; kt < K; kt += 16) {
#pragma unroll
        for (int e = 0; e < 4; e++) {
            int idx = tid + e * 256;
            int m = idx >> 4, k = idx & 15;
            int gm = m0 + m, gk = kt + k;
            float2 a = (gm < M && gk < K) ? A[(long long)gm * lda + gk]
                                          : make_float2(0.f, 0.f);
            As[k][m] = pack2(a.x, a.y);
        }
#pragma unroll
        for (int e = 0; e < 8; e++) {
            int idx = tid + e * 256;
            int k = idx >> 7, n = idx & 127;
            int gk = kt + k, gn = n0 + n;
            float2 bb = (gk < K && gn < N) ? B[(long long)gk * ldb + gn]
                                           : make_float2(0.f, 0.f);
            Bs[k][n] = pack2(bb.x, -bb.y);
        }
        __syncthreads();
#pragma unroll
        for (int k = 0; k < 16; k++) {
            ull av[4], bv[8];
            *(ulonglong2*)&av[0] = *(const ulonglong2*)&As[k][mt];
            *(ulonglong2*)&av[2] = *(const ulonglong2*)&As[k][mt + 2];
            *(ulonglong2*)&bv[0] = *(const ulonglong2*)&Bs[k][nt];
            *(ulonglong2*)&bv[2] = *(const ulonglong2*)&Bs[k][nt + 2];
            *(ulonglong2*)&bv[4] = *(const ulonglong2*)&Bs[k][nt + 4];
            *(ulonglong2*)&bv[6] = *(const ulonglong2*)&Bs[k][nt + 6];
#pragma unroll
            for (int i = 0; i < 4; i++)
#pragma unroll
                for (int j = 0; j < 8; j++)
                    acc[i][j] = ffma2(av[i], bv[j], acc[i][j]);
        }
        __syncthreads();
    }

#pragma unroll
    for (int i = 0; i < 4; i++) {
        int gm = m0 + mt + i;
        if (gm >= M) continue;
#pragma unroll
        for (int j = 0; j < 8; j++) {
            int gn = n0 + nt + j;
            if (gn >= N) continue;
            float2 v = unpack2(acc[i][j]);
            C[(long long)gm * ldc + gn] = v.x + v.y;
        }
    }
}

// ---------------------------------------------------------------------------
// Symmetry mirror kernels for the sine transform
// ---------------------------------------------------------------------------
__global__ void k_mirror_u(float* __restrict__ U)
{
    int b = blockIdx.z;
    int t = blockIdx.x * 16 + threadIdx.x + 1;   // 1..256
    int i = blockIdx.y * 16 + threadIdx.y;       // 0..510
    if (t > 256 || i >= NI) return;
    float* Ub = U + (long long)b * NIG;
    Ub[(long long)i * NG + (256 - t)] = -Ub[(long long)i * NG + (256 + t)];
}

__global__ void k_mirror_rh(float* __restrict__ rh)
{
    int b = blockIdx.z;
    int q = blockIdx.x * 16 + threadIdx.x;       // 0..512
    int t = blockIdx.y * 16 + threadIdx.y + 1;   // 1..256
    if (q >= NG || t > 256) return;
    float* R = rh + (long long)b * NN;
    R[(long long)(256 - t) * NG + q] = -R[(long long)(256 + t) * NG + q];
}

// ---------------------------------------------------------------------------
// Real-input complex conv (first forward conv): Y[o] = rh * (w1r[o] + i w1i[o])
// ---------------------------------------------------------------------------
__global__ __launch_bounds__(256)
void k_conv_r41(const float* __restrict__ X, float2* __restrict__ Y,
                const float* __restrict__ wr, const float* __restrict__ wi)
{
    int b = blockIdx.z;
    __shared__ ull ws[36];
    int t = threadIdx.y * 16 + threadIdx.x;
    if (t < 36) ws[t] = pack2(wr[b * 36 + t], wi[b * 36 + t]);
    __syncthreads();
    int q = blockIdx.x * 16 + threadIdx.x;
    int p = blockIdx.y * 16 + threadIdx.y;
    if (p >= NG || q >= NG) return;
    const float* Xb = X + (long long)b * NN;
    ull acc[4] = {0ULL, 0ULL, 0ULL, 0ULL};
#pragma unroll
    for (int dy = 0; dy < 3; dy++) {
        int ii = p + dy - 1;
#pragma unroll
        for (int dx = 0; dx < 3; dx++) {
            int jj = q + dx - 1;
            float xv = 0.f;
            if (ii >= 0 && ii < NG && jj >= 0 && jj < NG)
                xv = Xb[(long long)ii * NG + jj];
            ull xx = pack2(xv, xv);
            int tap = dy * 3 + dx;
#pragma unroll
            for (int o = 0; o < 4; o++)
                acc[o] = ffma2(xx, ws[o * 9 + tap], acc[o]);
        }
    }
    float2* Yb = Y + (long long)b * 4 * NN;
    long long po = (long long)p * NG + q;
#pragma unroll
    for (int o = 0; o < 4; o++) Yb[(long long)o * NN + po] = unpack2(acc[o]);
}

// ---------------------------------------------------------------------------
// Complex multi-channel 3x3 conv (pad=1), f32x2 inner (2 FFMA2 per cmac).
// conjt=1 applies conjT(w) via index remap + conjugation.
// ---------------------------------------------------------------------------
template<int CO, int CI>
__global__ __launch_bounds__(256)
void k_conv(const float2* __restrict__ X, float2* __restrict__ Y,
            const float* __restrict__ wr, const float* __restrict__ wi,
            int conjt)
{
    int b = blockIdx.z;
    __shared__ ull ws1[CO * CI * 9];
    __shared__ ull ws2[CO * CI * 9];
    int t = threadIdx.y * 16 + threadIdx.x;
    if (t < CO * CI * 9) {
        int o = t / (CI * 9), rem = t % (CI * 9), i = rem / 9, tap = rem % 9;
        int dy = tap / 3, dx = tap % 3;
        long long widx;
        float sgn;
        if (conjt) { widx = ((long long)(b * CI + i) * CO + o) * 9 + dx * 3 + dy; sgn = -1.f; }
        else       { widx = ((long long)(b * CO + o) * CI + i) * 9 + dy * 3 + dx; sgn =  1.f; }
        float wrv = wr[widx], wiv = sgn * wi[widx];
        ws1[t] = pack2(wrv, wiv);
        ws2[t] = pack2(-wiv, wrv);
    }
    __syncthreads();
    int q = blockIdx.x * 16 + threadIdx.x;
    int p = blockIdx.y * 16 + threadIdx.y;
    if (p >= NG || q >= NG) return;
    const float2* Xb = X + (long long)b * CI * NN;
    ull acc[CO];
#pragma unroll
    for (int o = 0; o < CO; o++) acc[o] = 0ULL;
#pragma unroll
    for (int i = 0; i < CI; i++) {
#pragma unroll
        for (int dy = 0; dy < 3; dy++) {
            int ii = p + dy - 1;
#pragma unroll
            for (int dx = 0; dx < 3; dx++) {
                int jj = q + dx - 1;
                float2 xv = make_float2(0.f, 0.f);
                if (ii >= 0 && ii < NG && jj >= 0 && jj < NG)
                    xv = Xb[(long long)i * NN + (long long)ii * NG + jj];
                ull xr = pack2(xv.x, xv.x);
                ull xi = pack2(xv.y, xv.y);
                int tap = dy * 3 + dx;
#pragma unroll
                for (int o = 0; o < CO; o++) {
                    int widx = (o * CI + i) * 9 + tap;
                    acc[o] = ffma2(xr, ws1[widx], acc[o]);
                    acc[o] = ffma2(xi, ws2[widx], acc[o]);
                }
            }
        }
    }
    float2* Yb = Y + (long long)b * CO * NN;
    long long po = (long long)p * NG + q;
#pragma unroll
    for (int o = 0; o < CO; o++) Yb[(long long)o * NN + po] = unpack2(acc[o]);
}

// ---------------------------------------------------------------------------
// out = rh3 * wt * ik2 (in place on cC)
// ---------------------------------------------------------------------------
__global__ void k_wtik(float2* __restrict__ C, const float* __restrict__ wtr,
                       const float* __restrict__ wti)
{
    int b = blockIdx.z;
    int q = blockIdx.x * 16 + threadIdx.x;
    int p = blockIdx.y * 16 + threadIdx.y;
    if (p >= NG || q >= NG) return;
    long long o = (long long)b * NN + (long long)p * NG + q;
    float2 c = C[o];
    float wr = wtr[o], wi = wti[o];
    float dp = (float)(p - 256), dq = (float)(q - 256);
    float s = dp * dp + dq * dq;
    const float pi2 = 9.869604401089358f;
    float ik = (s == 0.f) ? 1.f : 1.f / (pi2 * s);
    float2 r;
    r.x = (c.x * wr - c.y * wi) * ik;
    r.y = (c.x * wi + c.y * wr) * ik;
    C[o] = r;
}

// ---------------------------------------------------------------------------
// Reductions (deterministic, double accumulation)
// ---------------------------------------------------------------------------
__global__ __launch_bounds__(256)
void k_alpha_part(const float* __restrict__ r, const float* __restrict__ e,
                  const float* __restrict__ a, double* __restrict__ p1,
                  double* __restrict__ p2)
{
    int b = blockIdx.y;
    const float* rb = r + (long long)b * NN;
    const float* eb = e + (long long)b * NN;
    const float* ab = a + (long long)b * NCC;
    double num = 0.0, den = 0.0;
    for (long long idx = (long long)blockIdx.x * 256 + threadIdx.x; idx < NN;
         idx += (long long)gridDim.x * 256) {
        int i = (int)(idx / NG), j = (int)(idx - (long long)i * NG);
        float ev = eb[idx];
        num += (double)(rb[idx] * ev);
        if (i > 0 && j > 0 && i < NG - 1 && j < NG - 1) {
            float d = darcy_at(eb, ab, i, j);
            den += (double)(d * ev);
        }
    }
    __shared__ double s1[256], s2[256];
    int t = threadIdx.x;
    s1[t] = num; s2[t] = den;
    __syncthreads();
    for (int s = 128; s > 0; s >>= 1) {
        if (t < s) { s1[t] += s1[t + s]; s2[t] += s2[t + s]; }
        __syncthreads();
    }
    if (t == 0) { p1[b * NBLK_A + blockIdx.x] = s1[0]; p2[b * NBLK_A + blockIdx.x] = s2[0]; }
}

__global__ void k_alpha_fin(const double* __restrict__ p1,
                            const double* __restrict__ p2,
                            float* __restrict__ alpha)
{
    int b = blockIdx.x;
    __shared__ double s1[256], s2[256];
    double n = 0.0, d = 0.0;
    for (int i = threadIdx.x; i < NBLK_A; i += 256) {
        n += p1[b * NBLK_A + i]; d += p2[b * NBLK_A + i];
    }
    int t = threadIdx.x;
    s1[t] = n; s2[t] = d;
    __syncthreads();
    for (int s = 128; s > 0; s >>= 1) {
        if (t < s) { s1[t] += s1[t + s]; s2[t] += s2[t + s]; }
        __syncthreads();
    }
    if (t == 0) alpha[b] = (float)(s1[0] / s2[0]);
}

__global__ void k_update(float* __restrict__ x, const float* __restrict__ e,
                         const float* __restrict__ alpha)
{
    int b = blockIdx.z;
    int j = blockIdx.x * 16 + threadIdx.x + 1;
    int i = blockIdx.y * 16 + threadIdx.y + 1;
    if (i > NI || j > NI) return;
    long long o = (long long)b * NN + (long long)i * NG + j;
    x[o] = fmaf(alpha[b], e[o], x[o]);
}

__global__ __launch_bounds__(256)
void k_norm_part(const float* __restrict__ r, const float* __restrict__ f,
                 double* __restrict__ p1, double* __restrict__ p2)
{
    double sr = 0.0, sf = 0.0;
    long long tot = (long long)NB * NN;
    for (long long idx = (long long)blockIdx.x * 256 + threadIdx.x; idx < tot;
         idx += (long long)gridDim.x * 256) {
        float rv = r[idx], fv = f[idx];
        sr += (double)rv * rv;
        sf += (double)fv * fv;
    }
    __shared__ double s1[256], s2[256];
    int t = threadIdx.x;
    s1[t] = sr; s2[t] = sf;
    __syncthreads();
    for (int s = 128; s > 0; s >>= 1) {
        if (t < s) { s1[t] += s1[t + s]; s2[t] += s2[t + s]; }
        __syncthreads();
    }
    if (t == 0) { p1[blockIdx.x] = s1[0]; p2[blockIdx.x] = s2[0]; }
}

__global__ void k_norm_fin(const double* __restrict__ p1,
                           const double* __restrict__ p2,
                           float* __restrict__ out)
{
    __shared__ double s1[256], s2[256];
    double a = 0.0, b = 0.0;
    for (int i = threadIdx.x; i < NBLK_N; i += 256) { a += p1[i]; b += p2[i]; }
    int t = threadIdx.x;
    s1[t] = a; s2[t] = b;
    __syncthreads();
    for (int s = 128; s > 0; s >>= 1) {
        if (t < s) { s1[t] += s1[t + s]; s2[t] += s2[t + s]; }
        __syncthreads();
    }
    if (t == 0) out[0] = (float)sqrt(s1[0] / s2[0]);
}

// ---------------------------------------------------------------------------
// Host orchestration
// ---------------------------------------------------------------------------
template<typename T>
static T* sym_addr(const void* sym)
{
    void* p = nullptr;
    cudaGetSymbolAddress(&p, sym);
    return (T*)p;
}

extern "C" void kernel_launch(void* const* d_in, const int* in_sizes, int n_in,
                              void* d_out, int out_size)
{
    const float* f    = (const float*)d_in[0];
    const float* coef = (const float*)d_in[1];
    const float* w1r = (const float*)d_in[3];
    const float* w1i = (const float*)d_in[4];
    const float* w2r = (const float*)d_in[5];
    const float* w2i = (const float*)d_in[6];
    const float* w3r = (const float*)d_in[7];
    const float* w3i = (const float*)d_in[8];
    const float* wtr = (const float*)d_in[9];
    const float* wti = (const float*)d_in[10];

    float*  x    = sym_addr<float>(g_x);
    float*  x2   = sym_addr<float>(g_x2);
    float*  r    = sym_addr<float>(g_r);
    float*  e    = sym_addr<float>(g_e);
    float*  rh   = sym_addr<float>(g_rh);
    float*  dinv = sym_addr<float>(g_dinv);
    float*  S    = sym_addr<float>(g_S);
    float*  St   = sym_addr<float>(g_St);
    float2* G    = sym_addr<float2>(g_G);
    float2* Gt   = sym_addr<float2>(g_Gt);
    float*  U    = sym_addr<float>(g_U);
    float2* cA   = sym_addr<float2>(g_cA);
    float2* cB   = sym_addr<float2>(g_cB);
    float2* cC   = sym_addr<float2>(g_cC);
    float2* W    = sym_addr<float2>(g_W);
    double* pd1  = sym_addr<double>(g_pd1);
    double* pd2  = sym_addr<double>(g_pd2);
    float*  alph = sym_addr<float>(g_alpha);

    dim3 blk2(16, 16);
    dim3 gInt((NI + 15) / 16, (NI + 15) / 16, NB);
    dim3 gFull((NG + 15) / 16, (NG + 15) / 16, NB);

    // ---- setup ----
    {
        long long tot = (long long)NB * NN;
        k_zero3<<<(int)((tot + 255) / 256), 256>>>(x, x2, e);
        int nSG = NG * NI;
        k_precS<<<(nSG + 255) / 256, 256>>>(S, St);
        k_precG<<<(nSG + 255) / 256, 256>>>(G, Gt);
        k_dinv<<<gInt, blk2>>>(coef, dinv);
    }

    float* xa = x;
    float* xb = x2;

    for (int step = 0; step < KSTEPS; step++) {
        // ---- 10 Jacobi sweeps ----
        for (int it = 0; it < 10; it++) {
            k_jacobi<<<gInt, blk2>>>(xa, xb, f, coef, dinv);
            float* tmp = xa; xa = xb; xb = tmp;
        }
        // ---- residual ----
        k_resid<<<gFull, blk2>>>(xa, f, coef, r);

        // ---- forward sine transform with odd symmetry ----
        // V = r_int(511x511) * St(511x513), only cols 256..512 then mirror
        {
            dim3 g((257 + 127) / 128, (NI + 63) / 64, NB);
            k_sgemm2<<<g, 256>>>(r + NG + 1, NG, NN,
                                 St + 256, NG, 0,
                                 U + 256, NG, NIG,
                                 NI, 257, NI, 1.f);
            dim3 gm(16, (NI + 15) / 16, NB);
            k_mirror_u<<<gm, blk2>>>(U);
        }
        // rh = -(1/512^2) S * V, rows 256..512 then mirror (planar real)
        {
            dim3 g((NG + 127) / 128, (257 + 63) / 64, NB);
            k_sgemm2<<<g, 256>>>(S + 256 * NI, NI, 0,
                                 U, NG, NIG,
                                 rh + 256 * NG, NG, NN,
                                 257, NG, NI, -1.f / (512.f * 512.f));
            dim3 gm((NG + 15) / 16, 16, NB);
            k_mirror_rh<<<gm, blk2>>>(rh);
        }

        // ---- 3 complex convs forward (first has real input) ----
        k_conv_r41<<<gFull, blk2>>>(rh, cA, w1r, w1i);
        k_conv<4, 4><<<gFull, blk2>>>(cA, cB, w2r, w2i, 0);
        k_conv<1, 4><<<gFull, blk2>>>(cB, cC, w3r, w3i, 0);

        // ---- spectral multiply ----
        k_wtik<<<gFull, blk2>>>(cC, wtr, wti);

        // ---- 3 complex convs backward (conjT) ----
        k_conv<4, 1><<<gFull, blk2>>>(cC, cA, w3r, w3i, 1);
        k_conv<4, 4><<<gFull, blk2>>>(cA, cB, w2r, w2i, 1);
        k_conv<1, 4><<<gFull, blk2>>>(cB, cC, w1r, w1i, 1);

        // ---- inverse transform: W = cC * Gt, e_int = Re(G * W) ----
        {
            dim3 g((NI + 63) / 64, (NG + 63) / 64, NB);
            k_cgemm_full<<<g, 256>>>(cC, NG, NN,
                                     Gt, NI, 0,
                                     W, NI, NIG,
                                     NG, NI, NG);
        }
        {
            dim3 g((NI + 127) / 128, (NI + 63) / 64, NB);
            k_cgemm_re<<<g, 256>>>(G, NG, 0,
                                   W, NI, NIG,
                                   e + NG + 1, NG, NN,
                                   NI, NI, NG);
        }

        // ---- alpha and update ----
        {
            dim3 g(NBLK_A, NB);
            k_alpha_part<<<g, 256>>>(r, e, coef, pd1, pd2);
            k_alpha_fin<<<NB, 256>>>(pd1, pd2, alph);
            k_update<<<gInt, blk2>>>(xa, e, alph);
        }
    }

    // ---- final relative residual norm ----
    k_resid<<<gFull, blk2>>>(xa, f, coef, r);
    k_norm_part<<<NBLK_N, 256>>>(r, f, pd1, pd2);
    k_norm_fin<<<1, 256>>>(pd1, pd2, (float*)d_out);
}

// round 4
// speedup vs baseline: 1.4101x; 1.4101x over previous
#include <cuda_runtime.h>
#include <math.h>

#define DINLINE __device__ __forceinline__

// ---------------------------------------------------------------------------
// Fixed problem dimensions (B=4, grid 513, coef 512, epoch=101 -> K=2)
// ---------------------------------------------------------------------------
namespace fns {
constexpr int NB = 4;
constexpr int NG = 513;
constexpr int NI = 511;
constexpr int NC = 512;
constexpr long long NN  = (long long)NG * NG;
constexpr long long NCC = (long long)NC * NC;
constexpr long long NII = (long long)NI * NI;
constexpr long long NIG = (long long)NI * NG;
constexpr int NBLK_A = 128;
constexpr int NBLK_N = 256;
constexpr int KSTEPS = 2;
}
using namespace fns;

// ---------------------------------------------------------------------------
// Static device scratch
// ---------------------------------------------------------------------------
__device__ float  g_x   [NB * NN];
__device__ float  g_x2  [NB * NN];
__device__ float  g_r   [NB * NN];
__device__ float  g_e   [NB * NN];
__device__ float  g_rh  [NB * NN];
__device__ float  g_dinv[NB * NII];
__device__ float  g_S   [NG * (long long)NI];  // S[p][j], ld=NI
__device__ float  g_St  [NIG];                 // St[j][p], ld=NG
__device__ float2 g_G   [NIG];                 // G[s][u],  ld=NG
__device__ float2 g_Gt  [NIG];                 // Gt[u][s], ld=NI
__device__ float  g_U   [NB * NIG];            // V = r_int * St, 511x513, ld=NG
__device__ float2 g_cA  [NB * 4 * NN];
__device__ float2 g_cB  [NB * 4 * NN];
__device__ float2 g_cC  [NB * NN];
__device__ float2 g_W   [NB * NIG];            // 513x511, ld=NI
__device__ double g_pd1 [2048];
__device__ double g_pd2 [2048];
__device__ float  g_alpha[NB];

// ---------------------------------------------------------------------------
// Darcy FEM 9-point stencil
// ---------------------------------------------------------------------------
DINLINE float darcy_at(const float* __restrict__ x,
                       const float* __restrict__ a, int i, int j)
{
    const float c23 = 2.f / 3.f, c16 = -1.f / 6.f, c13 = -1.f / 3.f;
    float s = 0.f;
#pragma unroll
    for (int u = 0; u < 2; u++) {
#pragma unroll
        for (int v = 0; v < 2; v++) {
            int I = i - 1 + u, J = j - 1 + v;
            float av = a[(long long)I * NC + J];
            float k0, k1, k2, k3;
            if (u == 0 && v == 0) { k0 = c16; k1 = c23; k2 = c16; k3 = c13; }
            else if (u == 0 && v == 1) { k0 = c23; k1 = c16; k2 = c13; k3 = c16; }
            else if (u == 1 && v == 0) { k0 = c13; k1 = c16; k2 = c23; k3 = c16; }
            else                        { k0 = c16; k1 = c13; k2 = c16; k3 = c23; }
            s += av * (k3 * x[(long long)I * NG + J]
                     + k2 * x[(long long)I * NG + J + 1]
                     + k0 * x[(long long)(I + 1) * NG + J]
                     + k1 * x[(long long)(I + 1) * NG + J + 1]);
        }
    }
    return s;
}

// ---------------------------------------------------------------------------
// Setup kernels
// ---------------------------------------------------------------------------
__global__ void k_precS(float* __restrict__ S, float* __restrict__ St)
{
    int idx = blockIdx.x * blockDim.x + threadIdx.x;
    if (idx >= NG * NI) return;
    int p = idx / NI, j = idx - p * NI;
    int m = (j + 1) * (p - 256);
    int mm = ((m % 1024) + 1024) % 1024;
    float v = sinpif((float)mm / 512.f);
    S[idx] = v;
    St[(long long)j * NG + p] = v;
}

__global__ void k_precG(float2* __restrict__ G, float2* __restrict__ Gt)
{
    int idx = blockIdx.x * blockDim.x + threadIdx.x;
    if (idx >= NI * NG) return;
    int s = idx / NG, u = idx - s * NG;
    int t = (u - 255) * s;
    int tm = ((t % 1025) + 1025) % 1025;
    float xr = 2.f * (float)tm / 1025.f;
    float2 g = make_float2(cospif(xr), -sinpif(xr));
    G[idx] = g;
    Gt[(long long)u * NI + s] = g;
}

__global__ void k_dinv(const float* __restrict__ a, float* __restrict__ dinv)
{
    int b = blockIdx.z;
    int q = blockIdx.x * 16 + threadIdx.x;
    int p = blockIdx.y * 16 + threadIdx.y;
    if (p >= NI || q >= NI) return;
    const float* ap = a + (long long)b * NCC;
    float s = ap[(long long)p * NC + q] + ap[(long long)p * NC + q + 1]
            + ap[(long long)(p + 1) * NC + q] + ap[(long long)(p + 1) * NC + q + 1];
    dinv[(long long)b * NII + (long long)p * NI + q] = 1.f / ((2.f / 3.f) * s);
}

__global__ void k_zero3(float* __restrict__ x, float* __restrict__ x2,
                        float* __restrict__ e)
{
    long long idx = (long long)blockIdx.x * blockDim.x + threadIdx.x;
    long long tot = (long long)NB * NN;
    if (idx >= tot) return;
    x[idx] = 0.f; x2[idx] = 0.f; e[idx] = 0.f;
}

// ---------------------------------------------------------------------------
// Jacobi sweep + residual
// ---------------------------------------------------------------------------
__global__ __launch_bounds__(256)
void k_jacobi(const float* __restrict__ xin, float* __restrict__ xout,
              const float* __restrict__ f, const float* __restrict__ a,
              const float* __restrict__ dinv)
{
    int b = blockIdx.z;
    int j = blockIdx.x * 16 + threadIdx.x + 1;
    int i = blockIdx.y * 16 + threadIdx.y + 1;
    if (i > NI || j > NI) return;
    const float* xp = xin + (long long)b * NN;
    const float* ap = a + (long long)b * NCC;
    long long o = (long long)b * NN + (long long)i * NG + j;
    float d = darcy_at(xp, ap, i, j);
    float r = f[o] - d;
    xout[o] = xp[(long long)i * NG + j]
            + 0.75f * dinv[(long long)b * NII + (long long)(i - 1) * NI + (j - 1)] * r;
}

__global__ __launch_bounds__(256)
void k_resid(const float* __restrict__ x, const float* __restrict__ f,
             const float* __restrict__ a, float* __restrict__ r)
{
    int b = blockIdx.z;
    int j = blockIdx.x * 16 + threadIdx.x;
    int i = blockIdx.y * 16 + threadIdx.y;
    if (i >= NG || j >= NG) return;
    long long o = (long long)b * NN + (long long)i * NG + j;
    float d = 0.f;
    if (i > 0 && j > 0 && i < NG - 1 && j < NG - 1)
        d = darcy_at(x + (long long)b * NN, a + (long long)b * NCC, i, j);
    r[o] = f[o] - d;
}

// ---------------------------------------------------------------------------
// Real SGEMM: C = alpha * A(MxK) * B(KxN). 64x64 tile, BK=16, 256 threads,
// 4x4 microtile. (Proven R1 kernel.)
// ---------------------------------------------------------------------------
__global__ __launch_bounds__(256)
void k_sgemm(const float* __restrict__ A, int lda, long long sA,
             const float* __restrict__ B, int ldb, long long sB,
             float* __restrict__ C, int ldc, long long sC,
             int M, int N, int K, float alpha)
{
    __shared__ float As[16][68];
    __shared__ float Bs[16][68];
    int b = blockIdx.z;
    A += (long long)b * sA;
    B += (long long)b * sB;
    int tid = threadIdx.x;
    int m0 = blockIdx.y * 64, n0 = blockIdx.x * 64;
    int mt = (tid & 15) * 4;
    int nt = (tid >> 4) * 4;
    float acc[4][4] = {};

    for (int kt = 0; kt < K; kt += 16) {
#pragma unroll
        for (int e = 0; e < 4; e++) {
            int idx = tid + e * 256;
            int r = idx >> 4, c = idx & 15;
            int gm = m0 + r, gk = kt + c;
            As[c][r] = (gm < M && gk < K) ? A[(long long)gm * lda + gk] : 0.f;
            int r2 = idx >> 6, c2 = idx & 63;
            int gk2 = kt + r2, gn = n0 + c2;
            Bs[r2][c2] = (gk2 < K && gn < N) ? B[(long long)gk2 * ldb + gn] : 0.f;
        }
        __syncthreads();
#pragma unroll
        for (int k = 0; k < 16; k++) {
            float av[4], bv[4];
#pragma unroll
            for (int i = 0; i < 4; i++) av[i] = As[k][mt + i];
#pragma unroll
            for (int j = 0; j < 4; j++) bv[j] = Bs[k][nt + j];
#pragma unroll
            for (int i = 0; i < 4; i++)
#pragma unroll
                for (int j = 0; j < 4; j++)
                    acc[i][j] = fmaf(av[i], bv[j], acc[i][j]);
        }
        __syncthreads();
    }

#pragma unroll
    for (int i = 0; i < 4; i++) {
        int gm = m0 + mt + i;
        if (gm >= M) continue;
#pragma unroll
        for (int j = 0; j < 4; j++) {
            int gn = n0 + nt + j;
            if (gn >= N) continue;
            C[(long long)b * sC + (long long)gm * ldc + gn] = alpha * acc[i][j];
        }
    }
}

// ---------------------------------------------------------------------------
// Complex GEMM (proven R1 kernel). REAL_OUT keeps only Re.
// ---------------------------------------------------------------------------
DINLINE float2 cmad(float2 acc, float2 a, float2 b)
{
    acc.x = fmaf(a.x, b.x, fmaf(-a.y, b.y, acc.x));
    acc.y = fmaf(a.x, b.y, fmaf(a.y, b.x, acc.y));
    return acc;
}

template<bool REAL_OUT>
__global__ __launch_bounds__(256)
void k_cgemm(const float2* __restrict__ A, int lda, long long sA,
             const float2* __restrict__ B, int ldb, long long sB,
             void* __restrict__ Cv, int ldc, long long sC,
             int M, int N, int K)
{
    __shared__ float2 As[16][66];
    __shared__ float2 Bs[16][66];
    int b = blockIdx.z;
    A += (long long)b * sA;
    B += (long long)b * sB;
    int tid = threadIdx.x;
    int m0 = blockIdx.y * 64, n0 = blockIdx.x * 64;
    int mt = (tid & 15) * 4;
    int nt = (tid >> 4) * 4;
    float2 accc[4][4];
    float  accr[4][4];
#pragma unroll
    for (int i = 0; i < 4; i++)
#pragma unroll
        for (int j = 0; j < 4; j++) { accc[i][j] = make_float2(0.f, 0.f); accr[i][j] = 0.f; }

    for (int kt = 0; kt < K; kt += 16) {
#pragma unroll
        for (int e = 0; e < 4; e++) {
            int idx = tid + e * 256;
            int r = idx >> 4, c = idx & 15;
            int gm = m0 + r, gk = kt + c;
            As[c][r] = (gm < M && gk < K) ? A[(long long)gm * lda + gk] : make_float2(0.f, 0.f);
            int r2 = idx >> 6, c2 = idx & 63;
            int gk2 = kt + r2, gn = n0 + c2;
            Bs[r2][c2] = (gk2 < K && gn < N) ? B[(long long)gk2 * ldb + gn] : make_float2(0.f, 0.f);
        }
        __syncthreads();
#pragma unroll
        for (int k = 0; k < 16; k++) {
            float2 av[4], bv[4];
#pragma unroll
            for (int i = 0; i < 4; i++) av[i] = As[k][mt + i];
#pragma unroll
            for (int j = 0; j < 4; j++) bv[j] = Bs[k][nt + j];
#pragma unroll
            for (int i = 0; i < 4; i++)
#pragma unroll
                for (int j = 0; j < 4; j++) {
                    if (REAL_OUT) {
                        accr[i][j] = fmaf(av[i].x, bv[j].x,
                                     fmaf(-av[i].y, bv[j].y, accr[i][j]));
                    } else {
                        accc[i][j] = cmad(accc[i][j], av[i], bv[j]);
                    }
                }
        }
        __syncthreads();
    }

#pragma unroll
    for (int i = 0; i < 4; i++) {
        int gm = m0 + mt + i;
        if (gm >= M) continue;
#pragma unroll
        for (int j = 0; j < 4; j++) {
            int gn = n0 + nt + j;
            if (gn >= N) continue;
            if (REAL_OUT) {
                float* C = (float*)Cv;
                C[(long long)b * sC + (long long)gm * ldc + gn] = accr[i][j];
            } else {
                float2* C = (float2*)Cv;
                C[(long long)b * sC + (long long)gm * ldc + gn] = accc[i][j];
            }
        }
    }
}

// ---------------------------------------------------------------------------
// Symmetry mirror kernels for the sine transform (validated in R2)
// ---------------------------------------------------------------------------
__global__ void k_mirror_u(float* __restrict__ U)
{
    int b = blockIdx.z;
    int t = blockIdx.x * 16 + threadIdx.x + 1;   // 1..256
    int i = blockIdx.y * 16 + threadIdx.y;       // 0..510
    if (t > 256 || i >= NI) return;
    float* Ub = U + (long long)b * NIG;
    Ub[(long long)i * NG + (256 - t)] = -Ub[(long long)i * NG + (256 + t)];
}

__global__ void k_mirror_rh(float* __restrict__ rh)
{
    int b = blockIdx.z;
    int q = blockIdx.x * 16 + threadIdx.x;       // 0..512
    int t = blockIdx.y * 16 + threadIdx.y + 1;   // 1..256
    if (q >= NG || t > 256) return;
    float* R = rh + (long long)b * NN;
    R[(long long)(256 - t) * NG + q] = -R[(long long)(256 + t) * NG + q];
}

// ---------------------------------------------------------------------------
// Real-input complex conv (first forward conv, plain fp32)
// ---------------------------------------------------------------------------
__global__ __launch_bounds__(256)
void k_conv_r41(const float* __restrict__ X, float2* __restrict__ Y,
                const float* __restrict__ wr, const float* __restrict__ wi)
{
    int b = blockIdx.z;
    __shared__ float2 ws[36];
    int t = threadIdx.y * 16 + threadIdx.x;
    if (t < 36) ws[t] = make_float2(wr[b * 36 + t], wi[b * 36 + t]);
    __syncthreads();
    int q = blockIdx.x * 16 + threadIdx.x;
    int p = blockIdx.y * 16 + threadIdx.y;
    if (p >= NG || q >= NG) return;
    const float* Xb = X + (long long)b * NN;
    float2 acc[4];
#pragma unroll
    for (int o = 0; o < 4; o++) acc[o] = make_float2(0.f, 0.f);
#pragma unroll
    for (int dy = 0; dy < 3; dy++) {
        int ii = p + dy - 1;
#pragma unroll
        for (int dx = 0; dx < 3; dx++) {
            int jj = q + dx - 1;
            float xv = 0.f;
            if (ii >= 0 && ii < NG && jj >= 0 && jj < NG)
                xv = Xb[(long long)ii * NG + jj];
            int tap = dy * 3 + dx;
#pragma unroll
            for (int o = 0; o < 4; o++) {
                float2 w = ws[o * 9 + tap];
                acc[o].x = fmaf(xv, w.x, acc[o].x);
                acc[o].y = fmaf(xv, w.y, acc[o].y);
            }
        }
    }
    float2* Yb = Y + (long long)b * 4 * NN;
    long long po = (long long)p * NG + q;
#pragma unroll
    for (int o = 0; o < 4; o++) Yb[(long long)o * NN + po] = acc[o];
}

// ---------------------------------------------------------------------------
// Complex multi-channel 3x3 conv (pad=1), plain fp32 (proven R1 kernel).
// WTIK: fuse the wt*ik2 elementwise multiply into the epilogue (CO==1 use).
// ---------------------------------------------------------------------------
template<int CO, int CI, bool WTIK>
__global__ __launch_bounds__(256)
void k_conv(const float2* __restrict__ X, float2* __restrict__ Y,
            const float* __restrict__ wr, const float* __restrict__ wi,
            int conjt, const float* __restrict__ wtr,
            const float* __restrict__ wti)
{
    int b = blockIdx.z;
    __shared__ float2 ws[CO * CI * 9];
    int t = threadIdx.y * 16 + threadIdx.x;
    if (t < CO * CI * 9) {
        int o = t / (CI * 9), rem = t % (CI * 9), i = rem / 9, tap = rem % 9;
        int dy = tap / 3, dx = tap % 3;
        long long widx;
        float sgn;
        if (conjt) { widx = ((long long)(b * CI + i) * CO + o) * 9 + dx * 3 + dy; sgn = -1.f; }
        else       { widx = ((long long)(b * CO + o) * CI + i) * 9 + dy * 3 + dx; sgn =  1.f; }
        ws[t] = make_float2(wr[widx], sgn * wi[widx]);
    }
    __syncthreads();
    int q = blockIdx.x * 16 + threadIdx.x;
    int p = blockIdx.y * 16 + threadIdx.y;
    if (p >= NG || q >= NG) return;
    const float2* Xb = X + (long long)b * CI * NN;
    float2 acc[CO];
#pragma unroll
    for (int o = 0; o < CO; o++) acc[o] = make_float2(0.f, 0.f);
#pragma unroll
    for (int i = 0; i < CI; i++) {
#pragma unroll
        for (int dy = 0; dy < 3; dy++) {
            int ii = p + dy - 1;
#pragma unroll
            for (int dx = 0; dx < 3; dx++) {
                int jj = q + dx - 1;
                float2 xv = make_float2(0.f, 0.f);
                if (ii >= 0 && ii < NG && jj >= 0 && jj < NG)
                    xv = Xb[(long long)i * NN + (long long)ii * NG + jj];
                int tap = dy * 3 + dx;
#pragma unroll
                for (int o = 0; o < CO; o++)
                    acc[o] = cmad(acc[o], xv, ws[(o * CI + i) * 9 + tap]);
            }
        }
    }
    float2* Yb = Y + (long long)b * CO * NN;
    long long po = (long long)p * NG + q;
    if (WTIK) {
        long long o = (long long)b * NN + po;
        float wrv = wtr[o], wiv = wti[o];
        float dp = (float)(p - 256), dq = (float)(q - 256);
        float s = dp * dp + dq * dq;
        const float pi2 = 9.869604401089358f;
        float ik = (s == 0.f) ? 1.f : 1.f / (pi2 * s);
        float2 c = acc[0];
        float2 rr;
        rr.x = (c.x * wrv - c.y * wiv) * ik;
        rr.y = (c.x * wiv + c.y * wrv) * ik;
        Yb[po] = rr;
    } else {
#pragma unroll
        for (int o = 0; o < CO; o++) Yb[(long long)o * NN + po] = acc[o];
    }
}

// ---------------------------------------------------------------------------
// Reductions (deterministic, double accumulation)
// ---------------------------------------------------------------------------
__global__ __launch_bounds__(256)
void k_alpha_part(const float* __restrict__ r, const float* __restrict__ e,
                  const float* __restrict__ a, double* __restrict__ p1,
                  double* __restrict__ p2)
{
    int b = blockIdx.y;
    const float* rb = r + (long long)b * NN;
    const float* eb = e + (long long)b * NN;
    const float* ab = a + (long long)b * NCC;
    double num = 0.0, den = 0.0;
    for (long long idx = (long long)blockIdx.x * 256 + threadIdx.x; idx < NN;
         idx += (long long)gridDim.x * 256) {
        int i = (int)(idx / NG), j = (int)(idx - (long long)i * NG);
        float ev = eb[idx];
        num += (double)(rb[idx] * ev);
        if (i > 0 && j > 0 && i < NG - 1 && j < NG - 1) {
            float d = darcy_at(eb, ab, i, j);
            den += (double)(d * ev);
        }
    }
    __shared__ double s1[256], s2[256];
    int t = threadIdx.x;
    s1[t] = num; s2[t] = den;
    __syncthreads();
    for (int s = 128; s > 0; s >>= 1) {
        if (t < s) { s1[t] += s1[t + s]; s2[t] += s2[t + s]; }
        __syncthreads();
    }
    if (t == 0) { p1[b * NBLK_A + blockIdx.x] = s1[0]; p2[b * NBLK_A + blockIdx.x] = s2[0]; }
}

__global__ void k_alpha_fin(const double* __restrict__ p1,
                            const double* __restrict__ p2,
                            float* __restrict__ alpha)
{
    int b = blockIdx.x;
    __shared__ double s1[256], s2[256];
    double n = 0.0, d = 0.0;
    for (int i = threadIdx.x; i < NBLK_A; i += 256) {
        n += p1[b * NBLK_A + i]; d += p2[b * NBLK_A + i];
    }
    int t = threadIdx.x;
    s1[t] = n; s2[t] = d;
    __syncthreads();
    for (int s = 128; s > 0; s >>= 1) {
        if (t < s) { s1[t] += s1[t + s]; s2[t] += s2[t + s]; }
        __syncthreads();
    }
    if (t == 0) alpha[b] = (float)(s1[0] / s2[0]);
}

__global__ void k_update(float* __restrict__ x, const float* __restrict__ e,
                         const float* __restrict__ alpha)
{
    int b = blockIdx.z;
    int j = blockIdx.x * 16 + threadIdx.x + 1;
    int i = blockIdx.y * 16 + threadIdx.y + 1;
    if (i > NI || j > NI) return;
    long long o = (long long)b * NN + (long long)i * NG + j;
    x[o] = fmaf(alpha[b], e[o], x[o]);
}

__global__ __launch_bounds__(256)
void k_norm_part(const float* __restrict__ r, const float* __restrict__ f,
                 double* __restrict__ p1, double* __restrict__ p2)
{
    double sr = 0.0, sf = 0.0;
    long long tot = (long long)NB * NN;
    for (long long idx = (long long)blockIdx.x * 256 + threadIdx.x; idx < tot;
         idx += (long long)gridDim.x * 256) {
        float rv = r[idx], fv = f[idx];
        sr += (double)rv * rv;
        sf += (double)fv * fv;
    }
    __shared__ double s1[256], s2[256];
    int t = threadIdx.x;
    s1[t] = sr; s2[t] = sf;
    __syncthreads();
    for (int s = 128; s > 0; s >>= 1) {
        if (t < s) { s1[t] += s1[t + s]; s2[t] += s2[t + s]; }
        __syncthreads();
    }
    if (t == 0) { p1[blockIdx.x] = s1[0]; p2[blockIdx.x] = s2[0]; }
}

__global__ void k_norm_fin(const double* __restrict__ p1,
                           const double* __restrict__ p2,
                           float* __restrict__ out)
{
    __shared__ double s1[256], s2[256];
    double a = 0.0, b = 0.0;
    for (int i = threadIdx.x; i < NBLK_N; i += 256) { a += p1[i]; b += p2[i]; }
    int t = threadIdx.x;
    s1[t] = a; s2[t] = b;
    __syncthreads();
    for (int s = 128; s > 0; s >>= 1) {
        if (t < s) { s1[t] += s1[t + s]; s2[t] += s2[t + s]; }
        __syncthreads();
    }
    if (t == 0) out[0] = (float)sqrt(s1[0] / s2[0]);
}

// ---------------------------------------------------------------------------
// Host orchestration
// ---------------------------------------------------------------------------
template<typename T>
static T* sym_addr(const void* sym)
{
    void* p = nullptr;
    cudaGetSymbolAddress(&p, sym);
    return (T*)p;
}

extern "C" void kernel_launch(void* const* d_in, const int* in_sizes, int n_in,
                              void* d_out, int out_size)
{
    const float* f    = (const float*)d_in[0];
    const float* coef = (const float*)d_in[1];
    const float* w1r = (const float*)d_in[3];
    const float* w1i = (const float*)d_in[4];
    const float* w2r = (const float*)d_in[5];
    const float* w2i = (const float*)d_in[6];
    const float* w3r = (const float*)d_in[7];
    const float* w3i = (const float*)d_in[8];
    const float* wtr = (const float*)d_in[9];
    const float* wti = (const float*)d_in[10];

    float*  x    = sym_addr<float>(g_x);
    float*  x2   = sym_addr<float>(g_x2);
    float*  r    = sym_addr<float>(g_r);
    float*  e    = sym_addr<float>(g_e);
    float*  rh   = sym_addr<float>(g_rh);
    float*  dinv = sym_addr<float>(g_dinv);
    float*  S    = sym_addr<float>(g_S);
    float*  St   = sym_addr<float>(g_St);
    float2* G    = sym_addr<float2>(g_G);
    float2* Gt   = sym_addr<float2>(g_Gt);
    float*  U    = sym_addr<float>(g_U);
    float2* cA   = sym_addr<float2>(g_cA);
    float2* cB   = sym_addr<float2>(g_cB);
    float2* cC   = sym_addr<float2>(g_cC);
    float2* W    = sym_addr<float2>(g_W);
    double* pd1  = sym_addr<double>(g_pd1);
    double* pd2  = sym_addr<double>(g_pd2);
    float*  alph = sym_addr<float>(g_alpha);

    dim3 blk2(16, 16);
    dim3 gInt((NI + 15) / 16, (NI + 15) / 16, NB);
    dim3 gFull((NG + 15) / 16, (NG + 15) / 16, NB);

    // ---- setup ----
    {
        long long tot = (long long)NB * NN;
        k_zero3<<<(int)((tot + 255) / 256), 256>>>(x, x2, e);
        int nSG = NG * NI;
        k_precS<<<(nSG + 255) / 256, 256>>>(S, St);
        k_precG<<<(nSG + 255) / 256, 256>>>(G, Gt);
        k_dinv<<<gInt, blk2>>>(coef, dinv);
    }

    float* xa = x;
    float* xb = x2;

    for (int step = 0; step < KSTEPS; step++) {
        // ---- 10 Jacobi sweeps ----
        for (int it = 0; it < 10; it++) {
            k_jacobi<<<gInt, blk2>>>(xa, xb, f, coef, dinv);
            float* tmp = xa; xa = xb; xb = tmp;
        }
        // ---- residual ----
        k_resid<<<gFull, blk2>>>(xa, f, coef, r);

        // ---- forward sine transform with odd symmetry ----
        // U cols 256..512: U(:,256+t) = r_int * St(:,256+t); mirror the rest.
        {
            dim3 g((257 + 63) / 64, (NI + 63) / 64, NB);
            k_sgemm<<<g, 256>>>(r + NG + 1, NG, NN,
                                St + 256, NG, 0,
                                U + 256, NG, NIG,
                                NI, 257, NI, 1.f);
            dim3 gm(16, (NI + 15) / 16, NB);
            k_mirror_u<<<gm, blk2>>>(U);
        }
        // rh rows 256..512 = -(1/512^2) * S[256:,:] * U; mirror the rest.
        {
            dim3 g((NG + 63) / 64, (257 + 63) / 64, NB);
            k_sgemm<<<g, 256>>>(S + 256 * NI, NI, 0,
                                U, NG, NIG,
                                rh + 256 * NG, NG, NN,
                                257, NG, NI, -1.f / (512.f * 512.f));
            dim3 gm((NG + 15) / 16, 16, NB);
            k_mirror_rh<<<gm, blk2>>>(rh);
        }

        // ---- 3 complex convs forward (first real-input, third fused w/ wt*ik2) ----
        k_conv_r41<<<gFull, blk2>>>(rh, cA, w1r, w1i);
        k_conv<4, 4, false><<<gFull, blk2>>>(cA, cB, w2r, w2i, 0, nullptr, nullptr);
        k_conv<1, 4, true ><<<gFull, blk2>>>(cB, cC, w3r, w3i, 0, wtr, wti);

        // ---- 3 complex convs backward (conjT) ----
        k_conv<4, 1, false><<<gFull, blk2>>>(cC, cA, w3r, w3i, 1, nullptr, nullptr);
        k_conv<4, 4, false><<<gFull, blk2>>>(cA, cB, w2r, w2i, 1, nullptr, nullptr);
        k_conv<1, 4, false><<<gFull, blk2>>>(cB, cC, w1r, w1i, 1, nullptr, nullptr);

        // ---- inverse transform: W = cC * Gt, e_int = Re(G * W) ----
        {
            dim3 g((NI + 63) / 64, (NG + 63) / 64, NB);
            k_cgemm<false><<<g, 256>>>(cC, NG, NN,
                                       Gt, NI, 0,
                                       W, NI, NIG,
                                       NG, NI, NG);
        }
        {
            dim3 g((NI + 63) / 64, (NI + 63) / 64, NB);
            k_cgemm<true><<<g, 256>>>(G, NG, 0,
                                      W, NI, NIG,
                                      e + NG + 1, NG, NN,
                                      NI, NI, NG);
        }

        // ---- alpha and update ----
        {
            dim3 g(NBLK_A, NB);
            k_alpha_part<<<g, 256>>>(r, e, coef, pd1, pd2);
            k_alpha_fin<<<NB, 256>>>(pd1, pd2, alph);
            k_update<<<gInt, blk2>>>(xa, e, alph);
        }
    }

    // ---- final relative residual norm ----
    k_resid<<<gFull, blk2>>>(xa, f, coef, r);
    k_norm_part<<<NBLK_N, 256>>>(r, f, pd1, pd2);
    k_norm_fin<<<1, 256>>>(pd1, pd2, (float*)d_out);
}

// round 5
// speedup vs baseline: 1.5439x; 1.0949x over previous
#include <cuda_runtime.h>
#include <math.h>

#define DINLINE __device__ __forceinline__

// ---------------------------------------------------------------------------
// Fixed problem dimensions (B=4, grid 513, coef 512, epoch=101 -> K=2)
// ---------------------------------------------------------------------------
namespace fns {
constexpr int NB = 4;
constexpr int NG = 513;
constexpr int NI = 511;
constexpr int NC = 512;
constexpr long long NN  = (long long)NG * NG;
constexpr long long NCC = (long long)NC * NC;
constexpr long long NII = (long long)NI * NI;
constexpr long long NIG = (long long)NI * NG;
constexpr int NBLK_A = 128;
constexpr int NBLK_N = 256;
constexpr int KSTEPS = 2;
}
using namespace fns;

// ---------------------------------------------------------------------------
// Static device scratch
// ---------------------------------------------------------------------------
__device__ float  g_x   [NB * NN];
__device__ float  g_x2  [NB * NN];
__device__ float  g_r   [NB * NN];
__device__ float  g_e   [NB * NN];
__device__ float  g_rh  [NB * NN];
__device__ float  g_dinv[NB * NII];
__device__ float  g_S   [NG * (long long)NI];  // S[p][j], ld=NI
__device__ float  g_St  [NIG];                 // St[j][p], ld=NG
__device__ float2 g_G   [NIG];                 // G[s][u],  ld=NG
__device__ float2 g_Gt  [NIG];                 // Gt[u][s], ld=NI
__device__ float  g_U   [NB * NIG];            // 511 x 513, ld=NG
__device__ float2 g_cA  [NB * 4 * NN];
__device__ float2 g_cB  [NB * 4 * NN];
__device__ float2 g_cC  [NB * NN];
__device__ float2 g_W   [NB * NIG];            // 513x511, ld=NI
__device__ double g_pd1 [2048];
__device__ double g_pd2 [2048];
__device__ float  g_alpha[NB];

// ---------------------------------------------------------------------------
// Darcy FEM 9-point stencil (pointer form, used by resid / alpha)
// ---------------------------------------------------------------------------
DINLINE float darcy_at(const float* __restrict__ x,
                       const float* __restrict__ a, int i, int j)
{
    const float c23 = 2.f / 3.f, c16 = -1.f / 6.f, c13 = -1.f / 3.f;
    float s = 0.f;
#pragma unroll
    for (int u = 0; u < 2; u++) {
#pragma unroll
        for (int v = 0; v < 2; v++) {
            int I = i - 1 + u, J = j - 1 + v;
            float av = a[(long long)I * NC + J];
            float k0, k1, k2, k3;
            if (u == 0 && v == 0) { k0 = c16; k1 = c23; k2 = c16; k3 = c13; }
            else if (u == 0 && v == 1) { k0 = c23; k1 = c16; k2 = c13; k3 = c16; }
            else if (u == 1 && v == 0) { k0 = c13; k1 = c16; k2 = c23; k3 = c16; }
            else                        { k0 = c16; k1 = c13; k2 = c16; k3 = c23; }
            s += av * (k3 * x[(long long)I * NG + J]
                     + k2 * x[(long long)I * NG + J + 1]
                     + k0 * x[(long long)(I + 1) * NG + J]
                     + k1 * x[(long long)(I + 1) * NG + J + 1]);
        }
    }
    return s;
}

// ---------------------------------------------------------------------------
// Setup kernels
// ---------------------------------------------------------------------------
__global__ void k_precS(float* __restrict__ S, float* __restrict__ St)
{
    int idx = blockIdx.x * blockDim.x + threadIdx.x;
    if (idx >= NG * NI) return;
    int p = idx / NI, j = idx - p * NI;
    int m = (j + 1) * (p - 256);
    int mm = ((m % 1024) + 1024) % 1024;
    float v = sinpif((float)mm / 512.f);
    S[idx] = v;
    St[(long long)j * NG + p] = v;
}

__global__ void k_precG(float2* __restrict__ G, float2* __restrict__ Gt)
{
    int idx = blockIdx.x * blockDim.x + threadIdx.x;
    if (idx >= NI * NG) return;
    int s = idx / NG, u = idx - s * NG;
    int t = (u - 255) * s;
    int tm = ((t % 1025) + 1025) % 1025;
    float xr = 2.f * (float)tm / 1025.f;
    float2 g = make_float2(cospif(xr), -sinpif(xr));
    G[idx] = g;
    Gt[(long long)u * NI + s] = g;
}

__global__ void k_dinv(const float* __restrict__ a, float* __restrict__ dinv)
{
    int b = blockIdx.z;
    int q = blockIdx.x * 16 + threadIdx.x;
    int p = blockIdx.y * 16 + threadIdx.y;
    if (p >= NI || q >= NI) return;
    const float* ap = a + (long long)b * NCC;
    float s = ap[(long long)p * NC + q] + ap[(long long)p * NC + q + 1]
            + ap[(long long)(p + 1) * NC + q] + ap[(long long)(p + 1) * NC + q + 1];
    dinv[(long long)b * NII + (long long)p * NI + q] = 1.f / ((2.f / 3.f) * s);
}

__global__ void k_zero3(float* __restrict__ x, float* __restrict__ x2,
                        float* __restrict__ e)
{
    long long idx = (long long)blockIdx.x * blockDim.x + threadIdx.x;
    long long tot = (long long)NB * NN;
    if (idx >= tot) return;
    x[idx] = 0.f; x2[idx] = 0.f; e[idx] = 0.f;
}

// ---------------------------------------------------------------------------
// Jacobi sweep: 2x2 nodes per thread (register-cached stencil neighborhood)
// ---------------------------------------------------------------------------
__global__ __launch_bounds__(256)
void k_jacobi2(const float* __restrict__ xin, float* __restrict__ xout,
               const float* __restrict__ f, const float* __restrict__ a,
               const float* __restrict__ dinv)
{
    int b = blockIdx.z;
    int tj = blockIdx.x * 16 + threadIdx.x;
    int ti = blockIdx.y * 16 + threadIdx.y;
    int i0 = 2 * ti + 1, j0 = 2 * tj + 1;     // top-left node of 2x2 group
    if (i0 > NI || j0 > NI) return;
    const float* xp = xin + (long long)b * NN;
    const float* ap = a + (long long)b * NCC;
    const float* fp = f + (long long)b * NN;
    const float* dp = dinv + (long long)b * NII;
    float* xo = xout + (long long)b * NN;

    float xx[4][4];
#pragma unroll
    for (int di = 0; di < 4; di++) {
        int ii = i0 - 1 + di;
        bool vi = (ii <= NG - 1);
#pragma unroll
        for (int dj = 0; dj < 4; dj++) {
            int jj = j0 - 1 + dj;
            xx[di][dj] = (vi && jj <= NG - 1) ? xp[(long long)ii * NG + jj] : 0.f;
        }
    }
    float ax[3][3];
#pragma unroll
    for (int di = 0; di < 3; di++) {
        int II = i0 - 1 + di;
        bool vi = (II <= NC - 1);
#pragma unroll
        for (int dj = 0; dj < 3; dj++) {
            int JJ = j0 - 1 + dj;
            ax[di][dj] = (vi && JJ <= NC - 1) ? ap[(long long)II * NC + JJ] : 0.f;
        }
    }

    const float c23 = 2.f / 3.f, c16 = -1.f / 6.f, c13 = -1.f / 3.f;
#pragma unroll
    for (int u = 0; u < 2; u++) {
#pragma unroll
        for (int v = 0; v < 2; v++) {
            int i = i0 + u, j = j0 + v;
            if (i > NI || j > NI) continue;
            float s = 0.f;
#pragma unroll
            for (int uu = 0; uu < 2; uu++) {
#pragma unroll
                for (int vv = 0; vv < 2; vv++) {
                    float av = ax[u + uu][v + vv];
                    float k0, k1, k2, k3;
                    if (uu == 0 && vv == 0) { k0 = c16; k1 = c23; k2 = c16; k3 = c13; }
                    else if (uu == 0 && vv == 1) { k0 = c23; k1 = c16; k2 = c13; k3 = c16; }
                    else if (uu == 1 && vv == 0) { k0 = c13; k1 = c16; k2 = c23; k3 = c16; }
                    else                          { k0 = c16; k1 = c13; k2 = c16; k3 = c23; }
                    s += av * (k3 * xx[u + uu][v + vv]
                             + k2 * xx[u + uu][v + vv + 1]
                             + k0 * xx[u + uu + 1][v + vv]
                             + k1 * xx[u + uu + 1][v + vv + 1]);
                }
            }
            long long o = (long long)i * NG + j;
            float r = fp[o] - s;
            xo[o] = xx[1 + u][1 + v]
                  + 0.75f * dp[(long long)(i - 1) * NI + (j - 1)] * r;
        }
    }
}

__global__ __launch_bounds__(256)
void k_resid(const float* __restrict__ x, const float* __restrict__ f,
             const float* __restrict__ a, float* __restrict__ r)
{
    int b = blockIdx.z;
    int j = blockIdx.x * 16 + threadIdx.x;
    int i = blockIdx.y * 16 + threadIdx.y;
    if (i >= NG || j >= NG) return;
    long long o = (long long)b * NN + (long long)i * NG + j;
    float d = 0.f;
    if (i > 0 && j > 0 && i < NG - 1 && j < NG - 1)
        d = darcy_at(x + (long long)b * NN, a + (long long)b * NCC, i, j);
    r[o] = f[o] - d;
}

// ---------------------------------------------------------------------------
// Real SGEMM, double-buffered. C = alpha*A(MxK)*B(KxN). Tile 64x64, BK=16.
// MIR: 0 = plain; 1 = mirror columns about 256 (col = 256+gn, -val at 256-gn);
//      2 = mirror rows about 256.
// ---------------------------------------------------------------------------
template<int MIR>
__global__ __launch_bounds__(256)
void k_sgemm(const float* __restrict__ A, int lda, long long sA,
             const float* __restrict__ B, int ldb, long long sB,
             float* __restrict__ C, int ldc, long long sC,
             int M, int N, int K, float alpha)
{
    __shared__ float As[2][16][68];
    __shared__ float Bs[2][16][68];
    int b = blockIdx.z;
    A += (long long)b * sA;
    B += (long long)b * sB;
    C += (long long)b * sC;
    int tid = threadIdx.x;
    int m0 = blockIdx.y * 64, n0 = blockIdx.x * 64;
    int mt = (tid & 15) * 4;
    int nt = (tid >> 4) * 4;
    int ra_r[4], ra_c[4], rb_r[4], rb_c[4];
#pragma unroll
    for (int e = 0; e < 4; e++) {
        int idx = tid + e * 256;
        ra_r[e] = idx >> 4; ra_c[e] = idx & 15;
        rb_r[e] = idx >> 6; rb_c[e] = idx & 63;
    }
    float ra[4], rb[4];
    int ntiles = (K + 15) / 16;

    // prologue: tile 0
#pragma unroll
    for (int e = 0; e < 4; e++) {
        int gm = m0 + ra_r[e], gk = ra_c[e];
        ra[e] = (gm < M && gk < K) ? A[(long long)gm * lda + gk] : 0.f;
        int gk2 = rb_r[e], gn = n0 + rb_c[e];
        rb[e] = (gk2 < K && gn < N) ? B[(long long)gk2 * ldb + gn] : 0.f;
    }
#pragma unroll
    for (int e = 0; e < 4; e++) {
        As[0][ra_c[e]][ra_r[e]] = ra[e];
        Bs[0][rb_r[e]][rb_c[e]] = rb[e];
    }
    __syncthreads();

    float acc[4][4] = {};
    for (int t = 0; t < ntiles; t++) {
        int kt = (t + 1) * 16;
        if (t + 1 < ntiles) {
#pragma unroll
            for (int e = 0; e < 4; e++) {
                int gm = m0 + ra_r[e], gk = kt + ra_c[e];
                ra[e] = (gm < M && gk < K) ? A[(long long)gm * lda + gk] : 0.f;
                int gk2 = kt + rb_r[e], gn = n0 + rb_c[e];
                rb[e] = (gk2 < K && gn < N) ? B[(long long)gk2 * ldb + gn] : 0.f;
            }
        }
        int cur = t & 1;
#pragma unroll
        for (int k = 0; k < 16; k++) {
            float av[4], bv[4];
#pragma unroll
            for (int i = 0; i < 4; i++) av[i] = As[cur][k][mt + i];
#pragma unroll
            for (int j = 0; j < 4; j++) bv[j] = Bs[cur][k][nt + j];
#pragma unroll
            for (int i = 0; i < 4; i++)
#pragma unroll
                for (int j = 0; j < 4; j++)
                    acc[i][j] = fmaf(av[i], bv[j], acc[i][j]);
        }
        if (t + 1 < ntiles) {
            int nxt = cur ^ 1;
#pragma unroll
            for (int e = 0; e < 4; e++) {
                As[nxt][ra_c[e]][ra_r[e]] = ra[e];
                Bs[nxt][rb_r[e]][rb_c[e]] = rb[e];
            }
        }
        __syncthreads();
    }

#pragma unroll
    for (int i = 0; i < 4; i++) {
        int gm = m0 + mt + i;
        if (gm >= M) continue;
#pragma unroll
        for (int j = 0; j < 4; j++) {
            int gn = n0 + nt + j;
            if (gn >= N) continue;
            float v = alpha * acc[i][j];
            if (MIR == 0) {
                C[(long long)gm * ldc + gn] = v;
            } else if (MIR == 1) {
                C[(long long)gm * ldc + 256 + gn] = v;
                if (gn > 0) C[(long long)gm * ldc + 256 - gn] = -v;
            } else {
                C[(long long)(256 + gm) * ldc + gn] = v;
                if (gm > 0) C[(long long)(256 - gm) * ldc + gn] = -v;
            }
        }
    }
}

// ---------------------------------------------------------------------------
// Complex GEMM, double-buffered. REAL_OUT keeps only Re.
// ---------------------------------------------------------------------------
DINLINE float2 cmad(float2 acc, float2 a, float2 b)
{
    acc.x = fmaf(a.x, b.x, fmaf(-a.y, b.y, acc.x));
    acc.y = fmaf(a.x, b.y, fmaf(a.y, b.x, acc.y));
    return acc;
}

template<bool REAL_OUT>
__global__ __launch_bounds__(256)
void k_cgemm(const float2* __restrict__ A, int lda, long long sA,
             const float2* __restrict__ B, int ldb, long long sB,
             void* __restrict__ Cv, int ldc, long long sC,
             int M, int N, int K)
{
    __shared__ float2 As[2][16][66];
    __shared__ float2 Bs[2][16][66];
    int b = blockIdx.z;
    A += (long long)b * sA;
    B += (long long)b * sB;
    int tid = threadIdx.x;
    int m0 = blockIdx.y * 64, n0 = blockIdx.x * 64;
    int mt = (tid & 15) * 4;
    int nt = (tid >> 4) * 4;
    int ra_r[4], ra_c[4], rb_r[4], rb_c[4];
#pragma unroll
    for (int e = 0; e < 4; e++) {
        int idx = tid + e * 256;
        ra_r[e] = idx >> 4; ra_c[e] = idx & 15;
        rb_r[e] = idx >> 6; rb_c[e] = idx & 63;
    }
    float2 ra[4], rb[4];
    int ntiles = (K + 15) / 16;

#pragma unroll
    for (int e = 0; e < 4; e++) {
        int gm = m0 + ra_r[e], gk = ra_c[e];
        ra[e] = (gm < M && gk < K) ? A[(long long)gm * lda + gk] : make_float2(0.f, 0.f);
        int gk2 = rb_r[e], gn = n0 + rb_c[e];
        rb[e] = (gk2 < K && gn < N) ? B[(long long)gk2 * ldb + gn] : make_float2(0.f, 0.f);
    }
#pragma unroll
    for (int e = 0; e < 4; e++) {
        As[0][ra_c[e]][ra_r[e]] = ra[e];
        Bs[0][rb_r[e]][rb_c[e]] = rb[e];
    }
    __syncthreads();

    float2 accc[4][4];
    float  accr[4][4];
#pragma unroll
    for (int i = 0; i < 4; i++)
#pragma unroll
        for (int j = 0; j < 4; j++) { accc[i][j] = make_float2(0.f, 0.f); accr[i][j] = 0.f; }

    for (int t = 0; t < ntiles; t++) {
        int kt = (t + 1) * 16;
        if (t + 1 < ntiles) {
#pragma unroll
            for (int e = 0; e < 4; e++) {
                int gm = m0 + ra_r[e], gk = kt + ra_c[e];
                ra[e] = (gm < M && gk < K) ? A[(long long)gm * lda + gk] : make_float2(0.f, 0.f);
                int gk2 = kt + rb_r[e], gn = n0 + rb_c[e];
                rb[e] = (gk2 < K && gn < N) ? B[(long long)gk2 * ldb + gn] : make_float2(0.f, 0.f);
            }
        }
        int cur = t & 1;
#pragma unroll
        for (int k = 0; k < 16; k++) {
            float2 av[4], bv[4];
#pragma unroll
            for (int i = 0; i < 4; i++) av[i] = As[cur][k][mt + i];
#pragma unroll
            for (int j = 0; j < 4; j++) bv[j] = Bs[cur][k][nt + j];
#pragma unroll
            for (int i = 0; i < 4; i++)
#pragma unroll
                for (int j = 0; j < 4; j++) {
                    if (REAL_OUT) {
                        accr[i][j] = fmaf(av[i].x, bv[j].x,
                                     fmaf(-av[i].y, bv[j].y, accr[i][j]));
                    } else {
                        accc[i][j] = cmad(accc[i][j], av[i], bv[j]);
                    }
                }
        }
        if (t + 1 < ntiles) {
            int nxt = cur ^ 1;
#pragma unroll
            for (int e = 0; e < 4; e++) {
                As[nxt][ra_c[e]][ra_r[e]] = ra[e];
                Bs[nxt][rb_r[e]][rb_c[e]] = rb[e];
            }
        }
        __syncthreads();
    }

#pragma unroll
    for (int i = 0; i < 4; i++) {
        int gm = m0 + mt + i;
        if (gm >= M) continue;
#pragma unroll
        for (int j = 0; j < 4; j++) {
            int gn = n0 + nt + j;
            if (gn >= N) continue;
            if (REAL_OUT) {
                float* C = (float*)Cv;
                C[(long long)b * sC + (long long)gm * ldc + gn] = accr[i][j];
            } else {
                float2* C = (float2*)Cv;
                C[(long long)b * sC + (long long)gm * ldc + gn] = accc[i][j];
            }
        }
    }
}

// ---------------------------------------------------------------------------
// Real-input complex conv (first forward conv)
// ---------------------------------------------------------------------------
template<bool GUARD>
DINLINE void conv_r41_body(const float* __restrict__ Xb, float2* __restrict__ acc,
                           const float2* __restrict__ ws, int p, int q)
{
#pragma unroll
    for (int dy = 0; dy < 3; dy++) {
        int ii = p + dy - 1;
#pragma unroll
        for (int dx = 0; dx < 3; dx++) {
            int jj = q + dx - 1;
            float xv;
            if (GUARD)
                xv = (ii >= 0 && ii < NG && jj >= 0 && jj < NG)
                   ? Xb[(long long)ii * NG + jj] : 0.f;
            else
                xv = Xb[(long long)ii * NG + jj];
            int tap = dy * 3 + dx;
#pragma unroll
            for (int o = 0; o < 4; o++) {
                float2 w = ws[o * 9 + tap];
                acc[o].x = fmaf(xv, w.x, acc[o].x);
                acc[o].y = fmaf(xv, w.y, acc[o].y);
            }
        }
    }
}

__global__ __launch_bounds__(256)
void k_conv_r41(const float* __restrict__ X, float2* __restrict__ Y,
                const float* __restrict__ wr, const float* __restrict__ wi)
{
    int b = blockIdx.z;
    __shared__ float2 ws[36];
    int t = threadIdx.y * 16 + threadIdx.x;
    if (t < 36) ws[t] = make_float2(wr[b * 36 + t], wi[b * 36 + t]);
    __syncthreads();
    int q = blockIdx.x * 16 + threadIdx.x;
    int p = blockIdx.y * 16 + threadIdx.y;
    if (p >= NG || q >= NG) return;
    const float* Xb = X + (long long)b * NN;
    float2 acc[4];
#pragma unroll
    for (int o = 0; o < 4; o++) acc[o] = make_float2(0.f, 0.f);
    int p0 = blockIdx.y * 16, q0 = blockIdx.x * 16;
    bool interior = (p0 >= 1) && (p0 + 15 <= NG - 2) && (q0 >= 1) && (q0 + 15 <= NG - 2);
    if (interior) conv_r41_body<false>(Xb, acc, ws, p, q);
    else          conv_r41_body<true >(Xb, acc, ws, p, q);
    float2* Yb = Y + (long long)b * 4 * NN;
    long long po = (long long)p * NG + q;
#pragma unroll
    for (int o = 0; o < 4; o++) Yb[(long long)o * NN + po] = acc[o];
}

// ---------------------------------------------------------------------------
// Complex multi-channel 3x3 conv (pad=1). WTIK fuses wt*ik2 (CO==1 use only).
// ---------------------------------------------------------------------------
template<int CO, int CI, bool GUARD>
DINLINE void conv_body(const float2* __restrict__ Xb, float2* __restrict__ acc,
                       const float2* __restrict__ ws, int p, int q)
{
#pragma unroll
    for (int i = 0; i < CI; i++) {
#pragma unroll
        for (int dy = 0; dy < 3; dy++) {
            int ii = p + dy - 1;
#pragma unroll
            for (int dx = 0; dx < 3; dx++) {
                int jj = q + dx - 1;
                float2 xv;
                if (GUARD)
                    xv = (ii >= 0 && ii < NG && jj >= 0 && jj < NG)
                       ? Xb[(long long)i * NN + (long long)ii * NG + jj]
                       : make_float2(0.f, 0.f);
                else
                    xv = Xb[(long long)i * NN + (long long)ii * NG + jj];
                int tap = dy * 3 + dx;
#pragma unroll
                for (int o = 0; o < CO; o++)
                    acc[o] = cmad(acc[o], xv, ws[(o * CI + i) * 9 + tap]);
            }
        }
    }
}

template<int CO, int CI, bool WTIK>
__global__ __launch_bounds__(256)
void k_conv(const float2* __restrict__ X, float2* __restrict__ Y,
            const float* __restrict__ wr, const float* __restrict__ wi,
            int conjt, const float* __restrict__ wtr,
            const float* __restrict__ wti)
{
    int b = blockIdx.z;
    __shared__ float2 ws[CO * CI * 9];
    int t = threadIdx.y * 16 + threadIdx.x;
    if (t < CO * CI * 9) {
        int o = t / (CI * 9), rem = t % (CI * 9), i = rem / 9, tap = rem % 9;
        int dy = tap / 3, dx = tap % 3;
        long long widx;
        float sgn;
        if (conjt) { widx = ((long long)(b * CI + i) * CO + o) * 9 + dx * 3 + dy; sgn = -1.f; }
        else       { widx = ((long long)(b * CO + o) * CI + i) * 9 + dy * 3 + dx; sgn =  1.f; }
        ws[t] = make_float2(wr[widx], sgn * wi[widx]);
    }
    __syncthreads();
    int q = blockIdx.x * 16 + threadIdx.x;
    int p = blockIdx.y * 16 + threadIdx.y;
    if (p >= NG || q >= NG) return;
    const float2* Xb = X + (long long)b * CI * NN;
    float2 acc[CO];
#pragma unroll
    for (int o = 0; o < CO; o++) acc[o] = make_float2(0.f, 0.f);
    int p0 = blockIdx.y * 16, q0 = blockIdx.x * 16;
    bool interior = (p0 >= 1) && (p0 + 15 <= NG - 2) && (q0 >= 1) && (q0 + 15 <= NG - 2);
    if (interior) conv_body<CO, CI, false>(Xb, acc, ws, p, q);
    else          conv_body<CO, CI, true >(Xb, acc, ws, p, q);

    float2* Yb = Y + (long long)b * CO * NN;
    long long po = (long long)p * NG + q;
    if (WTIK) {
        long long o = (long long)b * NN + po;
        float wrv = wtr[o], wiv = wti[o];
        float dp = (float)(p - 256), dq = (float)(q - 256);
        float s = dp * dp + dq * dq;
        const float pi2 = 9.869604401089358f;
        float ik = (s == 0.f) ? 1.f : 1.f / (pi2 * s);
        float2 c = acc[0];
        float2 rr;
        rr.x = (c.x * wrv - c.y * wiv) * ik;
        rr.y = (c.x * wiv + c.y * wrv) * ik;
        Yb[po] = rr;
    } else {
#pragma unroll
        for (int o = 0; o < CO; o++) Yb[(long long)o * NN + po] = acc[o];
    }
}

// ---------------------------------------------------------------------------
// Reductions (deterministic, double accumulation)
// ---------------------------------------------------------------------------
__global__ __launch_bounds__(256)
void k_alpha_part(const float* __restrict__ r, const float* __restrict__ e,
                  const float* __restrict__ a, double* __restrict__ p1,
                  double* __restrict__ p2)
{
    int b = blockIdx.y;
    const float* rb = r + (long long)b * NN;
    const float* eb = e + (long long)b * NN;
    const float* ab = a + (long long)b * NCC;
    double num = 0.0, den = 0.0;
    for (long long idx = (long long)blockIdx.x * 256 + threadIdx.x; idx < NN;
         idx += (long long)gridDim.x * 256) {
        int i = (int)(idx / NG), j = (int)(idx - (long long)i * NG);
        float ev = eb[idx];
        num += (double)(rb[idx] * ev);
        if (i > 0 && j > 0 && i < NG - 1 && j < NG - 1) {
            float d = darcy_at(eb, ab, i, j);
            den += (double)(d * ev);
        }
    }
    __shared__ double s1[256], s2[256];
    int t = threadIdx.x;
    s1[t] = num; s2[t] = den;
    __syncthreads();
    for (int s = 128; s > 0; s >>= 1) {
        if (t < s) { s1[t] += s1[t + s]; s2[t] += s2[t + s]; }
        __syncthreads();
    }
    if (t == 0) { p1[b * NBLK_A + blockIdx.x] = s1[0]; p2[b * NBLK_A + blockIdx.x] = s2[0]; }
}

__global__ void k_alpha_fin(const double* __restrict__ p1,
                            const double* __restrict__ p2,
                            float* __restrict__ alpha)
{
    int b = blockIdx.x;
    __shared__ double s1[256], s2[256];
    double n = 0.0, d = 0.0;
    for (int i = threadIdx.x; i < NBLK_A; i += 256) {
        n += p1[b * NBLK_A + i]; d += p2[b * NBLK_A + i];
    }
    int t = threadIdx.x;
    s1[t] = n; s2[t] = d;
    __syncthreads();
    for (int s = 128; s > 0; s >>= 1) {
        if (t < s) { s1[t] += s1[t + s]; s2[t] += s2[t + s]; }
        __syncthreads();
    }
    if (t == 0) alpha[b] = (float)(s1[0] / s2[0]);
}

__global__ void k_update(float* __restrict__ x, const float* __restrict__ e,
                         const float* __restrict__ alpha)
{
    int b = blockIdx.z;
    int j = blockIdx.x * 16 + threadIdx.x + 1;
    int i = blockIdx.y * 16 + threadIdx.y + 1;
    if (i > NI || j > NI) return;
    long long o = (long long)b * NN + (long long)i * NG + j;
    x[o] = fmaf(alpha[b], e[o], x[o]);
}

__global__ __launch_bounds__(256)
void k_norm_part(const float* __restrict__ r, const float* __restrict__ f,
                 double* __restrict__ p1, double* __restrict__ p2)
{
    double sr = 0.0, sf = 0.0;
    long long tot = (long long)NB * NN;
    for (long long idx = (long long)blockIdx.x * 256 + threadIdx.x; idx < tot;
         idx += (long long)gridDim.x * 256) {
        float rv = r[idx], fv = f[idx];
        sr += (double)rv * rv;
        sf += (double)fv * fv;
    }
    __shared__ double s1[256], s2[256];
    int t = threadIdx.x;
    s1[t] = sr; s2[t] = sf;
    __syncthreads();
    for (int s = 128; s > 0; s >>= 1) {
        if (t < s) { s1[t] += s1[t + s]; s2[t] += s2[t + s]; }
        __syncthreads();
    }
    if (t == 0) { p1[blockIdx.x] = s1[0]; p2[blockIdx.x] = s2[0]; }
}

__global__ void k_norm_fin(const double* __restrict__ p1,
                           const double* __restrict__ p2,
                           float* __restrict__ out)
{
    __shared__ double s1[256], s2[256];
    double a = 0.0, b = 0.0;
    for (int i = threadIdx.x; i < NBLK_N; i += 256) { a += p1[i]; b += p2[i]; }
    int t = threadIdx.x;
    s1[t] = a; s2[t] = b;
    __syncthreads();
    for (int s = 128; s > 0; s >>= 1) {
        if (t < s) { s1[t] += s1[t + s]; s2[t] += s2[t + s]; }
        __syncthreads();
    }
    if (t == 0) out[0] = (float)sqrt(s1[0] / s2[0]);
}

// ---------------------------------------------------------------------------
// Host orchestration
// ---------------------------------------------------------------------------
template<typename T>
static T* sym_addr(const void* sym)
{
    void* p = nullptr;
    cudaGetSymbolAddress(&p, sym);
    return (T*)p;
}

extern "C" void kernel_launch(void* const* d_in, const int* in_sizes, int n_in,
                              void* d_out, int out_size)
{
    const float* f    = (const float*)d_in[0];
    const float* coef = (const float*)d_in[1];
    const float* w1r = (const float*)d_in[3];
    const float* w1i = (const float*)d_in[4];
    const float* w2r = (const float*)d_in[5];
    const float* w2i = (const float*)d_in[6];
    const float* w3r = (const float*)d_in[7];
    const float* w3i = (const float*)d_in[8];
    const float* wtr = (const float*)d_in[9];
    const float* wti = (const float*)d_in[10];

    float*  x    = sym_addr<float>(g_x);
    float*  x2   = sym_addr<float>(g_x2);
    float*  r    = sym_addr<float>(g_r);
    float*  e    = sym_addr<float>(g_e);
    float*  rh   = sym_addr<float>(g_rh);
    float*  dinv = sym_addr<float>(g_dinv);
    float*  S    = sym_addr<float>(g_S);
    float*  St   = sym_addr<float>(g_St);
    float2* G    = sym_addr<float2>(g_G);
    float2* Gt   = sym_addr<float2>(g_Gt);
    float*  U    = sym_addr<float>(g_U);
    float2* cA   = sym_addr<float2>(g_cA);
    float2* cB   = sym_addr<float2>(g_cB);
    float2* cC   = sym_addr<float2>(g_cC);
    float2* W    = sym_addr<float2>(g_W);
    double* pd1  = sym_addr<double>(g_pd1);
    double* pd2  = sym_addr<double>(g_pd2);
    float*  alph = sym_addr<float>(g_alpha);

    dim3 blk2(16, 16);
    dim3 gInt((NI + 15) / 16, (NI + 15) / 16, NB);
    dim3 gFull((NG + 15) / 16, (NG + 15) / 16, NB);
    dim3 gJac(16, 16, NB);   // 2x2 nodes per thread, 16x16 threads -> 32x32 nodes/blk

    // ---- setup ----
    {
        long long tot = (long long)NB * NN;
        k_zero3<<<(int)((tot + 255) / 256), 256>>>(x, x2, e);
        int nSG = NG * NI;
        k_precS<<<(nSG + 255) / 256, 256>>>(S, St);
        k_precG<<<(nSG + 255) / 256, 256>>>(G, Gt);
        k_dinv<<<gInt, blk2>>>(coef, dinv);
    }

    float* xa = x;
    float* xb = x2;

    for (int step = 0; step < KSTEPS; step++) {
        // ---- 10 Jacobi sweeps ----
        for (int it = 0; it < 10; it++) {
            k_jacobi2<<<gJac, blk2>>>(xa, xb, f, coef, dinv);
            float* tmp = xa; xa = xb; xb = tmp;
        }
        // ---- residual ----
        k_resid<<<gFull, blk2>>>(xa, f, coef, r);

        // ---- forward sine transform (odd symmetry fused in epilogue) ----
        // U[i][256 +- c] = (r_int * St[:,256+c]), c = 0..256
        {
            dim3 g((257 + 63) / 64, (NI + 63) / 64, NB);
            k_sgemm<1><<<g, 256>>>(r + NG + 1, NG, NN,
                                   St + 256, NG, 0,
                                   U, NG, NIG,
                                   NI, 257, NI, 1.f);
        }
        // rh[256 +- t][q] = -(1/512^2) (S[256+t,:] * U)
        {
            dim3 g((NG + 63) / 64, (257 + 63) / 64, NB);
            k_sgemm<2><<<g, 256>>>(S + 256 * NI, NI, 0,
                                   U, NG, NIG,
                                   rh, NG, NN,
                                   257, NG, NI, -1.f / (512.f * 512.f));
        }

        // ---- 3 complex convs forward (first real-input, third fused w/ wt*ik2) ----
        k_conv_r41<<<gFull, blk2>>>(rh, cA, w1r, w1i);
        k_conv<4, 4, false><<<gFull, blk2>>>(cA, cB, w2r, w2i, 0, nullptr, nullptr);
        k_conv<1, 4, true ><<<gFull, blk2>>>(cB, cC, w3r, w3i, 0, wtr, wti);

        // ---- 3 complex convs backward (conjT) ----
        k_conv<4, 1, false><<<gFull, blk2>>>(cC, cA, w3r, w3i, 1, nullptr, nullptr);
        k_conv<4, 4, false><<<gFull, blk2>>>(cA, cB, w2r, w2i, 1, nullptr, nullptr);
        k_conv<1, 4, false><<<gFull, blk2>>>(cB, cC, w1r, w1i, 1, nullptr, nullptr);

        // ---- inverse transform: W = cC * Gt, e_int = Re(G * W) ----
        {
            dim3 g((NI + 63) / 64, (NG + 63) / 64, NB);
            k_cgemm<false><<<g, 256>>>(cC, NG, NN,
                                       Gt, NI, 0,
                                       W, NI, NIG,
                                       NG, NI, NG);
        }
        {
            dim3 g((NI + 63) / 64, (NI + 63) / 64, NB);
            k_cgemm<true><<<g, 256>>>(G, NG, 0,
                                      W, NI, NIG,
                                      e + NG + 1, NG, NN,
                                      NI, NI, NG);
        }

        // ---- alpha and update ----
        {
            dim3 g(NBLK_A, NB);
            k_alpha_part<<<g, 256>>>(r, e, coef, pd1, pd2);
            k_alpha_fin<<<NB, 256>>>(pd1, pd2, alph);
            k_update<<<gInt, blk2>>>(xa, e, alph);
        }
    }

    // ---- final relative residual norm ----
    k_resid<<<gFull, blk2>>>(xa, f, coef, r);
    k_norm_part<<<NBLK_N, 256>>>(r, f, pd1, pd2);
    k_norm_fin<<<1, 256>>>(pd1, pd2, (float*)d_out);
}

// round 6
// speedup vs baseline: 1.6502x; 1.0688x over previous
#include <cuda_runtime.h>
#include <math.h>

#define DINLINE __device__ __forceinline__

// ---------------------------------------------------------------------------
// Fixed problem dimensions (B=4, grid 513, coef 512, epoch=101 -> K=2)
// ---------------------------------------------------------------------------
namespace fns {
constexpr int NB = 4;
constexpr int NG = 513;
constexpr int NI = 511;
constexpr int NC = 512;
constexpr long long NN  = (long long)NG * NG;
constexpr long long NCC = (long long)NC * NC;
constexpr long long NII = (long long)NI * NI;
constexpr long long NIG = (long long)NI * NG;
constexpr int NBLK_A = 128;
constexpr int NBLK_N = 256;
constexpr int KSTEPS = 2;
}
using namespace fns;

// ---------------------------------------------------------------------------
// Static device scratch
// ---------------------------------------------------------------------------
__device__ float  g_x   [NB * NN];
__device__ float  g_x2  [NB * NN];
__device__ float  g_r   [NB * NN];
__device__ float  g_e   [NB * NN];
__device__ float  g_rh  [NB * NN];
__device__ float  g_dinv[NB * NII];
__device__ float  g_S   [NG * (long long)NI];  // S[p][j], ld=NI
__device__ float  g_St  [NIG];                 // St[j][p], ld=NG
__device__ float2 g_G   [NIG];                 // G[s][u],  ld=NG
__device__ float2 g_Gt  [NIG];                 // Gt[u][s], ld=NI
__device__ float  g_U   [NB * NIG];            // 511 x 513, ld=NG
__device__ float2 g_cA  [NB * 4 * NN];
__device__ float2 g_cB  [NB * 4 * NN];
__device__ float2 g_cC  [NB * NN];
__device__ float2 g_W   [NB * NIG];            // 513x511, ld=NI
__device__ double g_pd1 [2048];
__device__ double g_pd2 [2048];
__device__ float  g_alpha[NB];

// ---------------------------------------------------------------------------
// Darcy FEM 9-point stencil (pointer form, used by resid / alpha)
// ---------------------------------------------------------------------------
DINLINE float darcy_at(const float* __restrict__ x,
                       const float* __restrict__ a, int i, int j)
{
    const float c23 = 2.f / 3.f, c16 = -1.f / 6.f, c13 = -1.f / 3.f;
    float s = 0.f;
#pragma unroll
    for (int u = 0; u < 2; u++) {
#pragma unroll
        for (int v = 0; v < 2; v++) {
            int I = i - 1 + u, J = j - 1 + v;
            float av = a[(long long)I * NC + J];
            float k0, k1, k2, k3;
            if (u == 0 && v == 0) { k0 = c16; k1 = c23; k2 = c16; k3 = c13; }
            else if (u == 0 && v == 1) { k0 = c23; k1 = c16; k2 = c13; k3 = c16; }
            else if (u == 1 && v == 0) { k0 = c13; k1 = c16; k2 = c23; k3 = c16; }
            else                        { k0 = c16; k1 = c13; k2 = c16; k3 = c23; }
            s += av * (k3 * x[(long long)I * NG + J]
                     + k2 * x[(long long)I * NG + J + 1]
                     + k0 * x[(long long)(I + 1) * NG + J]
                     + k1 * x[(long long)(I + 1) * NG + J + 1]);
        }
    }
    return s;
}

// ---------------------------------------------------------------------------
// Setup kernels
// ---------------------------------------------------------------------------
__global__ void k_precS(float* __restrict__ S, float* __restrict__ St)
{
    int idx = blockIdx.x * blockDim.x + threadIdx.x;
    if (idx >= NG * NI) return;
    int p = idx / NI, j = idx - p * NI;
    int m = (j + 1) * (p - 256);
    int mm = ((m % 1024) + 1024) % 1024;
    float v = sinpif((float)mm / 512.f);
    S[idx] = v;
    St[(long long)j * NG + p] = v;
}

__global__ void k_precG(float2* __restrict__ G, float2* __restrict__ Gt)
{
    int idx = blockIdx.x * blockDim.x + threadIdx.x;
    if (idx >= NI * NG) return;
    int s = idx / NG, u = idx - s * NG;
    int t = (u - 255) * s;
    int tm = ((t % 1025) + 1025) % 1025;
    float xr = 2.f * (float)tm / 1025.f;
    float2 g = make_float2(cospif(xr), -sinpif(xr));
    G[idx] = g;
    Gt[(long long)u * NI + s] = g;
}

__global__ void k_dinv(const float* __restrict__ a, float* __restrict__ dinv)
{
    int b = blockIdx.z;
    int q = blockIdx.x * 16 + threadIdx.x;
    int p = blockIdx.y * 16 + threadIdx.y;
    if (p >= NI || q >= NI) return;
    const float* ap = a + (long long)b * NCC;
    float s = ap[(long long)p * NC + q] + ap[(long long)p * NC + q + 1]
            + ap[(long long)(p + 1) * NC + q] + ap[(long long)(p + 1) * NC + q + 1];
    dinv[(long long)b * NII + (long long)p * NI + q] = 1.f / ((2.f / 3.f) * s);
}

__global__ void k_zero3(float* __restrict__ x, float* __restrict__ x2,
                        float* __restrict__ e)
{
    long long idx = (long long)blockIdx.x * blockDim.x + threadIdx.x;
    long long tot = (long long)NB * NN;
    if (idx >= tot) return;
    x[idx] = 0.f; x2[idx] = 0.f; e[idx] = 0.f;
}

// ---------------------------------------------------------------------------
// Jacobi sweep: 2x2 nodes per thread
// ---------------------------------------------------------------------------
__global__ __launch_bounds__(256)
void k_jacobi2(const float* __restrict__ xin, float* __restrict__ xout,
               const float* __restrict__ f, const float* __restrict__ a,
               const float* __restrict__ dinv)
{
    int b = blockIdx.z;
    int tj = blockIdx.x * 16 + threadIdx.x;
    int ti = blockIdx.y * 16 + threadIdx.y;
    int i0 = 2 * ti + 1, j0 = 2 * tj + 1;
    if (i0 > NI || j0 > NI) return;
    const float* xp = xin + (long long)b * NN;
    const float* ap = a + (long long)b * NCC;
    const float* fp = f + (long long)b * NN;
    const float* dp = dinv + (long long)b * NII;
    float* xo = xout + (long long)b * NN;

    float xx[4][4];
#pragma unroll
    for (int di = 0; di < 4; di++) {
        int ii = i0 - 1 + di;
        bool vi = (ii <= NG - 1);
#pragma unroll
        for (int dj = 0; dj < 4; dj++) {
            int jj = j0 - 1 + dj;
            xx[di][dj] = (vi && jj <= NG - 1) ? xp[(long long)ii * NG + jj] : 0.f;
        }
    }
    float ax[3][3];
#pragma unroll
    for (int di = 0; di < 3; di++) {
        int II = i0 - 1 + di;
        bool vi = (II <= NC - 1);
#pragma unroll
        for (int dj = 0; dj < 3; dj++) {
            int JJ = j0 - 1 + dj;
            ax[di][dj] = (vi && JJ <= NC - 1) ? ap[(long long)II * NC + JJ] : 0.f;
        }
    }

    const float c23 = 2.f / 3.f, c16 = -1.f / 6.f, c13 = -1.f / 3.f;
#pragma unroll
    for (int u = 0; u < 2; u++) {
#pragma unroll
        for (int v = 0; v < 2; v++) {
            int i = i0 + u, j = j0 + v;
            if (i > NI || j > NI) continue;
            float s = 0.f;
#pragma unroll
            for (int uu = 0; uu < 2; uu++) {
#pragma unroll
                for (int vv = 0; vv < 2; vv++) {
                    float av = ax[u + uu][v + vv];
                    float k0, k1, k2, k3;
                    if (uu == 0 && vv == 0) { k0 = c16; k1 = c23; k2 = c16; k3 = c13; }
                    else if (uu == 0 && vv == 1) { k0 = c23; k1 = c16; k2 = c13; k3 = c16; }
                    else if (uu == 1 && vv == 0) { k0 = c13; k1 = c16; k2 = c23; k3 = c16; }
                    else                          { k0 = c16; k1 = c13; k2 = c16; k3 = c23; }
                    s += av * (k3 * xx[u + uu][v + vv]
                             + k2 * xx[u + uu][v + vv + 1]
                             + k0 * xx[u + uu + 1][v + vv]
                             + k1 * xx[u + uu + 1][v + vv + 1]);
                }
            }
            long long o = (long long)i * NG + j;
            float r = fp[o] - s;
            xo[o] = xx[1 + u][1 + v]
                  + 0.75f * dp[(long long)(i - 1) * NI + (j - 1)] * r;
        }
    }
}

__global__ __launch_bounds__(256)
void k_resid(const float* __restrict__ x, const float* __restrict__ f,
             const float* __restrict__ a, float* __restrict__ r)
{
    int b = blockIdx.z;
    int j = blockIdx.x * 16 + threadIdx.x;
    int i = blockIdx.y * 16 + threadIdx.y;
    if (i >= NG || j >= NG) return;
    long long o = (long long)b * NN + (long long)i * NG + j;
    float d = 0.f;
    if (i > 0 && j > 0 && i < NG - 1 && j < NG - 1)
        d = darcy_at(x + (long long)b * NN, a + (long long)b * NCC, i, j);
    r[o] = f[o] - d;
}

// ---------------------------------------------------------------------------
// Real SGEMM, double-buffered, 64x64/BK16, mirror epilogues (proven R4).
// ---------------------------------------------------------------------------
template<int MIR>
__global__ __launch_bounds__(256)
void k_sgemm(const float* __restrict__ A, int lda, long long sA,
             const float* __restrict__ B, int ldb, long long sB,
             float* __restrict__ C, int ldc, long long sC,
             int M, int N, int K, float alpha)
{
    __shared__ float As[2][16][68];
    __shared__ float Bs[2][16][68];
    int b = blockIdx.z;
    A += (long long)b * sA;
    B += (long long)b * sB;
    C += (long long)b * sC;
    int tid = threadIdx.x;
    int m0 = blockIdx.y * 64, n0 = blockIdx.x * 64;
    int mt = (tid & 15) * 4;
    int nt = (tid >> 4) * 4;
    int ra_r[4], ra_c[4], rb_r[4], rb_c[4];
#pragma unroll
    for (int e = 0; e < 4; e++) {
        int idx = tid + e * 256;
        ra_r[e] = idx >> 4; ra_c[e] = idx & 15;
        rb_r[e] = idx >> 6; rb_c[e] = idx & 63;
    }
    float ra[4], rb[4];
    int ntiles = (K + 15) / 16;

#pragma unroll
    for (int e = 0; e < 4; e++) {
        int gm = m0 + ra_r[e], gk = ra_c[e];
        ra[e] = (gm < M && gk < K) ? A[(long long)gm * lda + gk] : 0.f;
        int gk2 = rb_r[e], gn = n0 + rb_c[e];
        rb[e] = (gk2 < K && gn < N) ? B[(long long)gk2 * ldb + gn] : 0.f;
    }
#pragma unroll
    for (int e = 0; e < 4; e++) {
        As[0][ra_c[e]][ra_r[e]] = ra[e];
        Bs[0][rb_r[e]][rb_c[e]] = rb[e];
    }
    __syncthreads();

    float acc[4][4] = {};
    for (int t = 0; t < ntiles; t++) {
        int kt = (t + 1) * 16;
        if (t + 1 < ntiles) {
#pragma unroll
            for (int e = 0; e < 4; e++) {
                int gm = m0 + ra_r[e], gk = kt + ra_c[e];
                ra[e] = (gm < M && gk < K) ? A[(long long)gm * lda + gk] : 0.f;
                int gk2 = kt + rb_r[e], gn = n0 + rb_c[e];
                rb[e] = (gk2 < K && gn < N) ? B[(long long)gk2 * ldb + gn] : 0.f;
            }
        }
        int cur = t & 1;
#pragma unroll
        for (int k = 0; k < 16; k++) {
            float av[4], bv[4];
#pragma unroll
            for (int i = 0; i < 4; i++) av[i] = As[cur][k][mt + i];
#pragma unroll
            for (int j = 0; j < 4; j++) bv[j] = Bs[cur][k][nt + j];
#pragma unroll
            for (int i = 0; i < 4; i++)
#pragma unroll
                for (int j = 0; j < 4; j++)
                    acc[i][j] = fmaf(av[i], bv[j], acc[i][j]);
        }
        if (t + 1 < ntiles) {
            int nxt = cur ^ 1;
#pragma unroll
            for (int e = 0; e < 4; e++) {
                As[nxt][ra_c[e]][ra_r[e]] = ra[e];
                Bs[nxt][rb_r[e]][rb_c[e]] = rb[e];
            }
        }
        __syncthreads();
    }

#pragma unroll
    for (int i = 0; i < 4; i++) {
        int gm = m0 + mt + i;
        if (gm >= M) continue;
#pragma unroll
        for (int j = 0; j < 4; j++) {
            int gn = n0 + nt + j;
            if (gn >= N) continue;
            float v = alpha * acc[i][j];
            if (MIR == 0) {
                C[(long long)gm * ldc + gn] = v;
            } else if (MIR == 1) {
                C[(long long)gm * ldc + 256 + gn] = v;
                if (gn > 0) C[(long long)gm * ldc + 256 - gn] = -v;
            } else {
                C[(long long)(256 + gm) * ldc + gn] = v;
                if (gm > 0) C[(long long)(256 - gm) * ldc + gn] = -v;
            }
        }
    }
}

// ---------------------------------------------------------------------------
// Karatsuba complex GEMM: C = A*B, 3 real FFMA per complex MAC.
// Tile 64x64, BK=8, double-buffered; smem holds ar, ai, ar+ai / br, bi, br+bi.
// ---------------------------------------------------------------------------
__global__ __launch_bounds__(256)
void k_cgemm_kar(const float2* __restrict__ A, int lda, long long sA,
                 const float2* __restrict__ B, int ldb, long long sB,
                 float2* __restrict__ C, int ldc, long long sC,
                 int M, int N, int K)
{
    __shared__ __align__(16) float Ar[2][8][68], Ai[2][8][68], Au[2][8][68];
    __shared__ __align__(16) float Br[2][8][68], Bi[2][8][68], Bu[2][8][68];
    int b = blockIdx.z;
    A += (long long)b * sA;
    B += (long long)b * sB;
    C += (long long)b * sC;
    int tid = threadIdx.x;
    int m0 = blockIdx.y * 64, n0 = blockIdx.x * 64;
    int mt = (tid & 15) * 4;
    int nt = (tid >> 4) * 4;
    // loaders: 2 elements each for A and B (64x8 = 512 = 2*256)
    int la_m[2], la_k[2], lb_k[2], lb_n[2];
#pragma unroll
    for (int e = 0; e < 2; e++) {
        int idx = tid + e * 256;
        la_m[e] = idx >> 3; la_k[e] = idx & 7;
        lb_k[e] = idx >> 6; lb_n[e] = idx & 63;
    }
    float2 ra[2], rb[2];
    int ntiles = (K + 7) / 8;

#pragma unroll
    for (int e = 0; e < 2; e++) {
        int gm = m0 + la_m[e], gk = la_k[e];
        ra[e] = (gm < M && gk < K) ? A[(long long)gm * lda + gk] : make_float2(0.f, 0.f);
        int gk2 = lb_k[e], gn = n0 + lb_n[e];
        rb[e] = (gk2 < K && gn < N) ? B[(long long)gk2 * ldb + gn] : make_float2(0.f, 0.f);
    }
#pragma unroll
    for (int e = 0; e < 2; e++) {
        Ar[0][la_k[e]][la_m[e]] = ra[e].x;
        Ai[0][la_k[e]][la_m[e]] = ra[e].y;
        Au[0][la_k[e]][la_m[e]] = ra[e].x + ra[e].y;
        Br[0][lb_k[e]][lb_n[e]] = rb[e].x;
        Bi[0][lb_k[e]][lb_n[e]] = rb[e].y;
        Bu[0][lb_k[e]][lb_n[e]] = rb[e].x + rb[e].y;
    }
    __syncthreads();

    float a1[4][4] = {}, a2[4][4] = {}, a3[4][4] = {};
    for (int t = 0; t < ntiles; t++) {
        int kt = (t + 1) * 8;
        if (t + 1 < ntiles) {
#pragma unroll
            for (int e = 0; e < 2; e++) {
                int gm = m0 + la_m[e], gk = kt + la_k[e];
                ra[e] = (gm < M && gk < K) ? A[(long long)gm * lda + gk] : make_float2(0.f, 0.f);
                int gk2 = kt + lb_k[e], gn = n0 + lb_n[e];
                rb[e] = (gk2 < K && gn < N) ? B[(long long)gk2 * ldb + gn] : make_float2(0.f, 0.f);
            }
        }
        int cur = t & 1;
#pragma unroll
        for (int k = 0; k < 8; k++) {
            float arv[4], aiv[4], auv[4], brv[4], biv[4], buv[4];
            *(float4*)arv = *(const float4*)&Ar[cur][k][mt];
            *(float4*)aiv = *(const float4*)&Ai[cur][k][mt];
            *(float4*)auv = *(const float4*)&Au[cur][k][mt];
            *(float4*)brv = *(const float4*)&Br[cur][k][nt];
            *(float4*)biv = *(const float4*)&Bi[cur][k][nt];
            *(float4*)buv = *(const float4*)&Bu[cur][k][nt];
#pragma unroll
            for (int i = 0; i < 4; i++)
#pragma unroll
                for (int j = 0; j < 4; j++) {
                    a1[i][j] = fmaf(arv[i], brv[j], a1[i][j]);
                    a2[i][j] = fmaf(aiv[i], biv[j], a2[i][j]);
                    a3[i][j] = fmaf(auv[i], buv[j], a3[i][j]);
                }
        }
        if (t + 1 < ntiles) {
            int nxt = cur ^ 1;
#pragma unroll
            for (int e = 0; e < 2; e++) {
                Ar[nxt][la_k[e]][la_m[e]] = ra[e].x;
                Ai[nxt][la_k[e]][la_m[e]] = ra[e].y;
                Au[nxt][la_k[e]][la_m[e]] = ra[e].x + ra[e].y;
                Br[nxt][lb_k[e]][lb_n[e]] = rb[e].x;
                Bi[nxt][lb_k[e]][lb_n[e]] = rb[e].y;
                Bu[nxt][lb_k[e]][lb_n[e]] = rb[e].x + rb[e].y;
            }
        }
        __syncthreads();
    }

#pragma unroll
    for (int i = 0; i < 4; i++) {
        int gm = m0 + mt + i;
        if (gm >= M) continue;
#pragma unroll
        for (int j = 0; j < 4; j++) {
            int gn = n0 + nt + j;
            if (gn >= N) continue;
            float cr = a1[i][j] - a2[i][j];
            float ci = a3[i][j] - a1[i][j] - a2[i][j];
            C[(long long)gm * ldc + gn] = make_float2(cr, ci);
        }
    }
}

// ---------------------------------------------------------------------------
// Complex GEMM, double-buffered, Re-only output (2 FFMA per cmac; proven R4).
// ---------------------------------------------------------------------------
DINLINE float2 cmad(float2 acc, float2 a, float2 b)
{
    acc.x = fmaf(a.x, b.x, fmaf(-a.y, b.y, acc.x));
    acc.y = fmaf(a.x, b.y, fmaf(a.y, b.x, acc.y));
    return acc;
}

__global__ __launch_bounds__(256)
void k_cgemm_re(const float2* __restrict__ A, int lda, long long sA,
                const float2* __restrict__ B, int ldb, long long sB,
                float* __restrict__ C, int ldc, long long sC,
                int M, int N, int K)
{
    __shared__ float2 As[2][16][66];
    __shared__ float2 Bs[2][16][66];
    int b = blockIdx.z;
    A += (long long)b * sA;
    B += (long long)b * sB;
    int tid = threadIdx.x;
    int m0 = blockIdx.y * 64, n0 = blockIdx.x * 64;
    int mt = (tid & 15) * 4;
    int nt = (tid >> 4) * 4;
    int ra_r[4], ra_c[4], rb_r[4], rb_c[4];
#pragma unroll
    for (int e = 0; e < 4; e++) {
        int idx = tid + e * 256;
        ra_r[e] = idx >> 4; ra_c[e] = idx & 15;
        rb_r[e] = idx >> 6; rb_c[e] = idx & 63;
    }
    float2 ra[4], rb[4];
    int ntiles = (K + 15) / 16;

#pragma unroll
    for (int e = 0; e < 4; e++) {
        int gm = m0 + ra_r[e], gk = ra_c[e];
        ra[e] = (gm < M && gk < K) ? A[(long long)gm * lda + gk] : make_float2(0.f, 0.f);
        int gk2 = rb_r[e], gn = n0 + rb_c[e];
        rb[e] = (gk2 < K && gn < N) ? B[(long long)gk2 * ldb + gn] : make_float2(0.f, 0.f);
    }
#pragma unroll
    for (int e = 0; e < 4; e++) {
        As[0][ra_c[e]][ra_r[e]] = ra[e];
        Bs[0][rb_r[e]][rb_c[e]] = rb[e];
    }
    __syncthreads();

    float accr[4][4] = {};
    for (int t = 0; t < ntiles; t++) {
        int kt = (t + 1) * 16;
        if (t + 1 < ntiles) {
#pragma unroll
            for (int e = 0; e < 4; e++) {
                int gm = m0 + ra_r[e], gk = kt + ra_c[e];
                ra[e] = (gm < M && gk < K) ? A[(long long)gm * lda + gk] : make_float2(0.f, 0.f);
                int gk2 = kt + rb_r[e], gn = n0 + rb_c[e];
                rb[e] = (gk2 < K && gn < N) ? B[(long long)gk2 * ldb + gn] : make_float2(0.f, 0.f);
            }
        }
        int cur = t & 1;
#pragma unroll
        for (int k = 0; k < 16; k++) {
            float2 av[4], bv[4];
#pragma unroll
            for (int i = 0; i < 4; i++) av[i] = As[cur][k][mt + i];
#pragma unroll
            for (int j = 0; j < 4; j++) bv[j] = Bs[cur][k][nt + j];
#pragma unroll
            for (int i = 0; i < 4; i++)
#pragma unroll
                for (int j = 0; j < 4; j++)
                    accr[i][j] = fmaf(av[i].x, bv[j].x,
                                 fmaf(-av[i].y, bv[j].y, accr[i][j]));
        }
        if (t + 1 < ntiles) {
            int nxt = cur ^ 1;
#pragma unroll
            for (int e = 0; e < 4; e++) {
                As[nxt][ra_c[e]][ra_r[e]] = ra[e];
                Bs[nxt][rb_r[e]][rb_c[e]] = rb[e];
            }
        }
        __syncthreads();
    }

#pragma unroll
    for (int i = 0; i < 4; i++) {
        int gm = m0 + mt + i;
        if (gm >= M) continue;
#pragma unroll
        for (int j = 0; j < 4; j++) {
            int gn = n0 + nt + j;
            if (gn >= N) continue;
            C[(long long)b * sC + (long long)gm * ldc + gn] = accr[i][j];
        }
    }
}

// ---------------------------------------------------------------------------
// Real-input complex conv, 2 vertical pixels per thread
// ---------------------------------------------------------------------------
template<bool GUARD>
DINLINE void conv_r41_body2(const float* __restrict__ Xb, float2 acc[2][4],
                            const float2* __restrict__ ws, int p0, int q)
{
    float xv[4][3];
#pragma unroll
    for (int r = 0; r < 4; r++) {
        int ii = p0 - 1 + r;
#pragma unroll
        for (int c = 0; c < 3; c++) {
            int jj = q - 1 + c;
            if (GUARD)
                xv[r][c] = (ii >= 0 && ii < NG && jj >= 0 && jj < NG)
                         ? Xb[(long long)ii * NG + jj] : 0.f;
            else
                xv[r][c] = Xb[(long long)ii * NG + jj];
        }
    }
#pragma unroll
    for (int dy = 0; dy < 3; dy++)
#pragma unroll
        for (int dx = 0; dx < 3; dx++) {
            int tap = dy * 3 + dx;
#pragma unroll
            for (int o = 0; o < 4; o++) {
                float2 w = ws[o * 9 + tap];
                acc[0][o].x = fmaf(xv[dy][dx], w.x, acc[0][o].x);
                acc[0][o].y = fmaf(xv[dy][dx], w.y, acc[0][o].y);
                acc[1][o].x = fmaf(xv[dy + 1][dx], w.x, acc[1][o].x);
                acc[1][o].y = fmaf(xv[dy + 1][dx], w.y, acc[1][o].y);
            }
        }
}

__global__ __launch_bounds__(256)
void k_conv_r41(const float* __restrict__ X, float2* __restrict__ Y,
                const float* __restrict__ wr, const float* __restrict__ wi)
{
    int b = blockIdx.z;
    __shared__ float2 ws[36];
    int t = threadIdx.y * 16 + threadIdx.x;
    if (t < 36) ws[t] = make_float2(wr[b * 36 + t], wi[b * 36 + t]);
    __syncthreads();
    int q = blockIdx.x * 16 + threadIdx.x;
    int p0 = blockIdx.y * 32 + 2 * threadIdx.y;
    if (q >= NG || p0 >= NG) return;
    bool hasP1 = (p0 + 1 < NG);
    const float* Xb = X + (long long)b * NN;
    float2 acc[2][4];
#pragma unroll
    for (int r = 0; r < 2; r++)
#pragma unroll
        for (int o = 0; o < 4; o++) acc[r][o] = make_float2(0.f, 0.f);
    int pB = blockIdx.y * 32, qB = blockIdx.x * 16;
    bool interior = (pB >= 1) && (pB + 32 <= NG - 1) && (qB >= 1) && (qB + 16 <= NG - 1);
    if (interior) conv_r41_body2<false>(Xb, acc, ws, p0, q);
    else          conv_r41_body2<true >(Xb, acc, ws, p0, q);
    float2* Yb = Y + (long long)b * 4 * NN;
#pragma unroll
    for (int o = 0; o < 4; o++) {
        Yb[(long long)o * NN + (long long)p0 * NG + q] = acc[0][o];
        if (hasP1)
            Yb[(long long)o * NN + (long long)(p0 + 1) * NG + q] = acc[1][o];
    }
}

// ---------------------------------------------------------------------------
// Complex multi-channel 3x3 conv, 2 vertical pixels per thread.
// WTIK fuses wt*ik2 (CO==1 use only).
// ---------------------------------------------------------------------------
template<int CO, int CI, bool GUARD>
DINLINE void conv_body2(const float2* __restrict__ Xb, float2 acc[2][CO],
                        const float2* __restrict__ ws, int p0, int q)
{
#pragma unroll
    for (int i = 0; i < CI; i++) {
        float2 xv[4][3];
#pragma unroll
        for (int r = 0; r < 4; r++) {
            int ii = p0 - 1 + r;
#pragma unroll
            for (int c = 0; c < 3; c++) {
                int jj = q - 1 + c;
                if (GUARD)
                    xv[r][c] = (ii >= 0 && ii < NG && jj >= 0 && jj < NG)
                             ? Xb[(long long)i * NN + (long long)ii * NG + jj]
                             : make_float2(0.f, 0.f);
                else
                    xv[r][c] = Xb[(long long)i * NN + (long long)ii * NG + jj];
            }
        }
#pragma unroll
        for (int dy = 0; dy < 3; dy++)
#pragma unroll
            for (int dx = 0; dx < 3; dx++) {
                int tap = dy * 3 + dx;
#pragma unroll
                for (int o = 0; o < CO; o++) {
                    float2 w = ws[(o * CI + i) * 9 + tap];
                    acc[0][o] = cmad(acc[0][o], xv[dy][dx], w);
                    acc[1][o] = cmad(acc[1][o], xv[dy + 1][dx], w);
                }
            }
    }
}

template<int CO, int CI, bool WTIK>
__global__ __launch_bounds__(256)
void k_conv(const float2* __restrict__ X, float2* __restrict__ Y,
            const float* __restrict__ wr, const float* __restrict__ wi,
            int conjt, const float* __restrict__ wtr,
            const float* __restrict__ wti)
{
    int b = blockIdx.z;
    __shared__ float2 ws[CO * CI * 9];
    int t = threadIdx.y * 16 + threadIdx.x;
    if (t < CO * CI * 9) {
        int o = t / (CI * 9), rem = t % (CI * 9), i = rem / 9, tap = rem % 9;
        int dy = tap / 3, dx = tap % 3;
        long long widx;
        float sgn;
        if (conjt) { widx = ((long long)(b * CI + i) * CO + o) * 9 + dx * 3 + dy; sgn = -1.f; }
        else       { widx = ((long long)(b * CO + o) * CI + i) * 9 + dy * 3 + dx; sgn =  1.f; }
        ws[t] = make_float2(wr[widx], sgn * wi[widx]);
    }
    __syncthreads();
    int q = blockIdx.x * 16 + threadIdx.x;
    int p0 = blockIdx.y * 32 + 2 * threadIdx.y;
    if (q >= NG || p0 >= NG) return;
    bool hasP1 = (p0 + 1 < NG);
    const float2* Xb = X + (long long)b * CI * NN;
    float2 acc[2][CO];
#pragma unroll
    for (int r = 0; r < 2; r++)
#pragma unroll
        for (int o = 0; o < CO; o++) acc[r][o] = make_float2(0.f, 0.f);
    int pB = blockIdx.y * 32, qB = blockIdx.x * 16;
    bool interior = (pB >= 1) && (pB + 32 <= NG - 1) && (qB >= 1) && (qB + 16 <= NG - 1);
    if (interior) conv_body2<CO, CI, false>(Xb, acc, ws, p0, q);
    else          conv_body2<CO, CI, true >(Xb, acc, ws, p0, q);

    float2* Yb = Y + (long long)b * CO * NN;
    if (WTIK) {
        const float pi2 = 9.869604401089358f;
#pragma unroll
        for (int r = 0; r < 2; r++) {
            int p = p0 + r;
            if (r == 1 && !hasP1) break;
            long long po = (long long)p * NG + q;
            long long o = (long long)b * NN + po;
            float wrv = wtr[o], wiv = wti[o];
            float dp = (float)(p - 256), dq = (float)(q - 256);
            float s = dp * dp + dq * dq;
            float ik = (s == 0.f) ? 1.f : 1.f / (pi2 * s);
            float2 c = acc[r][0];
            float2 rr;
            rr.x = (c.x * wrv - c.y * wiv) * ik;
            rr.y = (c.x * wiv + c.y * wrv) * ik;
            Yb[po] = rr;
        }
    } else {
#pragma unroll
        for (int o = 0; o < CO; o++) {
            Yb[(long long)o * NN + (long long)p0 * NG + q] = acc[0][o];
            if (hasP1)
                Yb[(long long)o * NN + (long long)(p0 + 1) * NG + q] = acc[1][o];
        }
    }
}

// ---------------------------------------------------------------------------
// Reductions (deterministic, double accumulation)
// ---------------------------------------------------------------------------
__global__ __launch_bounds__(256)
void k_alpha_part(const float* __restrict__ r, const float* __restrict__ e,
                  const float* __restrict__ a, double* __restrict__ p1,
                  double* __restrict__ p2)
{
    int b = blockIdx.y;
    const float* rb = r + (long long)b * NN;
    const float* eb = e + (long long)b * NN;
    const float* ab = a + (long long)b * NCC;
    double num = 0.0, den = 0.0;
    for (long long idx = (long long)blockIdx.x * 256 + threadIdx.x; idx < NN;
         idx += (long long)gridDim.x * 256) {
        int i = (int)(idx / NG), j = (int)(idx - (long long)i * NG);
        float ev = eb[idx];
        num += (double)(rb[idx] * ev);
        if (i > 0 && j > 0 && i < NG - 1 && j < NG - 1) {
            float d = darcy_at(eb, ab, i, j);
            den += (double)(d * ev);
        }
    }
    __shared__ double s1[256], s2[256];
    int t = threadIdx.x;
    s1[t] = num; s2[t] = den;
    __syncthreads();
    for (int s = 128; s > 0; s >>= 1) {
        if (t < s) { s1[t] += s1[t + s]; s2[t] += s2[t + s]; }
        __syncthreads();
    }
    if (t == 0) { p1[b * NBLK_A + blockIdx.x] = s1[0]; p2[b * NBLK_A + blockIdx.x] = s2[0]; }
}

__global__ void k_alpha_fin(const double* __restrict__ p1,
                            const double* __restrict__ p2,
                            float* __restrict__ alpha)
{
    int b = blockIdx.x;
    __shared__ double s1[256], s2[256];
    double n = 0.0, d = 0.0;
    for (int i = threadIdx.x; i < NBLK_A; i += 256) {
        n += p1[b * NBLK_A + i]; d += p2[b * NBLK_A + i];
    }
    int t = threadIdx.x;
    s1[t] = n; s2[t] = d;
    __syncthreads();
    for (int s = 128; s > 0; s >>= 1) {
        if (t < s) { s1[t] += s1[t + s]; s2[t] += s2[t + s]; }
        __syncthreads();
    }
    if (t == 0) alpha[b] = (float)(s1[0] / s2[0]);
}

__global__ void k_update(float* __restrict__ x, const float* __restrict__ e,
                         const float* __restrict__ alpha)
{
    int b = blockIdx.z;
    int j = blockIdx.x * 16 + threadIdx.x + 1;
    int i = blockIdx.y * 16 + threadIdx.y + 1;
    if (i > NI || j > NI) return;
    long long o = (long long)b * NN + (long long)i * NG + j;
    x[o] = fmaf(alpha[b], e[o], x[o]);
}

__global__ __launch_bounds__(256)
void k_norm_part(const float* __restrict__ r, const float* __restrict__ f,
                 double* __restrict__ p1, double* __restrict__ p2)
{
    double sr = 0.0, sf = 0.0;
    long long tot = (long long)NB * NN;
    for (long long idx = (long long)blockIdx.x * 256 + threadIdx.x; idx < tot;
         idx += (long long)gridDim.x * 256) {
        float rv = r[idx], fv = f[idx];
        sr += (double)rv * rv;
        sf += (double)fv * fv;
    }
    __shared__ double s1[256], s2[256];
    int t = threadIdx.x;
    s1[t] = sr; s2[t] = sf;
    __syncthreads();
    for (int s = 128; s > 0; s >>= 1) {
        if (t < s) { s1[t] += s1[t + s]; s2[t] += s2[t + s]; }
        __syncthreads();
    }
    if (t == 0) { p1[blockIdx.x] = s1[0]; p2[blockIdx.x] = s2[0]; }
}

__global__ void k_norm_fin(const double* __restrict__ p1,
                           const double* __restrict__ p2,
                           float* __restrict__ out)
{
    __shared__ double s1[256], s2[256];
    double a = 0.0, b = 0.0;
    for (int i = threadIdx.x; i < NBLK_N; i += 256) { a += p1[i]; b += p2[i]; }
    int t = threadIdx.x;
    s1[t] = a; s2[t] = b;
    __syncthreads();
    for (int s = 128; s > 0; s >>= 1) {
        if (t < s) { s1[t] += s1[t + s]; s2[t] += s2[t + s]; }
        __syncthreads();
    }
    if (t == 0) out[0] = (float)sqrt(s1[0] / s2[0]);
}

// ---------------------------------------------------------------------------
// Host orchestration
// ---------------------------------------------------------------------------
template<typename T>
static T* sym_addr(const void* sym)
{
    void* p = nullptr;
    cudaGetSymbolAddress(&p, sym);
    return (T*)p;
}

extern "C" void kernel_launch(void* const* d_in, const int* in_sizes, int n_in,
                              void* d_out, int out_size)
{
    const float* f    = (const float*)d_in[0];
    const float* coef = (const float*)d_in[1];
    const float* w1r = (const float*)d_in[3];
    const float* w1i = (const float*)d_in[4];
    const float* w2r = (const float*)d_in[5];
    const float* w2i = (const float*)d_in[6];
    const float* w3r = (const float*)d_in[7];
    const float* w3i = (const float*)d_in[8];
    const float* wtr = (const float*)d_in[9];
    const float* wti = (const float*)d_in[10];

    float*  x    = sym_addr<float>(g_x);
    float*  x2   = sym_addr<float>(g_x2);
    float*  r    = sym_addr<float>(g_r);
    float*  e    = sym_addr<float>(g_e);
    float*  rh   = sym_addr<float>(g_rh);
    float*  dinv = sym_addr<float>(g_dinv);
    float*  S    = sym_addr<float>(g_S);
    float*  St   = sym_addr<float>(g_St);
    float2* G    = sym_addr<float2>(g_G);
    float2* Gt   = sym_addr<float2>(g_Gt);
    float*  U    = sym_addr<float>(g_U);
    float2* cA   = sym_addr<float2>(g_cA);
    float2* cB   = sym_addr<float2>(g_cB);
    float2* cC   = sym_addr<float2>(g_cC);
    float2* W    = sym_addr<float2>(g_W);
    double* pd1  = sym_addr<double>(g_pd1);
    double* pd2  = sym_addr<double>(g_pd2);
    float*  alph = sym_addr<float>(g_alpha);

    dim3 blk2(16, 16);
    dim3 gInt((NI + 15) / 16, (NI + 15) / 16, NB);
    dim3 gFull((NG + 15) / 16, (NG + 15) / 16, NB);
    dim3 gJac(16, 16, NB);
    dim3 gConv((NG + 15) / 16, (NG + 31) / 32, NB);   // 2 rows per thread

    // ---- setup ----
    {
        long long tot = (long long)NB * NN;
        k_zero3<<<(int)((tot + 255) / 256), 256>>>(x, x2, e);
        int nSG = NG * NI;
        k_precS<<<(nSG + 255) / 256, 256>>>(S, St);
        k_precG<<<(nSG + 255) / 256, 256>>>(G, Gt);
        k_dinv<<<gInt, blk2>>>(coef, dinv);
    }

    float* xa = x;
    float* xb = x2;

    for (int step = 0; step < KSTEPS; step++) {
        // ---- 10 Jacobi sweeps ----
        for (int it = 0; it < 10; it++) {
            k_jacobi2<<<gJac, blk2>>>(xa, xb, f, coef, dinv);
            float* tmp = xa; xa = xb; xb = tmp;
        }
        // ---- residual ----
        k_resid<<<gFull, blk2>>>(xa, f, coef, r);

        // ---- forward sine transform (odd symmetry fused in epilogue) ----
        {
            dim3 g((257 + 63) / 64, (NI + 63) / 64, NB);
            k_sgemm<1><<<g, 256>>>(r + NG + 1, NG, NN,
                                   St + 256, NG, 0,
                                   U, NG, NIG,
                                   NI, 257, NI, 1.f);
        }
        {
            dim3 g((NG + 63) / 64, (257 + 63) / 64, NB);
            k_sgemm<2><<<g, 256>>>(S + 256 * NI, NI, 0,
                                   U, NG, NIG,
                                   rh, NG, NN,
                                   257, NG, NI, -1.f / (512.f * 512.f));
        }

        // ---- 3 complex convs forward ----
        k_conv_r41<<<gConv, blk2>>>(rh, cA, w1r, w1i);
        k_conv<4, 4, false><<<gConv, blk2>>>(cA, cB, w2r, w2i, 0, nullptr, nullptr);
        k_conv<1, 4, true ><<<gConv, blk2>>>(cB, cC, w3r, w3i, 0, wtr, wti);

        // ---- 3 complex convs backward (conjT) ----
        k_conv<4, 1, false><<<gConv, blk2>>>(cC, cA, w3r, w3i, 1, nullptr, nullptr);
        k_conv<4, 4, false><<<gConv, blk2>>>(cA, cB, w2r, w2i, 1, nullptr, nullptr);
        k_conv<1, 4, false><<<gConv, blk2>>>(cB, cC, w1r, w1i, 1, nullptr, nullptr);

        // ---- inverse transform: W = cC * Gt (Karatsuba), e_int = Re(G * W) ----
        {
            dim3 g((NI + 63) / 64, (NG + 63) / 64, NB);
            k_cgemm_kar<<<g, 256>>>(cC, NG, NN,
                                    Gt, NI, 0,
                                    W, NI, NIG,
                                    NG, NI, NG);
        }
        {
            dim3 g((NI + 63) / 64, (NI + 63) / 64, NB);
            k_cgemm_re<<<g, 256>>>(G, NG, 0,
                                   W, NI, NIG,
                                   e + NG + 1, NG, NN,
                                   NI, NI, NG);
        }

        // ---- alpha and update ----
        {
            dim3 g(NBLK_A, NB);
            k_alpha_part<<<g, 256>>>(r, e, coef, pd1, pd2);
            k_alpha_fin<<<NB, 256>>>(pd1, pd2, alph);
            k_update<<<gInt, blk2>>>(xa, e, alph);
        }
    }

    // ---- final relative residual norm ----
    k_resid<<<gFull, blk2>>>(xa, f, coef, r);
    k_norm_part<<<NBLK_N, 256>>>(r, f, pd1, pd2);
    k_norm_fin<<<1, 256>>>(pd1, pd2, (float*)d_out);
}

// round 7
// speedup vs baseline: 1.7399x; 1.0544x over previous
#include <cuda_runtime.h>
#include <math.h>

#define DINLINE __device__ __forceinline__

// ---------------------------------------------------------------------------
// Fixed problem dimensions (B=4, grid 513, coef 512, epoch=101 -> K=2)
// ---------------------------------------------------------------------------
namespace fns {
constexpr int NB = 4;
constexpr int NG = 513;
constexpr int NI = 511;
constexpr int NC = 512;
constexpr long long NN  = (long long)NG * NG;
constexpr long long NCC = (long long)NC * NC;
constexpr long long NII = (long long)NI * NI;
constexpr long long NIG = (long long)NI * NG;
constexpr int NBLK_A = 128;
constexpr int NBLK_N = 256;
constexpr int KSTEPS = 2;
}
using namespace fns;

// ---------------------------------------------------------------------------
// Static device scratch
// ---------------------------------------------------------------------------
__device__ float  g_x   [NB * NN];
__device__ float  g_x2  [NB * NN];
__device__ float  g_r   [NB * NN];
__device__ float  g_e   [NB * NN];
__device__ float  g_rh  [NB * NN];
__device__ float  g_dinv[NB * NII];
__device__ float  g_S   [NG * (long long)NI];  // S[p][j], ld=NI
__device__ float  g_St  [NIG];                 // St[j][p], ld=NG
__device__ float2 g_G   [NIG];                 // G[s][u],  ld=NG
__device__ float2 g_Gt  [NIG];                 // Gt[u][s], ld=NI
__device__ float  g_U   [NB * NIG];            // 511 x 513, ld=NG
__device__ float2 g_cA  [NB * 4 * NN];         // strip scratch stage-1
__device__ float2 g_cB  [NB * 4 * NN];         // strip scratch stage-2
__device__ float2 g_cC  [NB * NN];             // spectral signal
__device__ float2 g_cD  [NB * NN];             // backward-conv output
__device__ float2 g_W   [NB * NIG];            // 513x511, ld=NI
__device__ float2 g_wf  [NB * 49];             // composed 7x7 forward taps
__device__ double g_pd1 [2048];
__device__ double g_pd2 [2048];
__device__ float  g_alpha[NB];

// ---------------------------------------------------------------------------
// Darcy FEM 9-point stencil (pointer form, used by resid / alpha)
// ---------------------------------------------------------------------------
DINLINE float darcy_at(const float* __restrict__ x,
                       const float* __restrict__ a, int i, int j)
{
    const float c23 = 2.f / 3.f, c16 = -1.f / 6.f, c13 = -1.f / 3.f;
    float s = 0.f;
#pragma unroll
    for (int u = 0; u < 2; u++) {
#pragma unroll
        for (int v = 0; v < 2; v++) {
            int I = i - 1 + u, J = j - 1 + v;
            float av = a[(long long)I * NC + J];
            float k0, k1, k2, k3;
            if (u == 0 && v == 0) { k0 = c16; k1 = c23; k2 = c16; k3 = c13; }
            else if (u == 0 && v == 1) { k0 = c23; k1 = c16; k2 = c13; k3 = c16; }
            else if (u == 1 && v == 0) { k0 = c13; k1 = c16; k2 = c23; k3 = c16; }
            else                        { k0 = c16; k1 = c13; k2 = c16; k3 = c23; }
            s += av * (k3 * x[(long long)I * NG + J]
                     + k2 * x[(long long)I * NG + J + 1]
                     + k0 * x[(long long)(I + 1) * NG + J]
                     + k1 * x[(long long)(I + 1) * NG + J + 1]);
        }
    }
    return s;
}

DINLINE float2 cmad(float2 acc, float2 a, float2 b)
{
    acc.x = fmaf(a.x, b.x, fmaf(-a.y, b.y, acc.x));
    acc.y = fmaf(a.x, b.y, fmaf(a.y, b.x, acc.y));
    return acc;
}

// ---------------------------------------------------------------------------
// Setup kernels
// ---------------------------------------------------------------------------
__global__ void k_precS(float* __restrict__ S, float* __restrict__ St)
{
    int idx = blockIdx.x * blockDim.x + threadIdx.x;
    if (idx >= NG * NI) return;
    int p = idx / NI, j = idx - p * NI;
    int m = (j + 1) * (p - 256);
    int mm = ((m % 1024) + 1024) % 1024;
    float v = sinpif((float)mm / 512.f);
    S[idx] = v;
    St[(long long)j * NG + p] = v;
}

__global__ void k_precG(float2* __restrict__ G, float2* __restrict__ Gt)
{
    int idx = blockIdx.x * blockDim.x + threadIdx.x;
    if (idx >= NI * NG) return;
    int s = idx / NG, u = idx - s * NG;
    int t = (u - 255) * s;
    int tm = ((t % 1025) + 1025) % 1025;
    float xr = 2.f * (float)tm / 1025.f;
    float2 g = make_float2(cospif(xr), -sinpif(xr));
    G[idx] = g;
    Gt[(long long)u * NI + s] = g;
}

__global__ void k_dinv(const float* __restrict__ a, float* __restrict__ dinv)
{
    int b = blockIdx.z;
    int q = blockIdx.x * 16 + threadIdx.x;
    int p = blockIdx.y * 16 + threadIdx.y;
    if (p >= NI || q >= NI) return;
    const float* ap = a + (long long)b * NCC;
    float s = ap[(long long)p * NC + q] + ap[(long long)p * NC + q + 1]
            + ap[(long long)(p + 1) * NC + q] + ap[(long long)(p + 1) * NC + q + 1];
    dinv[(long long)b * NII + (long long)p * NI + q] = 1.f / ((2.f / 3.f) * s);
}

__global__ void k_zero3(float* __restrict__ x, float* __restrict__ x2,
                        float* __restrict__ e)
{
    long long idx = (long long)blockIdx.x * blockDim.x + threadIdx.x;
    long long tot = (long long)NB * NN;
    if (idx >= tot) return;
    x[idx] = 0.f; x2[idx] = 0.f; e[idx] = 0.f;
}

// ---------------------------------------------------------------------------
// Compose the 3-stage complex conv chain into one 7x7 tap set:
// wf[dy][dx] = sum_{c,o} sum_{a+b+cc=(dy,dx)} w1[c][a] w2[o][c][b] w3[o][cc]
// (plain tap-array convolution; backward taps are conj(wf^T))
// ---------------------------------------------------------------------------
__global__ void k_compose(const float* __restrict__ w1r, const float* __restrict__ w1i,
                          const float* __restrict__ w2r, const float* __restrict__ w2i,
                          const float* __restrict__ w3r, const float* __restrict__ w3i,
                          float2* __restrict__ wf)
{
    int b = blockIdx.x;
    int t = threadIdx.x;
    if (t >= 49) return;
    int dy = t / 7, dx = t % 7;
    float accr = 0.f, acci = 0.f;
    for (int c = 0; c < 4; c++) {
        for (int o = 0; o < 4; o++) {
            for (int a = 0; a < 9; a++) {
                int ay = a / 3, ax = a % 3;
                float r1 = w1r[(b * 4 + c) * 9 + a];
                float i1 = w1i[(b * 4 + c) * 9 + a];
                for (int bt = 0; bt < 9; bt++) {
                    int by = bt / 3, bx = bt % 3;
                    int cy = dy - ay - by, cx = dx - ax - bx;
                    if (cy < 0 || cy > 2 || cx < 0 || cx > 2) continue;
                    float r2 = w2r[((b * 4 + o) * 4 + c) * 9 + bt];
                    float i2 = w2i[((b * 4 + o) * 4 + c) * 9 + bt];
                    float r3 = w3r[(b * 4 + o) * 9 + cy * 3 + cx];
                    float i3 = w3i[(b * 4 + o) * 9 + cy * 3 + cx];
                    float tr = r1 * r2 - i1 * i2;
                    float ti = r1 * i2 + i1 * r2;
                    accr += tr * r3 - ti * i3;
                    acci += tr * i3 + ti * r3;
                }
            }
        }
    }
    wf[b * 49 + t] = make_float2(accr, acci);
}

// ---------------------------------------------------------------------------
// Jacobi sweep: 2x2 nodes per thread (proven R4)
// ---------------------------------------------------------------------------
__global__ __launch_bounds__(256)
void k_jacobi2(const float* __restrict__ xin, float* __restrict__ xout,
               const float* __restrict__ f, const float* __restrict__ a,
               const float* __restrict__ dinv)
{
    int b = blockIdx.z;
    int tj = blockIdx.x * 16 + threadIdx.x;
    int ti = blockIdx.y * 16 + threadIdx.y;
    int i0 = 2 * ti + 1, j0 = 2 * tj + 1;
    if (i0 > NI || j0 > NI) return;
    const float* xp = xin + (long long)b * NN;
    const float* ap = a + (long long)b * NCC;
    const float* fp = f + (long long)b * NN;
    const float* dp = dinv + (long long)b * NII;
    float* xo = xout + (long long)b * NN;

    float xx[4][4];
#pragma unroll
    for (int di = 0; di < 4; di++) {
        int ii = i0 - 1 + di;
        bool vi = (ii <= NG - 1);
#pragma unroll
        for (int dj = 0; dj < 4; dj++) {
            int jj = j0 - 1 + dj;
            xx[di][dj] = (vi && jj <= NG - 1) ? xp[(long long)ii * NG + jj] : 0.f;
        }
    }
    float ax[3][3];
#pragma unroll
    for (int di = 0; di < 3; di++) {
        int II = i0 - 1 + di;
        bool vi = (II <= NC - 1);
#pragma unroll
        for (int dj = 0; dj < 3; dj++) {
            int JJ = j0 - 1 + dj;
            ax[di][dj] = (vi && JJ <= NC - 1) ? ap[(long long)II * NC + JJ] : 0.f;
        }
    }

    const float c23 = 2.f / 3.f, c16 = -1.f / 6.f, c13 = -1.f / 3.f;
#pragma unroll
    for (int u = 0; u < 2; u++) {
#pragma unroll
        for (int v = 0; v < 2; v++) {
            int i = i0 + u, j = j0 + v;
            if (i > NI || j > NI) continue;
            float s = 0.f;
#pragma unroll
            for (int uu = 0; uu < 2; uu++) {
#pragma unroll
                for (int vv = 0; vv < 2; vv++) {
                    float av = ax[u + uu][v + vv];
                    float k0, k1, k2, k3;
                    if (uu == 0 && vv == 0) { k0 = c16; k1 = c23; k2 = c16; k3 = c13; }
                    else if (uu == 0 && vv == 1) { k0 = c23; k1 = c16; k2 = c13; k3 = c16; }
                    else if (uu == 1 && vv == 0) { k0 = c13; k1 = c16; k2 = c23; k3 = c16; }
                    else                          { k0 = c16; k1 = c13; k2 = c16; k3 = c23; }
                    s += av * (k3 * xx[u + uu][v + vv]
                             + k2 * xx[u + uu][v + vv + 1]
                             + k0 * xx[u + uu + 1][v + vv]
                             + k1 * xx[u + uu + 1][v + vv + 1]);
                }
            }
            long long o = (long long)i * NG + j;
            float r = fp[o] - s;
            xo[o] = xx[1 + u][1 + v]
                  + 0.75f * dp[(long long)(i - 1) * NI + (j - 1)] * r;
        }
    }
}

__global__ __launch_bounds__(256)
void k_resid(const float* __restrict__ x, const float* __restrict__ f,
             const float* __restrict__ a, float* __restrict__ r)
{
    int b = blockIdx.z;
    int j = blockIdx.x * 16 + threadIdx.x;
    int i = blockIdx.y * 16 + threadIdx.y;
    if (i >= NG || j >= NG) return;
    long long o = (long long)b * NN + (long long)i * NG + j;
    float d = 0.f;
    if (i > 0 && j > 0 && i < NG - 1 && j < NG - 1)
        d = darcy_at(x + (long long)b * NN, a + (long long)b * NCC, i, j);
    r[o] = f[o] - d;
}

// ---------------------------------------------------------------------------
// Real SGEMM, double-buffered, 64x64/BK16, mirror epilogues (proven R4).
// ---------------------------------------------------------------------------
template<int MIR>
__global__ __launch_bounds__(256)
void k_sgemm(const float* __restrict__ A, int lda, long long sA,
             const float* __restrict__ B, int ldb, long long sB,
             float* __restrict__ C, int ldc, long long sC,
             int M, int N, int K, float alpha)
{
    __shared__ float As[2][16][68];
    __shared__ float Bs[2][16][68];
    int b = blockIdx.z;
    A += (long long)b * sA;
    B += (long long)b * sB;
    C += (long long)b * sC;
    int tid = threadIdx.x;
    int m0 = blockIdx.y * 64, n0 = blockIdx.x * 64;
    int mt = (tid & 15) * 4;
    int nt = (tid >> 4) * 4;
    int ra_r[4], ra_c[4], rb_r[4], rb_c[4];
#pragma unroll
    for (int e = 0; e < 4; e++) {
        int idx = tid + e * 256;
        ra_r[e] = idx >> 4; ra_c[e] = idx & 15;
        rb_r[e] = idx >> 6; rb_c[e] = idx & 63;
    }
    float ra[4], rb[4];
    int ntiles = (K + 15) / 16;

#pragma unroll
    for (int e = 0; e < 4; e++) {
        int gm = m0 + ra_r[e], gk = ra_c[e];
        ra[e] = (gm < M && gk < K) ? A[(long long)gm * lda + gk] : 0.f;
        int gk2 = rb_r[e], gn = n0 + rb_c[e];
        rb[e] = (gk2 < K && gn < N) ? B[(long long)gk2 * ldb + gn] : 0.f;
    }
#pragma unroll
    for (int e = 0; e < 4; e++) {
        As[0][ra_c[e]][ra_r[e]] = ra[e];
        Bs[0][rb_r[e]][rb_c[e]] = rb[e];
    }
    __syncthreads();

    float acc[4][4] = {};
    for (int t = 0; t < ntiles; t++) {
        int kt = (t + 1) * 16;
        if (t + 1 < ntiles) {
#pragma unroll
            for (int e = 0; e < 4; e++) {
                int gm = m0 + ra_r[e], gk = kt + ra_c[e];
                ra[e] = (gm < M && gk < K) ? A[(long long)gm * lda + gk] : 0.f;
                int gk2 = kt + rb_r[e], gn = n0 + rb_c[e];
                rb[e] = (gk2 < K && gn < N) ? B[(long long)gk2 * ldb + gn] : 0.f;
            }
        }
        int cur = t & 1;
#pragma unroll
        for (int k = 0; k < 16; k++) {
            float av[4], bv[4];
#pragma unroll
            for (int i = 0; i < 4; i++) av[i] = As[cur][k][mt + i];
#pragma unroll
            for (int j = 0; j < 4; j++) bv[j] = Bs[cur][k][nt + j];
#pragma unroll
            for (int i = 0; i < 4; i++)
#pragma unroll
                for (int j = 0; j < 4; j++)
                    acc[i][j] = fmaf(av[i], bv[j], acc[i][j]);
        }
        if (t + 1 < ntiles) {
            int nxt = cur ^ 1;
#pragma unroll
            for (int e = 0; e < 4; e++) {
                As[nxt][ra_c[e]][ra_r[e]] = ra[e];
                Bs[nxt][rb_r[e]][rb_c[e]] = rb[e];
            }
        }
        __syncthreads();
    }

#pragma unroll
    for (int i = 0; i < 4; i++) {
        int gm = m0 + mt + i;
        if (gm >= M) continue;
#pragma unroll
        for (int j = 0; j < 4; j++) {
            int gn = n0 + nt + j;
            if (gn >= N) continue;
            float v = alpha * acc[i][j];
            if (MIR == 0) {
                C[(long long)gm * ldc + gn] = v;
            } else if (MIR == 1) {
                C[(long long)gm * ldc + 256 + gn] = v;
                if (gn > 0) C[(long long)gm * ldc + 256 - gn] = -v;
            } else {
                C[(long long)(256 + gm) * ldc + gn] = v;
                if (gm > 0) C[(long long)(256 - gm) * ldc + gn] = -v;
            }
        }
    }
}

// ---------------------------------------------------------------------------
// Karatsuba complex GEMM (proven R5): 3 real FFMA per complex MAC, BK=8.
// ---------------------------------------------------------------------------
__global__ __launch_bounds__(256)
void k_cgemm_kar(const float2* __restrict__ A, int lda, long long sA,
                 const float2* __restrict__ B, int ldb, long long sB,
                 float2* __restrict__ C, int ldc, long long sC,
                 int M, int N, int K)
{
    __shared__ __align__(16) float Ar[2][8][68], Ai[2][8][68], Au[2][8][68];
    __shared__ __align__(16) float Br[2][8][68], Bi[2][8][68], Bu[2][8][68];
    int b = blockIdx.z;
    A += (long long)b * sA;
    B += (long long)b * sB;
    C += (long long)b * sC;
    int tid = threadIdx.x;
    int m0 = blockIdx.y * 64, n0 = blockIdx.x * 64;
    int mt = (tid & 15) * 4;
    int nt = (tid >> 4) * 4;
    int la_m[2], la_k[2], lb_k[2], lb_n[2];
#pragma unroll
    for (int e = 0; e < 2; e++) {
        int idx = tid + e * 256;
        la_m[e] = idx >> 3; la_k[e] = idx & 7;
        lb_k[e] = idx >> 6; lb_n[e] = idx & 63;
    }
    float2 ra[2], rb[2];
    int ntiles = (K + 7) / 8;

#pragma unroll
    for (int e = 0; e < 2; e++) {
        int gm = m0 + la_m[e], gk = la_k[e];
        ra[e] = (gm < M && gk < K) ? A[(long long)gm * lda + gk] : make_float2(0.f, 0.f);
        int gk2 = lb_k[e], gn = n0 + lb_n[e];
        rb[e] = (gk2 < K && gn < N) ? B[(long long)gk2 * ldb + gn] : make_float2(0.f, 0.f);
    }
#pragma unroll
    for (int e = 0; e < 2; e++) {
        Ar[0][la_k[e]][la_m[e]] = ra[e].x;
        Ai[0][la_k[e]][la_m[e]] = ra[e].y;
        Au[0][la_k[e]][la_m[e]] = ra[e].x + ra[e].y;
        Br[0][lb_k[e]][lb_n[e]] = rb[e].x;
        Bi[0][lb_k[e]][lb_n[e]] = rb[e].y;
        Bu[0][lb_k[e]][lb_n[e]] = rb[e].x + rb[e].y;
    }
    __syncthreads();

    float a1[4][4] = {}, a2[4][4] = {}, a3[4][4] = {};
    for (int t = 0; t < ntiles; t++) {
        int kt = (t + 1) * 8;
        if (t + 1 < ntiles) {
#pragma unroll
            for (int e = 0; e < 2; e++) {
                int gm = m0 + la_m[e], gk = kt + la_k[e];
                ra[e] = (gm < M && gk < K) ? A[(long long)gm * lda + gk] : make_float2(0.f, 0.f);
                int gk2 = kt + lb_k[e], gn = n0 + lb_n[e];
                rb[e] = (gk2 < K && gn < N) ? B[(long long)gk2 * ldb + gn] : make_float2(0.f, 0.f);
            }
        }
        int cur = t & 1;
#pragma unroll
        for (int k = 0; k < 8; k++) {
            float arv[4], aiv[4], auv[4], brv[4], biv[4], buv[4];
            *(float4*)arv = *(const float4*)&Ar[cur][k][mt];
            *(float4*)aiv = *(const float4*)&Ai[cur][k][mt];
            *(float4*)auv = *(const float4*)&Au[cur][k][mt];
            *(float4*)brv = *(const float4*)&Br[cur][k][nt];
            *(float4*)biv = *(const float4*)&Bi[cur][k][nt];
            *(float4*)buv = *(const float4*)&Bu[cur][k][nt];
#pragma unroll
            for (int i = 0; i < 4; i++)
#pragma unroll
                for (int j = 0; j < 4; j++) {
                    a1[i][j] = fmaf(arv[i], brv[j], a1[i][j]);
                    a2[i][j] = fmaf(aiv[i], biv[j], a2[i][j]);
                    a3[i][j] = fmaf(auv[i], buv[j], a3[i][j]);
                }
        }
        if (t + 1 < ntiles) {
            int nxt = cur ^ 1;
#pragma unroll
            for (int e = 0; e < 2; e++) {
                Ar[nxt][la_k[e]][la_m[e]] = ra[e].x;
                Ai[nxt][la_k[e]][la_m[e]] = ra[e].y;
                Au[nxt][la_k[e]][la_m[e]] = ra[e].x + ra[e].y;
                Br[nxt][lb_k[e]][lb_n[e]] = rb[e].x;
                Bi[nxt][lb_k[e]][lb_n[e]] = rb[e].y;
                Bu[nxt][lb_k[e]][lb_n[e]] = rb[e].x + rb[e].y;
            }
        }
        __syncthreads();
    }

#pragma unroll
    for (int i = 0; i < 4; i++) {
        int gm = m0 + mt + i;
        if (gm >= M) continue;
#pragma unroll
        for (int j = 0; j < 4; j++) {
            int gn = n0 + nt + j;
            if (gn >= N) continue;
            float cr = a1[i][j] - a2[i][j];
            float ci = a3[i][j] - a1[i][j] - a2[i][j];
            C[(long long)gm * ldc + gn] = make_float2(cr, ci);
        }
    }
}

// ---------------------------------------------------------------------------
// Complex GEMM, double-buffered, Re-only output (proven R4).
// ---------------------------------------------------------------------------
__global__ __launch_bounds__(256)
void k_cgemm_re(const float2* __restrict__ A, int lda, long long sA,
                const float2* __restrict__ B, int ldb, long long sB,
                float* __restrict__ C, int ldc, long long sC,
                int M, int N, int K)
{
    __shared__ float2 As[2][16][66];
    __shared__ float2 Bs[2][16][66];
    int b = blockIdx.z;
    A += (long long)b * sA;
    B += (long long)b * sB;
    int tid = threadIdx.x;
    int m0 = blockIdx.y * 64, n0 = blockIdx.x * 64;
    int mt = (tid & 15) * 4;
    int nt = (tid >> 4) * 4;
    int ra_r[4], ra_c[4], rb_r[4], rb_c[4];
#pragma unroll
    for (int e = 0; e < 4; e++) {
        int idx = tid + e * 256;
        ra_r[e] = idx >> 4; ra_c[e] = idx & 15;
        rb_r[e] = idx >> 6; rb_c[e] = idx & 63;
    }
    float2 ra[4], rb[4];
    int ntiles = (K + 15) / 16;

#pragma unroll
    for (int e = 0; e < 4; e++) {
        int gm = m0 + ra_r[e], gk = ra_c[e];
        ra[e] = (gm < M && gk < K) ? A[(long long)gm * lda + gk] : make_float2(0.f, 0.f);
        int gk2 = rb_r[e], gn = n0 + rb_c[e];
        rb[e] = (gk2 < K && gn < N) ? B[(long long)gk2 * ldb + gn] : make_float2(0.f, 0.f);
    }
#pragma unroll
    for (int e = 0; e < 4; e++) {
        As[0][ra_c[e]][ra_r[e]] = ra[e];
        Bs[0][rb_r[e]][rb_c[e]] = rb[e];
    }
    __syncthreads();

    float accr[4][4] = {};
    for (int t = 0; t < ntiles; t++) {
        int kt = (t + 1) * 16;
        if (t + 1 < ntiles) {
#pragma unroll
            for (int e = 0; e < 4; e++) {
                int gm = m0 + ra_r[e], gk = kt + ra_c[e];
                ra[e] = (gm < M && gk < K) ? A[(long long)gm * lda + gk] : make_float2(0.f, 0.f);
                int gk2 = kt + rb_r[e], gn = n0 + rb_c[e];
                rb[e] = (gk2 < K && gn < N) ? B[(long long)gk2 * ldb + gn] : make_float2(0.f, 0.f);
            }
        }
        int cur = t & 1;
#pragma unroll
        for (int k = 0; k < 16; k++) {
            float2 av[4], bv[4];
#pragma unroll
            for (int i = 0; i < 4; i++) av[i] = As[cur][k][mt + i];
#pragma unroll
            for (int j = 0; j < 4; j++) bv[j] = Bs[cur][k][nt + j];
#pragma unroll
            for (int i = 0; i < 4; i++)
#pragma unroll
                for (int j = 0; j < 4; j++)
                    accr[i][j] = fmaf(av[i].x, bv[j].x,
                                 fmaf(-av[i].y, bv[j].y, accr[i][j]));
        }
        if (t + 1 < ntiles) {
            int nxt = cur ^ 1;
#pragma unroll
            for (int e = 0; e < 4; e++) {
                As[nxt][ra_c[e]][ra_r[e]] = ra[e];
                Bs[nxt][rb_r[e]][rb_c[e]] = rb[e];
            }
        }
        __syncthreads();
    }

#pragma unroll
    for (int i = 0; i < 4; i++) {
        int gm = m0 + mt + i;
        if (gm >= M) continue;
#pragma unroll
        for (int j = 0; j < 4; j++) {
            int gn = n0 + nt + j;
            if (gn >= N) continue;
            C[(long long)b * sC + (long long)gm * ldc + gn] = accr[i][j];
        }
    }
}

// ---------------------------------------------------------------------------
// wt*ik2 helper
// ---------------------------------------------------------------------------
DINLINE float2 wtik_apply(float2 c, float wrv, float wiv, int p, int q)
{
    float dp = (float)(p - 256), dq = (float)(q - 256);
    float s = dp * dp + dq * dq;
    const float pi2 = 9.869604401089358f;
    float ik = (s == 0.f) ? 1.f : 1.f / (pi2 * s);
    float2 rr;
    rr.x = (c.x * wrv - c.y * wiv) * ik;
    rr.y = (c.x * wiv + c.y * wrv) * ik;
    return rr;
}

// ---------------------------------------------------------------------------
// Composed 7x7 forward conv (real input) + wt*ik2 epilogue. 2 px/thread.
// ---------------------------------------------------------------------------
__global__ __launch_bounds__(256)
void k_conv7f(const float* __restrict__ X, float2* __restrict__ Y,
              const float2* __restrict__ wf,
              const float* __restrict__ wtr, const float* __restrict__ wti)
{
    int b = blockIdx.z;
    __shared__ float2 ws[49];
    int t = threadIdx.y * 16 + threadIdx.x;
    if (t < 49) ws[t] = wf[b * 49 + t];
    __syncthreads();
    int q = blockIdx.x * 16 + threadIdx.x;
    int p0 = blockIdx.y * 32 + 2 * threadIdx.y;
    if (q >= NG || p0 >= NG) return;
    bool hasP1 = (p0 + 1 < NG);
    const float* Xb = X + (long long)b * NN;
    float2 a0 = make_float2(0.f, 0.f), a1 = make_float2(0.f, 0.f);
    int pB = blockIdx.y * 32, qB = blockIdx.x * 16;
    bool interior = (pB >= 3) && (pB + 34 <= NG - 1) && (qB >= 3) && (qB + 18 <= NG - 1);
    if (interior) {
#pragma unroll
        for (int r = 0; r < 8; r++) {
            int row = p0 - 3 + r;
            float xr[7];
#pragma unroll
            for (int c = 0; c < 7; c++) xr[c] = Xb[(long long)row * NG + q - 3 + c];
#pragma unroll
            for (int dx = 0; dx < 7; dx++) {
                if (r < 7) {
                    float2 w = ws[r * 7 + dx];
                    a0.x = fmaf(xr[dx], w.x, a0.x);
                    a0.y = fmaf(xr[dx], w.y, a0.y);
                }
                if (r >= 1) {
                    float2 w = ws[(r - 1) * 7 + dx];
                    a1.x = fmaf(xr[dx], w.x, a1.x);
                    a1.y = fmaf(xr[dx], w.y, a1.y);
                }
            }
        }
    } else {
#pragma unroll
        for (int r = 0; r < 8; r++) {
            int row = p0 - 3 + r;
            bool vr = (row >= 0 && row < NG);
            float xr[7];
#pragma unroll
            for (int c = 0; c < 7; c++) {
                int col = q - 3 + c;
                xr[c] = (vr && col >= 0 && col < NG) ? Xb[(long long)row * NG + col] : 0.f;
            }
#pragma unroll
            for (int dx = 0; dx < 7; dx++) {
                if (r < 7) {
                    float2 w = ws[r * 7 + dx];
                    a0.x = fmaf(xr[dx], w.x, a0.x);
                    a0.y = fmaf(xr[dx], w.y, a0.y);
                }
                if (r >= 1) {
                    float2 w = ws[(r - 1) * 7 + dx];
                    a1.x = fmaf(xr[dx], w.x, a1.x);
                    a1.y = fmaf(xr[dx], w.y, a1.y);
                }
            }
        }
    }
    float2* Yb = Y + (long long)b * NN;
    {
        long long o = (long long)b * NN + (long long)p0 * NG + q;
        Yb[(long long)p0 * NG + q] = wtik_apply(a0, wtr[o], wti[o], p0, q);
    }
    if (hasP1) {
        long long o = (long long)b * NN + (long long)(p0 + 1) * NG + q;
        Yb[(long long)(p0 + 1) * NG + q] = wtik_apply(a1, wtr[o], wti[o], p0 + 1, q);
    }
}

// ---------------------------------------------------------------------------
// Composed 7x7 backward conv (complex input), taps = conj(wf^T). 2 px/thread.
// ---------------------------------------------------------------------------
__global__ __launch_bounds__(256)
void k_conv7b(const float2* __restrict__ X, float2* __restrict__ Y,
              const float2* __restrict__ wf)
{
    int b = blockIdx.z;
    __shared__ float2 ws[49];
    int t = threadIdx.y * 16 + threadIdx.x;
    if (t < 49) {
        int dy = t / 7, dx = t % 7;
        float2 v = wf[b * 49 + dx * 7 + dy];
        ws[t] = make_float2(v.x, -v.y);
    }
    __syncthreads();
    int q = blockIdx.x * 16 + threadIdx.x;
    int p0 = blockIdx.y * 32 + 2 * threadIdx.y;
    if (q >= NG || p0 >= NG) return;
    bool hasP1 = (p0 + 1 < NG);
    const float2* Xb = X + (long long)b * NN;
    float2 a0 = make_float2(0.f, 0.f), a1 = make_float2(0.f, 0.f);
    int pB = blockIdx.y * 32, qB = blockIdx.x * 16;
    bool interior = (pB >= 3) && (pB + 34 <= NG - 1) && (qB >= 3) && (qB + 18 <= NG - 1);
    if (interior) {
#pragma unroll
        for (int r = 0; r < 8; r++) {
            int row = p0 - 3 + r;
            float2 xr[7];
#pragma unroll
            for (int c = 0; c < 7; c++) xr[c] = Xb[(long long)row * NG + q - 3 + c];
#pragma unroll
            for (int dx = 0; dx < 7; dx++) {
                if (r < 7) a0 = cmad(a0, xr[dx], ws[r * 7 + dx]);
                if (r >= 1) a1 = cmad(a1, xr[dx], ws[(r - 1) * 7 + dx]);
            }
        }
    } else {
#pragma unroll
        for (int r = 0; r < 8; r++) {
            int row = p0 - 3 + r;
            bool vr = (row >= 0 && row < NG);
            float2 xr[7];
#pragma unroll
            for (int c = 0; c < 7; c++) {
                int col = q - 3 + c;
                xr[c] = (vr && col >= 0 && col < NG)
                      ? Xb[(long long)row * NG + col] : make_float2(0.f, 0.f);
            }
#pragma unroll
            for (int dx = 0; dx < 7; dx++) {
                if (r < 7) a0 = cmad(a0, xr[dx], ws[r * 7 + dx]);
                if (r >= 1) a1 = cmad(a1, xr[dx], ws[(r - 1) * 7 + dx]);
            }
        }
    }
    float2* Yb = Y + (long long)b * NN;
    Yb[(long long)p0 * NG + q] = a0;
    if (hasP1) Yb[(long long)(p0 + 1) * NG + q] = a1;
}

// ---------------------------------------------------------------------------
// Strip conv: exact sequential 3x3 conv on a boundary frame of width FW.
// Used to correct the 3-wide ring where stage-wise zero-padding differs
// from the composed operator. Always fully guarded (tiny pixel count).
// ---------------------------------------------------------------------------
template<int CO, int CI, int FW, bool REAL_IN, bool WTIK>
__global__ __launch_bounds__(256)
void k_conv_strip(const void* __restrict__ Xv, float2* __restrict__ Y,
                  const float* __restrict__ wr, const float* __restrict__ wi,
                  int conjt, const float* __restrict__ wtr,
                  const float* __restrict__ wti)
{
    int b = blockIdx.y;
    __shared__ float2 ws[CO * CI * 9];
    int t = threadIdx.x;
    if (t < CO * CI * 9) {
        int o = t / (CI * 9), rem = t % (CI * 9), i = rem / 9, tap = rem % 9;
        int dy = tap / 3, dx = tap % 3;
        long long widx;
        float sgn;
        if (conjt) { widx = ((long long)(b * CI + i) * CO + o) * 9 + dx * 3 + dy; sgn = -1.f; }
        else       { widx = ((long long)(b * CO + o) * CI + i) * 9 + dy * 3 + dx; sgn =  1.f; }
        ws[t] = make_float2(wr[widx], sgn * wi[widx]);
    }
    __syncthreads();

    const int nTop = FW * NG;
    const int nSide = (NG - 2 * FW) * FW;
    const int total = 2 * nTop + 2 * nSide;
    int idx = blockIdx.x * 256 + t;
    if (idx >= total) return;
    int p, q;
    if (idx < nTop)            { p = idx / NG; q = idx - p * NG; }
    else if (idx < 2 * nTop)   { int k2 = idx - nTop; p = NG - FW + k2 / NG; q = k2 % NG; }
    else if (idx < 2 * nTop + nSide) { int k2 = idx - 2 * nTop; p = FW + k2 / FW; q = k2 % FW; }
    else                       { int k2 = idx - 2 * nTop - nSide; p = FW + k2 / FW; q = NG - FW + k2 % FW; }

    float2 acc[CO];
#pragma unroll
    for (int o = 0; o < CO; o++) acc[o] = make_float2(0.f, 0.f);
#pragma unroll
    for (int i = 0; i < CI; i++) {
#pragma unroll
        for (int dy = 0; dy < 3; dy++) {
            int ii = p + dy - 1;
#pragma unroll
            for (int dx = 0; dx < 3; dx++) {
                int jj = q + dx - 1;
                float2 xv = make_float2(0.f, 0.f);
                if (ii >= 0 && ii < NG && jj >= 0 && jj < NG) {
                    if (REAL_IN) {
                        const float* Xb = (const float*)Xv + (long long)b * NN;
                        xv.x = Xb[(long long)ii * NG + jj];
                    } else {
                        const float2* Xb = (const float2*)Xv + (long long)b * CI * NN;
                        xv = Xb[(long long)i * NN + (long long)ii * NG + jj];
                    }
                }
                int tap = dy * 3 + dx;
#pragma unroll
                for (int o = 0; o < CO; o++)
                    acc[o] = cmad(acc[o], xv, ws[(o * CI + i) * 9 + tap]);
            }
        }
    }
    float2* Yb = Y + (long long)b * CO * NN;
    long long po = (long long)p * NG + q;
    if (WTIK) {
        long long o = (long long)b * NN + po;
        Yb[po] = wtik_apply(acc[0], wtr[o], wti[o], p, q);
    } else {
#pragma unroll
        for (int o = 0; o < CO; o++) Yb[(long long)o * NN + po] = acc[o];
    }
}

// ---------------------------------------------------------------------------
// Reductions (deterministic, double accumulation)
// ---------------------------------------------------------------------------
__global__ __launch_bounds__(256)
void k_alpha_part(const float* __restrict__ r, const float* __restrict__ e,
                  const float* __restrict__ a, double* __restrict__ p1,
                  double* __restrict__ p2)
{
    int b = blockIdx.y;
    const float* rb = r + (long long)b * NN;
    const float* eb = e + (long long)b * NN;
    const float* ab = a + (long long)b * NCC;
    double num = 0.0, den = 0.0;
    for (long long idx = (long long)blockIdx.x * 256 + threadIdx.x; idx < NN;
         idx += (long long)gridDim.x * 256) {
        int i = (int)(idx / NG), j = (int)(idx - (long long)i * NG);
        float ev = eb[idx];
        num += (double)(rb[idx] * ev);
        if (i > 0 && j > 0 && i < NG - 1 && j < NG - 1) {
            float d = darcy_at(eb, ab, i, j);
            den += (double)(d * ev);
        }
    }
    __shared__ double s1[256], s2[256];
    int t = threadIdx.x;
    s1[t] = num; s2[t] = den;
    __syncthreads();
    for (int s = 128; s > 0; s >>= 1) {
        if (t < s) { s1[t] += s1[t + s]; s2[t] += s2[t + s]; }
        __syncthreads();
    }
    if (t == 0) { p1[b * NBLK_A + blockIdx.x] = s1[0]; p2[b * NBLK_A + blockIdx.x] = s2[0]; }
}

__global__ void k_alpha_fin(const double* __restrict__ p1,
                            const double* __restrict__ p2,
                            float* __restrict__ alpha)
{
    int b = blockIdx.x;
    __shared__ double s1[256], s2[256];
    double n = 0.0, d = 0.0;
    for (int i = threadIdx.x; i < NBLK_A; i += 256) {
        n += p1[b * NBLK_A + i]; d += p2[b * NBLK_A + i];
    }
    int t = threadIdx.x;
    s1[t] = n; s2[t] = d;
    __syncthreads();
    for (int s = 128; s > 0; s >>= 1) {
        if (t < s) { s1[t] += s1[t + s]; s2[t] += s2[t + s]; }
        __syncthreads();
    }
    if (t == 0) alpha[b] = (float)(s1[0] / s2[0]);
}

__global__ void k_update(float* __restrict__ x, const float* __restrict__ e,
                         const float* __restrict__ alpha)
{
    int b = blockIdx.z;
    int j = blockIdx.x * 16 + threadIdx.x + 1;
    int i = blockIdx.y * 16 + threadIdx.y + 1;
    if (i > NI || j > NI) return;
    long long o = (long long)b * NN + (long long)i * NG + j;
    x[o] = fmaf(alpha[b], e[o], x[o]);
}

__global__ __launch_bounds__(256)
void k_norm_part(const float* __restrict__ r, const float* __restrict__ f,
                 double* __restrict__ p1, double* __restrict__ p2)
{
    double sr = 0.0, sf = 0.0;
    long long tot = (long long)NB * NN;
    for (long long idx = (long long)blockIdx.x * 256 + threadIdx.x; idx < tot;
         idx += (long long)gridDim.x * 256) {
        float rv = r[idx], fv = f[idx];
        sr += (double)rv * rv;
        sf += (double)fv * fv;
    }
    __shared__ double s1[256], s2[256];
    int t = threadIdx.x;
    s1[t] = sr; s2[t] = sf;
    __syncthreads();
    for (int s = 128; s > 0; s >>= 1) {
        if (t < s) { s1[t] += s1[t + s]; s2[t] += s2[t + s]; }
        __syncthreads();
    }
    if (t == 0) { p1[blockIdx.x] = s1[0]; p2[blockIdx.x] = s2[0]; }
}

__global__ void k_norm_fin(const double* __restrict__ p1,
                           const double* __restrict__ p2,
                           float* __restrict__ out)
{
    __shared__ double s1[256], s2[256];
    double a = 0.0, b = 0.0;
    for (int i = threadIdx.x; i < NBLK_N; i += 256) { a += p1[i]; b += p2[i]; }
    int t = threadIdx.x;
    s1[t] = a; s2[t] = b;
    __syncthreads();
    for (int s = 128; s > 0; s >>= 1) {
        if (t < s) { s1[t] += s1[t + s]; s2[t] += s2[t + s]; }
        __syncthreads();
    }
    if (t == 0) out[0] = (float)sqrt(s1[0] / s2[0]);
}

// ---------------------------------------------------------------------------
// Host orchestration
// ---------------------------------------------------------------------------
template<typename T>
static T* sym_addr(const void* sym)
{
    void* p = nullptr;
    cudaGetSymbolAddress(&p, sym);
    return (T*)p;
}

static inline int strip_blocks(int FW)
{
    int nTop = FW * NG, nSide = (NG - 2 * FW) * FW;
    int total = 2 * nTop + 2 * nSide;
    return (total + 255) / 256;
}

extern "C" void kernel_launch(void* const* d_in, const int* in_sizes, int n_in,
                              void* d_out, int out_size)
{
    const float* f    = (const float*)d_in[0];
    const float* coef = (const float*)d_in[1];
    const float* w1r = (const float*)d_in[3];
    const float* w1i = (const float*)d_in[4];
    const float* w2r = (const float*)d_in[5];
    const float* w2i = (const float*)d_in[6];
    const float* w3r = (const float*)d_in[7];
    const float* w3i = (const float*)d_in[8];
    const float* wtr = (const float*)d_in[9];
    const float* wti = (const float*)d_in[10];

    float*  x    = sym_addr<float>(g_x);
    float*  x2   = sym_addr<float>(g_x2);
    float*  r    = sym_addr<float>(g_r);
    float*  e    = sym_addr<float>(g_e);
    float*  rh   = sym_addr<float>(g_rh);
    float*  dinv = sym_addr<float>(g_dinv);
    float*  S    = sym_addr<float>(g_S);
    float*  St   = sym_addr<float>(g_St);
    float2* G    = sym_addr<float2>(g_G);
    float2* Gt   = sym_addr<float2>(g_Gt);
    float*  U    = sym_addr<float>(g_U);
    float2* cA   = sym_addr<float2>(g_cA);
    float2* cB   = sym_addr<float2>(g_cB);
    float2* cC   = sym_addr<float2>(g_cC);
    float2* cD   = sym_addr<float2>(g_cD);
    float2* W    = sym_addr<float2>(g_W);
    float2* wf   = sym_addr<float2>(g_wf);
    double* pd1  = sym_addr<double>(g_pd1);
    double* pd2  = sym_addr<double>(g_pd2);
    float*  alph = sym_addr<float>(g_alpha);

    dim3 blk2(16, 16);
    dim3 gInt((NI + 15) / 16, (NI + 15) / 16, NB);
    dim3 gFull((NG + 15) / 16, (NG + 15) / 16, NB);
    dim3 gJac(16, 16, NB);
    dim3 gConv((NG + 15) / 16, (NG + 31) / 32, NB);

    dim3 gS5(strip_blocks(5), NB);
    dim3 gS4(strip_blocks(4), NB);
    dim3 gS3(strip_blocks(3), NB);

    // ---- setup ----
    {
        long long tot = (long long)NB * NN;
        k_zero3<<<(int)((tot + 255) / 256), 256>>>(x, x2, e);
        int nSG = NG * NI;
        k_precS<<<(nSG + 255) / 256, 256>>>(S, St);
        k_precG<<<(nSG + 255) / 256, 256>>>(G, Gt);
        k_dinv<<<gInt, blk2>>>(coef, dinv);
        k_compose<<<NB, 64>>>(w1r, w1i, w2r, w2i, w3r, w3i, wf);
    }

    float* xa = x;
    float* xb = x2;

    for (int step = 0; step < KSTEPS; step++) {
        // ---- 10 Jacobi sweeps ----
        for (int it = 0; it < 10; it++) {
            k_jacobi2<<<gJac, blk2>>>(xa, xb, f, coef, dinv);
            float* tmp = xa; xa = xb; xb = tmp;
        }
        // ---- residual ----
        k_resid<<<gFull, blk2>>>(xa, f, coef, r);

        // ---- forward sine transform (odd symmetry fused in epilogue) ----
        {
            dim3 g((257 + 63) / 64, (NI + 63) / 64, NB);
            k_sgemm<1><<<g, 256>>>(r + NG + 1, NG, NN,
                                   St + 256, NG, 0,
                                   U, NG, NIG,
                                   NI, 257, NI, 1.f);
        }
        {
            dim3 g((NG + 63) / 64, (257 + 63) / 64, NB);
            k_sgemm<2><<<g, 256>>>(S + 256 * NI, NI, 0,
                                   U, NG, NIG,
                                   rh, NG, NN,
                                   257, NG, NI, -1.f / (512.f * 512.f));
        }

        // ---- forward conv chain: composed 7x7 + exact ring correction ----
        k_conv7f<<<gConv, blk2>>>(rh, cC, wf, wtr, wti);
        k_conv_strip<4, 1, 5, true,  false><<<gS5, 256>>>(rh, cA, w1r, w1i, 0, nullptr, nullptr);
        k_conv_strip<4, 4, 4, false, false><<<gS4, 256>>>(cA, cB, w2r, w2i, 0, nullptr, nullptr);
        k_conv_strip<1, 4, 3, false, true ><<<gS3, 256>>>(cB, cC, w3r, w3i, 0, wtr, wti);

        // ---- backward conv chain: composed conj(wf^T) + ring correction ----
        k_conv7b<<<gConv, blk2>>>(cC, cD, wf);
        k_conv_strip<4, 1, 5, false, false><<<gS5, 256>>>(cC, cA, w3r, w3i, 1, nullptr, nullptr);
        k_conv_strip<4, 4, 4, false, false><<<gS4, 256>>>(cA, cB, w2r, w2i, 1, nullptr, nullptr);
        k_conv_strip<1, 4, 3, false, false><<<gS3, 256>>>(cB, cD, w1r, w1i, 1, nullptr, nullptr);

        // ---- inverse transform: W = cD * Gt (Karatsuba), e_int = Re(G * W) ----
        {
            dim3 g((NI + 63) / 64, (NG + 63) / 64, NB);
            k_cgemm_kar<<<g, 256>>>(cD, NG, NN,
                                    Gt, NI, 0,
                                    W, NI, NIG,
                                    NG, NI, NG);
        }
        {
            dim3 g((NI + 63) / 64, (NI + 63) / 64, NB);
            k_cgemm_re<<<g, 256>>>(G, NG, 0,
                                   W, NI, NIG,
                                   e + NG + 1, NG, NN,
                                   NI, NI, NG);
        }

        // ---- alpha and update ----
        {
            dim3 g(NBLK_A, NB);
            k_alpha_part<<<g, 256>>>(r, e, coef, pd1, pd2);
            k_alpha_fin<<<NB, 256>>>(pd1, pd2, alph);
            k_update<<<gInt, blk2>>>(xa, e, alph);
        }
    }

    // ---- final relative residual norm ----
    k_resid<<<gFull, blk2>>>(xa, f, coef, r);
    k_norm_part<<<NBLK_N, 256>>>(r, f, pd1, pd2);
    k_norm_fin<<<1, 256>>>(pd1, pd2, (float*)d_out);
}

// round 8
// speedup vs baseline: 1.7979x; 1.0333x over previous
#include <cuda_runtime.h>
#include <math.h>

#define DINLINE __device__ __forceinline__

// ---------------------------------------------------------------------------
// Fixed problem dimensions (B=4, grid 513, coef 512, epoch=101 -> K=2)
// ---------------------------------------------------------------------------
namespace fns {
constexpr int NB = 4;
constexpr int NG = 513;
constexpr int NI = 511;
constexpr int NC = 512;
constexpr int NK = 258;              // folded twiddle rows (k = 0..257)
constexpr int NK2 = 516;             // stacked [C;S] K dimension
constexpr long long NN  = (long long)NG * NG;
constexpr long long NCC = (long long)NC * NC;
constexpr long long NII = (long long)NI * NI;
constexpr long long NIG = (long long)NI * NG;
constexpr long long NA  = (long long)NG * NK2;   // 513 x 516
constexpr long long NF  = (long long)NK2 * NI;   // 516 x 511
constexpr int NBLK_A = 128;
constexpr int NBLK_N = 256;
constexpr int KSTEPS = 2;
}
using namespace fns;

// ---------------------------------------------------------------------------
// Static device scratch
// ---------------------------------------------------------------------------
__device__ float  g_x   [NB * NN];
__device__ float  g_x2  [NB * NN];
__device__ float  g_r   [NB * NN];
__device__ float  g_e   [NB * NN];
__device__ float  g_rh  [NB * NN];
__device__ float  g_dinv[NB * NII];
__device__ float  g_S   [NG * (long long)NI];  // S[p][j], ld=NI
__device__ float  g_St  [NIG];                 // St[j][p], ld=NG
__device__ float  g_U   [NB * NIG];            // 511 x 513, ld=NG
__device__ float2 g_cA  [NB * 4 * NN];         // strip scratch stage-1
__device__ float2 g_cB  [NB * 4 * NN];         // strip scratch stage-2
__device__ float2 g_cC  [NB * NN];             // spectral signal
__device__ float2 g_cD  [NB * NN];             // backward-conv output
__device__ float2 g_wf  [NB * 49];             // composed 7x7 forward taps
__device__ float  g_Wr  [NB * NIG];            // Re(W), 513 x 511, ld=NI
__device__ float  g_Wi  [NB * NIG];            // Im(W), 513 x 511, ld=NI
__device__ float  g_A1  [NB * NA];             // [Pr | -Mi], 513 x 516
__device__ float  g_A2  [NB * NA];             // [Pi |  Mr], 513 x 516
__device__ float  g_F   [NB * NF];             // [A ; B], 516 x 511
__device__ float  g_Bm  [NF];                  // [C ; S], 516 x 511 (const)
__device__ float  g_Em  [(long long)NI * NK2]; // [Cos | Sin], 511 x 516 (const)
__device__ double g_pd1 [2048];
__device__ double g_pd2 [2048];
__device__ float  g_alpha[NB];

// ---------------------------------------------------------------------------
// Darcy FEM 9-point stencil (pointer form, used by resid / alpha)
// ---------------------------------------------------------------------------
DINLINE float darcy_at(const float* __restrict__ x,
                       const float* __restrict__ a, int i, int j)
{
    const float c23 = 2.f / 3.f, c16 = -1.f / 6.f, c13 = -1.f / 3.f;
    float s = 0.f;
#pragma unroll
    for (int u = 0; u < 2; u++) {
#pragma unroll
        for (int v = 0; v < 2; v++) {
            int I = i - 1 + u, J = j - 1 + v;
            float av = a[(long long)I * NC + J];
            float k0, k1, k2, k3;
            if (u == 0 && v == 0) { k0 = c16; k1 = c23; k2 = c16; k3 = c13; }
            else if (u == 0 && v == 1) { k0 = c23; k1 = c16; k2 = c13; k3 = c16; }
            else if (u == 1 && v == 0) { k0 = c13; k1 = c16; k2 = c23; k3 = c16; }
            else                        { k0 = c16; k1 = c13; k2 = c16; k3 = c23; }
            s += av * (k3 * x[(long long)I * NG + J]
                     + k2 * x[(long long)I * NG + J + 1]
                     + k0 * x[(long long)(I + 1) * NG + J]
                     + k1 * x[(long long)(I + 1) * NG + J + 1]);
        }
    }
    return s;
}

DINLINE float2 cmad(float2 acc, float2 a, float2 b)
{
    acc.x = fmaf(a.x, b.x, fmaf(-a.y, b.y, acc.x));
    acc.y = fmaf(a.x, b.y, fmaf(a.y, b.x, acc.y));
    return acc;
}

// ---------------------------------------------------------------------------
// Setup kernels
// ---------------------------------------------------------------------------
__global__ void k_precS(float* __restrict__ S, float* __restrict__ St)
{
    int idx = blockIdx.x * blockDim.x + threadIdx.x;
    if (idx >= NG * NI) return;
    int p = idx / NI, j = idx - p * NI;
    int m = (j + 1) * (p - 256);
    int mm = ((m % 1024) + 1024) % 1024;
    float v = sinpif((float)mm / 512.f);
    S[idx] = v;
    St[(long long)j * NG + p] = v;
}

// Bm rows 0..257:  C[k][s] = cos(2*pi*k*s/1025)
// Bm rows 258..515: S[k][s] = -sin(2*pi*k*s/1025)
__global__ void k_precB(float* __restrict__ Bm)
{
    int idx = blockIdx.x * blockDim.x + threadIdx.x;
    if (idx >= NK2 * NI) return;
    int k2 = idx / NI, s = idx - k2 * NI;
    int k = (k2 < NK) ? k2 : k2 - NK;
    int tm = (2 * k * s) % 2050;
    float xr = (float)tm / 1025.f;
    Bm[idx] = (k2 < NK) ? cospif(xr) : -sinpif(xr);
}

// Em cols 0..257:  Cos[s][k] = cos(2*pi*s*k/1025)
// Em cols 258..515: Sin[s][k] = sin(2*pi*s*k/1025)
__global__ void k_precE(float* __restrict__ Em)
{
    int idx = blockIdx.x * blockDim.x + threadIdx.x;
    if (idx >= NI * NK2) return;
    int s = idx / NK2, k2 = idx - s * NK2;
    int k = (k2 < NK) ? k2 : k2 - NK;
    int tm = (2 * s * k) % 2050;
    float xr = (float)tm / 1025.f;
    Em[idx] = (k2 < NK) ? cospif(xr) : sinpif(xr);
}

__global__ void k_dinv(const float* __restrict__ a, float* __restrict__ dinv)
{
    int b = blockIdx.z;
    int q = blockIdx.x * 16 + threadIdx.x;
    int p = blockIdx.y * 16 + threadIdx.y;
    if (p >= NI || q >= NI) return;
    const float* ap = a + (long long)b * NCC;
    float s = ap[(long long)p * NC + q] + ap[(long long)p * NC + q + 1]
            + ap[(long long)(p + 1) * NC + q] + ap[(long long)(p + 1) * NC + q + 1];
    dinv[(long long)b * NII + (long long)p * NI + q] = 1.f / ((2.f / 3.f) * s);
}

__global__ void k_zero3(float* __restrict__ x, float* __restrict__ x2,
                        float* __restrict__ e)
{
    long long idx = (long long)blockIdx.x * blockDim.x + threadIdx.x;
    long long tot = (long long)NB * NN;
    if (idx >= tot) return;
    x[idx] = 0.f; x2[idx] = 0.f; e[idx] = 0.f;
}

// ---------------------------------------------------------------------------
// Compose the 3-stage complex conv chain into one 7x7 tap set.
// ---------------------------------------------------------------------------
__global__ void k_compose(const float* __restrict__ w1r, const float* __restrict__ w1i,
                          const float* __restrict__ w2r, const float* __restrict__ w2i,
                          const float* __restrict__ w3r, const float* __restrict__ w3i,
                          float2* __restrict__ wf)
{
    int b = blockIdx.x;
    int t = threadIdx.x;
    if (t >= 49) return;
    int dy = t / 7, dx = t % 7;
    float accr = 0.f, acci = 0.f;
    for (int c = 0; c < 4; c++) {
        for (int o = 0; o < 4; o++) {
            for (int a = 0; a < 9; a++) {
                int ay = a / 3, ax = a % 3;
                float r1 = w1r[(b * 4 + c) * 9 + a];
                float i1 = w1i[(b * 4 + c) * 9 + a];
                for (int bt = 0; bt < 9; bt++) {
                    int by = bt / 3, bx = bt % 3;
                    int cy = dy - ay - by, cx = dx - ax - bx;
                    if (cy < 0 || cy > 2 || cx < 0 || cx > 2) continue;
                    float r2 = w2r[((b * 4 + o) * 4 + c) * 9 + bt];
                    float i2 = w2i[((b * 4 + o) * 4 + c) * 9 + bt];
                    float r3 = w3r[(b * 4 + o) * 9 + cy * 3 + cx];
                    float i3 = w3i[(b * 4 + o) * 9 + cy * 3 + cx];
                    float tr = r1 * r2 - i1 * i2;
                    float ti = r1 * i2 + i1 * r2;
                    accr += tr * r3 - ti * i3;
                    acci += tr * i3 + ti * r3;
                }
            }
        }
    }
    wf[b * 49 + t] = make_float2(accr, acci);
}

// ---------------------------------------------------------------------------
// Jacobi sweep: 2x2 nodes per thread (proven R4)
// ---------------------------------------------------------------------------
__global__ __launch_bounds__(256)
void k_jacobi2(const float* __restrict__ xin, float* __restrict__ xout,
               const float* __restrict__ f, const float* __restrict__ a,
               const float* __restrict__ dinv)
{
    int b = blockIdx.z;
    int tj = blockIdx.x * 16 + threadIdx.x;
    int ti = blockIdx.y * 16 + threadIdx.y;
    int i0 = 2 * ti + 1, j0 = 2 * tj + 1;
    if (i0 > NI || j0 > NI) return;
    const float* xp = xin + (long long)b * NN;
    const float* ap = a + (long long)b * NCC;
    const float* fp = f + (long long)b * NN;
    const float* dp = dinv + (long long)b * NII;
    float* xo = xout + (long long)b * NN;

    float xx[4][4];
#pragma unroll
    for (int di = 0; di < 4; di++) {
        int ii = i0 - 1 + di;
        bool vi = (ii <= NG - 1);
#pragma unroll
        for (int dj = 0; dj < 4; dj++) {
            int jj = j0 - 1 + dj;
            xx[di][dj] = (vi && jj <= NG - 1) ? xp[(long long)ii * NG + jj] : 0.f;
        }
    }
    float ax[3][3];
#pragma unroll
    for (int di = 0; di < 3; di++) {
        int II = i0 - 1 + di;
        bool vi = (II <= NC - 1);
#pragma unroll
        for (int dj = 0; dj < 3; dj++) {
            int JJ = j0 - 1 + dj;
            ax[di][dj] = (vi && JJ <= NC - 1) ? ap[(long long)II * NC + JJ] : 0.f;
        }
    }

    const float c23 = 2.f / 3.f, c16 = -1.f / 6.f, c13 = -1.f / 3.f;
#pragma unroll
    for (int u = 0; u < 2; u++) {
#pragma unroll
        for (int v = 0; v < 2; v++) {
            int i = i0 + u, j = j0 + v;
            if (i > NI || j > NI) continue;
            float s = 0.f;
#pragma unroll
            for (int uu = 0; uu < 2; uu++) {
#pragma unroll
                for (int vv = 0; vv < 2; vv++) {
                    float av = ax[u + uu][v + vv];
                    float k0, k1, k2, k3;
                    if (uu == 0 && vv == 0) { k0 = c16; k1 = c23; k2 = c16; k3 = c13; }
                    else if (uu == 0 && vv == 1) { k0 = c23; k1 = c16; k2 = c13; k3 = c16; }
                    else if (uu == 1 && vv == 0) { k0 = c13; k1 = c16; k2 = c23; k3 = c16; }
                    else                          { k0 = c16; k1 = c13; k2 = c16; k3 = c23; }
                    s += av * (k3 * xx[u + uu][v + vv]
                             + k2 * xx[u + uu][v + vv + 1]
                             + k0 * xx[u + uu + 1][v + vv]
                             + k1 * xx[u + uu + 1][v + vv + 1]);
                }
            }
            long long o = (long long)i * NG + j;
            float r = fp[o] - s;
            xo[o] = xx[1 + u][1 + v]
                  + 0.75f * dp[(long long)(i - 1) * NI + (j - 1)] * r;
        }
    }
}

__global__ __launch_bounds__(256)
void k_resid(const float* __restrict__ x, const float* __restrict__ f,
             const float* __restrict__ a, float* __restrict__ r)
{
    int b = blockIdx.z;
    int j = blockIdx.x * 16 + threadIdx.x;
    int i = blockIdx.y * 16 + threadIdx.y;
    if (i >= NG || j >= NG) return;
    long long o = (long long)b * NN + (long long)i * NG + j;
    float d = 0.f;
    if (i > 0 && j > 0 && i < NG - 1 && j < NG - 1)
        d = darcy_at(x + (long long)b * NN, a + (long long)b * NCC, i, j);
    r[o] = f[o] - d;
}

// ---------------------------------------------------------------------------
// Real SGEMM, double-buffered, 64x64/BK16, mirror epilogues (proven R4).
// ---------------------------------------------------------------------------
template<int MIR>
__global__ __launch_bounds__(256)
void k_sgemm(const float* __restrict__ A, int lda, long long sA,
             const float* __restrict__ B, int ldb, long long sB,
             float* __restrict__ C, int ldc, long long sC,
             int M, int N, int K, float alpha)
{
    __shared__ float As[2][16][68];
    __shared__ float Bs[2][16][68];
    int b = blockIdx.z;
    A += (long long)b * sA;
    B += (long long)b * sB;
    C += (long long)b * sC;
    int tid = threadIdx.x;
    int m0 = blockIdx.y * 64, n0 = blockIdx.x * 64;
    int mt = (tid & 15) * 4;
    int nt = (tid >> 4) * 4;
    int ra_r[4], ra_c[4], rb_r[4], rb_c[4];
#pragma unroll
    for (int e = 0; e < 4; e++) {
        int idx = tid + e * 256;
        ra_r[e] = idx >> 4; ra_c[e] = idx & 15;
        rb_r[e] = idx >> 6; rb_c[e] = idx & 63;
    }
    float ra[4], rb[4];
    int ntiles = (K + 15) / 16;

#pragma unroll
    for (int e = 0; e < 4; e++) {
        int gm = m0 + ra_r[e], gk = ra_c[e];
        ra[e] = (gm < M && gk < K) ? A[(long long)gm * lda + gk] : 0.f;
        int gk2 = rb_r[e], gn = n0 + rb_c[e];
        rb[e] = (gk2 < K && gn < N) ? B[(long long)gk2 * ldb + gn] : 0.f;
    }
#pragma unroll
    for (int e = 0; e < 4; e++) {
        As[0][ra_c[e]][ra_r[e]] = ra[e];
        Bs[0][rb_r[e]][rb_c[e]] = rb[e];
    }
    __syncthreads();

    float acc[4][4] = {};
    for (int t = 0; t < ntiles; t++) {
        int kt = (t + 1) * 16;
        if (t + 1 < ntiles) {
#pragma unroll
            for (int e = 0; e < 4; e++) {
                int gm = m0 + ra_r[e], gk = kt + ra_c[e];
                ra[e] = (gm < M && gk < K) ? A[(long long)gm * lda + gk] : 0.f;
                int gk2 = kt + rb_r[e], gn = n0 + rb_c[e];
                rb[e] = (gk2 < K && gn < N) ? B[(long long)gk2 * ldb + gn] : 0.f;
            }
        }
        int cur = t & 1;
#pragma unroll
        for (int k = 0; k < 16; k++) {
            float av[4], bv[4];
#pragma unroll
            for (int i = 0; i < 4; i++) av[i] = As[cur][k][mt + i];
#pragma unroll
            for (int j = 0; j < 4; j++) bv[j] = Bs[cur][k][nt + j];
#pragma unroll
            for (int i = 0; i < 4; i++)
#pragma unroll
                for (int j = 0; j < 4; j++)
                    acc[i][j] = fmaf(av[i], bv[j], acc[i][j]);
        }
        if (t + 1 < ntiles) {
            int nxt = cur ^ 1;
#pragma unroll
            for (int e = 0; e < 4; e++) {
                As[nxt][ra_c[e]][ra_r[e]] = ra[e];
                Bs[nxt][rb_r[e]][rb_c[e]] = rb[e];
            }
        }
        __syncthreads();
    }

#pragma unroll
    for (int i = 0; i < 4; i++) {
        int gm = m0 + mt + i;
        if (gm >= M) continue;
#pragma unroll
        for (int j = 0; j < 4; j++) {
            int gn = n0 + nt + j;
            if (gn >= N) continue;
            float v = alpha * acc[i][j];
            if (MIR == 0) {
                C[(long long)gm * ldc + gn] = v;
            } else if (MIR == 1) {
                C[(long long)gm * ldc + 256 + gn] = v;
                if (gn > 0) C[(long long)gm * ldc + 256 - gn] = -v;
            } else {
                C[(long long)(256 + gm) * ldc + gn] = v;
                if (gm > 0) C[(long long)(256 - gm) * ldc + gn] = -v;
            }
        }
    }
}

// ---------------------------------------------------------------------------
// Fold kernels for the conjugate-symmetric inverse transform.
// fold1: cD (complex 513x513) -> A1 = [Pr | -Mi], A2 = [Pi | Mr]  (513x516)
//        P_k = cD[:,255+k] + cD[:,255-k], M_k = cD[:,255+k] - cD[:,255-k]
//        (minus-term zero for k=0 and k>255)
// ---------------------------------------------------------------------------
__global__ void k_fold1(const float2* __restrict__ cD,
                        float* __restrict__ A1, float* __restrict__ A2)
{
    int b = blockIdx.z;
    int k = blockIdx.x * 32 + threadIdx.x;
    int p = blockIdx.y * 8 + threadIdx.y;
    if (k >= NK || p >= NG) return;
    const float2* D = cD + (long long)b * NN + (long long)p * NG;
    float2 plus = D[255 + k];
    float2 minus = (k >= 1 && k <= 255) ? D[255 - k] : make_float2(0.f, 0.f);
    float* a1 = A1 + (long long)b * NA + (long long)p * NK2;
    float* a2 = A2 + (long long)b * NA + (long long)p * NK2;
    a1[k]      = plus.x + minus.x;      // Pr
    a1[NK + k] = -(plus.y - minus.y);   // -Mi
    a2[k]      = plus.y + minus.y;      // Pi
    a2[NK + k] = plus.x - minus.x;      // Mr
}

// fold2: Wr, Wi (513x511 real) -> F = [Wr+ + Wr- ; Wi+ - Wi-] (516x511)
__global__ void k_fold2(const float* __restrict__ Wr, const float* __restrict__ Wi,
                        float* __restrict__ F)
{
    int b = blockIdx.z;
    int t = blockIdx.x * 32 + threadIdx.x;
    int k = blockIdx.y * 8 + threadIdx.y;
    if (t >= NI || k >= NK) return;
    const float* wr = Wr + (long long)b * NIG;
    const float* wi = Wi + (long long)b * NIG;
    bool paired = (k >= 1 && k <= 255);
    float wrp = wr[(long long)(255 + k) * NI + t];
    float wrm = paired ? wr[(long long)(255 - k) * NI + t] : 0.f;
    float wip = wi[(long long)(255 + k) * NI + t];
    float wim = paired ? wi[(long long)(255 - k) * NI + t] : 0.f;
    float* Fb = F + (long long)b * NF;
    Fb[(long long)k * NI + t]        = wrp + wrm;
    Fb[(long long)(NK + k) * NI + t] = wip - wim;
}

// ---------------------------------------------------------------------------
// wt*ik2 helper
// ---------------------------------------------------------------------------
DINLINE float2 wtik_apply(float2 c, float wrv, float wiv, int p, int q)
{
    float dp = (float)(p - 256), dq = (float)(q - 256);
    float s = dp * dp + dq * dq;
    const float pi2 = 9.869604401089358f;
    float ik = (s == 0.f) ? 1.f : 1.f / (pi2 * s);
    float2 rr;
    rr.x = (c.x * wrv - c.y * wiv) * ik;
    rr.y = (c.x * wiv + c.y * wrv) * ik;
    return rr;
}

// ---------------------------------------------------------------------------
// Composed 7x7 forward conv (real input) + wt*ik2 epilogue. 2 px/thread.
// ---------------------------------------------------------------------------
__global__ __launch_bounds__(256)
void k_conv7f(const float* __restrict__ X, float2* __restrict__ Y,
              const float2* __restrict__ wf,
              const float* __restrict__ wtr, const float* __restrict__ wti)
{
    int b = blockIdx.z;
    __shared__ float2 ws[49];
    int t = threadIdx.y * 16 + threadIdx.x;
    if (t < 49) ws[t] = wf[b * 49 + t];
    __syncthreads();
    int q = blockIdx.x * 16 + threadIdx.x;
    int p0 = blockIdx.y * 32 + 2 * threadIdx.y;
    if (q >= NG || p0 >= NG) return;
    bool hasP1 = (p0 + 1 < NG);
    const float* Xb = X + (long long)b * NN;
    float2 a0 = make_float2(0.f, 0.f), a1 = make_float2(0.f, 0.f);
    int pB = blockIdx.y * 32, qB = blockIdx.x * 16;
    bool interior = (pB >= 3) && (pB + 34 <= NG - 1) && (qB >= 3) && (qB + 18 <= NG - 1);
    if (interior) {
#pragma unroll
        for (int r = 0; r < 8; r++) {
            int row = p0 - 3 + r;
            float xr[7];
#pragma unroll
            for (int c = 0; c < 7; c++) xr[c] = Xb[(long long)row * NG + q - 3 + c];
#pragma unroll
            for (int dx = 0; dx < 7; dx++) {
                if (r < 7) {
                    float2 w = ws[r * 7 + dx];
                    a0.x = fmaf(xr[dx], w.x, a0.x);
                    a0.y = fmaf(xr[dx], w.y, a0.y);
                }
                if (r >= 1) {
                    float2 w = ws[(r - 1) * 7 + dx];
                    a1.x = fmaf(xr[dx], w.x, a1.x);
                    a1.y = fmaf(xr[dx], w.y, a1.y);
                }
            }
        }
    } else {
#pragma unroll
        for (int r = 0; r < 8; r++) {
            int row = p0 - 3 + r;
            bool vr = (row >= 0 && row < NG);
            float xr[7];
#pragma unroll
            for (int c = 0; c < 7; c++) {
                int col = q - 3 + c;
                xr[c] = (vr && col >= 0 && col < NG) ? Xb[(long long)row * NG + col] : 0.f;
            }
#pragma unroll
            for (int dx = 0; dx < 7; dx++) {
                if (r < 7) {
                    float2 w = ws[r * 7 + dx];
                    a0.x = fmaf(xr[dx], w.x, a0.x);
                    a0.y = fmaf(xr[dx], w.y, a0.y);
                }
                if (r >= 1) {
                    float2 w = ws[(r - 1) * 7 + dx];
                    a1.x = fmaf(xr[dx], w.x, a1.x);
                    a1.y = fmaf(xr[dx], w.y, a1.y);
                }
            }
        }
    }
    float2* Yb = Y + (long long)b * NN;
    {
        long long o = (long long)b * NN + (long long)p0 * NG + q;
        Yb[(long long)p0 * NG + q] = wtik_apply(a0, wtr[o], wti[o], p0, q);
    }
    if (hasP1) {
        long long o = (long long)b * NN + (long long)(p0 + 1) * NG + q;
        Yb[(long long)(p0 + 1) * NG + q] = wtik_apply(a1, wtr[o], wti[o], p0 + 1, q);
    }
}

// ---------------------------------------------------------------------------
// Composed 7x7 backward conv (complex input), taps = conj(wf^T). 2 px/thread.
// ---------------------------------------------------------------------------
__global__ __launch_bounds__(256)
void k_conv7b(const float2* __restrict__ X, float2* __restrict__ Y,
              const float2* __restrict__ wf)
{
    int b = blockIdx.z;
    __shared__ float2 ws[49];
    int t = threadIdx.y * 16 + threadIdx.x;
    if (t < 49) {
        int dy = t / 7, dx = t % 7;
        float2 v = wf[b * 49 + dx * 7 + dy];
        ws[t] = make_float2(v.x, -v.y);
    }
    __syncthreads();
    int q = blockIdx.x * 16 + threadIdx.x;
    int p0 = blockIdx.y * 32 + 2 * threadIdx.y;
    if (q >= NG || p0 >= NG) return;
    bool hasP1 = (p0 + 1 < NG);
    const float2* Xb = X + (long long)b * NN;
    float2 a0 = make_float2(0.f, 0.f), a1 = make_float2(0.f, 0.f);
    int pB = blockIdx.y * 32, qB = blockIdx.x * 16;
    bool interior = (pB >= 3) && (pB + 34 <= NG - 1) && (qB >= 3) && (qB + 18 <= NG - 1);
    if (interior) {
#pragma unroll
        for (int r = 0; r < 8; r++) {
            int row = p0 - 3 + r;
            float2 xr[7];
#pragma unroll
            for (int c = 0; c < 7; c++) xr[c] = Xb[(long long)row * NG + q - 3 + c];
#pragma unroll
            for (int dx = 0; dx < 7; dx++) {
                if (r < 7) a0 = cmad(a0, xr[dx], ws[r * 7 + dx]);
                if (r >= 1) a1 = cmad(a1, xr[dx], ws[(r - 1) * 7 + dx]);
            }
        }
    } else {
#pragma unroll
        for (int r = 0; r < 8; r++) {
            int row = p0 - 3 + r;
            bool vr = (row >= 0 && row < NG);
            float2 xr[7];
#pragma unroll
            for (int c = 0; c < 7; c++) {
                int col = q - 3 + c;
                xr[c] = (vr && col >= 0 && col < NG)
                      ? Xb[(long long)row * NG + col] : make_float2(0.f, 0.f);
            }
#pragma unroll
            for (int dx = 0; dx < 7; dx++) {
                if (r < 7) a0 = cmad(a0, xr[dx], ws[r * 7 + dx]);
                if (r >= 1) a1 = cmad(a1, xr[dx], ws[(r - 1) * 7 + dx]);
            }
        }
    }
    float2* Yb = Y + (long long)b * NN;
    Yb[(long long)p0 * NG + q] = a0;
    if (hasP1) Yb[(long long)(p0 + 1) * NG + q] = a1;
}

// ---------------------------------------------------------------------------
// Strip conv: exact sequential 3x3 conv on a boundary frame of width FW.
// ---------------------------------------------------------------------------
template<int CO, int CI, int FW, bool REAL_IN, bool WTIK>
__global__ __launch_bounds__(256)
void k_conv_strip(const void* __restrict__ Xv, float2* __restrict__ Y,
                  const float* __restrict__ wr, const float* __restrict__ wi,
                  int conjt, const float* __restrict__ wtr,
                  const float* __restrict__ wti)
{
    int b = blockIdx.y;
    __shared__ float2 ws[CO * CI * 9];
    int t = threadIdx.x;
    if (t < CO * CI * 9) {
        int o = t / (CI * 9), rem = t % (CI * 9), i = rem / 9, tap = rem % 9;
        int dy = tap / 3, dx = tap % 3;
        long long widx;
        float sgn;
        if (conjt) { widx = ((long long)(b * CI + i) * CO + o) * 9 + dx * 3 + dy; sgn = -1.f; }
        else       { widx = ((long long)(b * CO + o) * CI + i) * 9 + dy * 3 + dx; sgn =  1.f; }
        ws[t] = make_float2(wr[widx], sgn * wi[widx]);
    }
    __syncthreads();

    const int nTop = FW * NG;
    const int nSide = (NG - 2 * FW) * FW;
    const int total = 2 * nTop + 2 * nSide;
    int idx = blockIdx.x * 256 + t;
    if (idx >= total) return;
    int p, q;
    if (idx < nTop)            { p = idx / NG; q = idx - p * NG; }
    else if (idx < 2 * nTop)   { int k2 = idx - nTop; p = NG - FW + k2 / NG; q = k2 % NG; }
    else if (idx < 2 * nTop + nSide) { int k2 = idx - 2 * nTop; p = FW + k2 / FW; q = k2 % FW; }
    else                       { int k2 = idx - 2 * nTop - nSide; p = FW + k2 / FW; q = NG - FW + k2 % FW; }

    float2 acc[CO];
#pragma unroll
    for (int o = 0; o < CO; o++) acc[o] = make_float2(0.f, 0.f);
#pragma unroll
    for (int i = 0; i < CI; i++) {
#pragma unroll
        for (int dy = 0; dy < 3; dy++) {
            int ii = p + dy - 1;
#pragma unroll
            for (int dx = 0; dx < 3; dx++) {
                int jj = q + dx - 1;
                float2 xv = make_float2(0.f, 0.f);
                if (ii >= 0 && ii < NG && jj >= 0 && jj < NG) {
                    if (REAL_IN) {
                        const float* Xb = (const float*)Xv + (long long)b * NN;
                        xv.x = Xb[(long long)ii * NG + jj];
                    } else {
                        const float2* Xb = (const float2*)Xv + (long long)b * CI * NN;
                        xv = Xb[(long long)i * NN + (long long)ii * NG + jj];
                    }
                }
                int tap = dy * 3 + dx;
#pragma unroll
                for (int o = 0; o < CO; o++)
                    acc[o] = cmad(acc[o], xv, ws[(o * CI + i) * 9 + tap]);
            }
        }
    }
    float2* Yb = Y + (long long)b * CO * NN;
    long long po = (long long)p * NG + q;
    if (WTIK) {
        long long o = (long long)b * NN + po;
        Yb[po] = wtik_apply(acc[0], wtr[o], wti[o], p, q);
    } else {
#pragma unroll
        for (int o = 0; o < CO; o++) Yb[(long long)o * NN + po] = acc[o];
    }
}

// ---------------------------------------------------------------------------
// Reductions (deterministic, double accumulation)
// ---------------------------------------------------------------------------
__global__ __launch_bounds__(256)
void k_alpha_part(const float* __restrict__ r, const float* __restrict__ e,
                  const float* __restrict__ a, double* __restrict__ p1,
                  double* __restrict__ p2)
{
    int b = blockIdx.y;
    const float* rb = r + (long long)b * NN;
    const float* eb = e + (long long)b * NN;
    const float* ab = a + (long long)b * NCC;
    double num = 0.0, den = 0.0;
    for (long long idx = (long long)blockIdx.x * 256 + threadIdx.x; idx < NN;
         idx += (long long)gridDim.x * 256) {
        int i = (int)(idx / NG), j = (int)(idx - (long long)i * NG);
        float ev = eb[idx];
        num += (double)(rb[idx] * ev);
        if (i > 0 && j > 0 && i < NG - 1 && j < NG - 1) {
            float d = darcy_at(eb, ab, i, j);
            den += (double)(d * ev);
        }
    }
    __shared__ double s1[256], s2[256];
    int t = threadIdx.x;
    s1[t] = num; s2[t] = den;
    __syncthreads();
    for (int s = 128; s > 0; s >>= 1) {
        if (t < s) { s1[t] += s1[t + s]; s2[t] += s2[t + s]; }
        __syncthreads();
    }
    if (t == 0) { p1[b * NBLK_A + blockIdx.x] = s1[0]; p2[b * NBLK_A + blockIdx.x] = s2[0]; }
}

__global__ void k_alpha_fin(const double* __restrict__ p1,
                            const double* __restrict__ p2,
                            float* __restrict__ alpha)
{
    int b = blockIdx.x;
    __shared__ double s1[256], s2[256];
    double n = 0.0, d = 0.0;
    for (int i = threadIdx.x; i < NBLK_A; i += 256) {
        n += p1[b * NBLK_A + i]; d += p2[b * NBLK_A + i];
    }
    int t = threadIdx.x;
    s1[t] = n; s2[t] = d;
    __syncthreads();
    for (int s = 128; s > 0; s >>= 1) {
        if (t < s) { s1[t] += s1[t + s]; s2[t] += s2[t + s]; }
        __syncthreads();
    }
    if (t == 0) alpha[b] = (float)(s1[0] / s2[0]);
}

__global__ void k_update(float* __restrict__ x, const float* __restrict__ e,
                         const float* __restrict__ alpha)
{
    int b = blockIdx.z;
    int j = blockIdx.x * 16 + threadIdx.x + 1;
    int i = blockIdx.y * 16 + threadIdx.y + 1;
    if (i > NI || j > NI) return;
    long long o = (long long)b * NN + (long long)i * NG + j;
    x[o] = fmaf(alpha[b], e[o], x[o]);
}

__global__ __launch_bounds__(256)
void k_norm_part(const float* __restrict__ r, const float* __restrict__ f,
                 double* __restrict__ p1, double* __restrict__ p2)
{
    double sr = 0.0, sf = 0.0;
    long long tot = (long long)NB * NN;
    for (long long idx = (long long)blockIdx.x * 256 + threadIdx.x; idx < tot;
         idx += (long long)gridDim.x * 256) {
        float rv = r[idx], fv = f[idx];
        sr += (double)rv * rv;
        sf += (double)fv * fv;
    }
    __shared__ double s1[256], s2[256];
    int t = threadIdx.x;
    s1[t] = sr; s2[t] = sf;
    __syncthreads();
    for (int s = 128; s > 0; s >>= 1) {
        if (t < s) { s1[t] += s1[t + s]; s2[t] += s2[t + s]; }
        __syncthreads();
    }
    if (t == 0) { p1[blockIdx.x] = s1[0]; p2[blockIdx.x] = s2[0]; }
}

__global__ void k_norm_fin(const double* __restrict__ p1,
                           const double* __restrict__ p2,
                           float* __restrict__ out)
{
    __shared__ double s1[256], s2[256];
    double a = 0.0, b = 0.0;
    for (int i = threadIdx.x; i < NBLK_N; i += 256) { a += p1[i]; b += p2[i]; }
    int t = threadIdx.x;
    s1[t] = a; s2[t] = b;
    __syncthreads();
    for (int s = 128; s > 0; s >>= 1) {
        if (t < s) { s1[t] += s1[t + s]; s2[t] += s2[t + s]; }
        __syncthreads();
    }
    if (t == 0) out[0] = (float)sqrt(s1[0] / s2[0]);
}

// ---------------------------------------------------------------------------
// Host orchestration
// ---------------------------------------------------------------------------
template<typename T>
static T* sym_addr(const void* sym)
{
    void* p = nullptr;
    cudaGetSymbolAddress(&p, sym);
    return (T*)p;
}

static inline int strip_blocks(int FW)
{
    int nTop = FW * NG, nSide = (NG - 2 * FW) * FW;
    int total = 2 * nTop + 2 * nSide;
    return (total + 255) / 256;
}

extern "C" void kernel_launch(void* const* d_in, const int* in_sizes, int n_in,
                              void* d_out, int out_size)
{
    const float* f    = (const float*)d_in[0];
    const float* coef = (const float*)d_in[1];
    const float* w1r = (const float*)d_in[3];
    const float* w1i = (const float*)d_in[4];
    const float* w2r = (const float*)d_in[5];
    const float* w2i = (const float*)d_in[6];
    const float* w3r = (const float*)d_in[7];
    const float* w3i = (const float*)d_in[8];
    const float* wtr = (const float*)d_in[9];
    const float* wti = (const float*)d_in[10];

    float*  x    = sym_addr<float>(g_x);
    float*  x2   = sym_addr<float>(g_x2);
    float*  r    = sym_addr<float>(g_r);
    float*  e    = sym_addr<float>(g_e);
    float*  rh   = sym_addr<float>(g_rh);
    float*  dinv = sym_addr<float>(g_dinv);
    float*  S    = sym_addr<float>(g_S);
    float*  St   = sym_addr<float>(g_St);
    float*  U    = sym_addr<float>(g_U);
    float2* cA   = sym_addr<float2>(g_cA);
    float2* cB   = sym_addr<float2>(g_cB);
    float2* cC   = sym_addr<float2>(g_cC);
    float2* cD   = sym_addr<float2>(g_cD);
    float2* wf   = sym_addr<float2>(g_wf);
    float*  Wr   = sym_addr<float>(g_Wr);
    float*  Wi   = sym_addr<float>(g_Wi);
    float*  A1   = sym_addr<float>(g_A1);
    float*  A2   = sym_addr<float>(g_A2);
    float*  F    = sym_addr<float>(g_F);
    float*  Bm   = sym_addr<float>(g_Bm);
    float*  Em   = sym_addr<float>(g_Em);
    double* pd1  = sym_addr<double>(g_pd1);
    double* pd2  = sym_addr<double>(g_pd2);
    float*  alph = sym_addr<float>(g_alpha);

    dim3 blk2(16, 16);
    dim3 gInt((NI + 15) / 16, (NI + 15) / 16, NB);
    dim3 gFull((NG + 15) / 16, (NG + 15) / 16, NB);
    dim3 gJac(16, 16, NB);
    dim3 gConv((NG + 15) / 16, (NG + 31) / 32, NB);

    dim3 gS5(strip_blocks(5), NB);
    dim3 gS4(strip_blocks(4), NB);
    dim3 gS3(strip_blocks(3), NB);

    dim3 blkF(32, 8);
    dim3 gF1((NK + 31) / 32, (NG + 7) / 8, NB);
    dim3 gF2((NI + 31) / 32, (NK + 7) / 8, NB);

    // ---- setup ----
    {
        long long tot = (long long)NB * NN;
        k_zero3<<<(int)((tot + 255) / 256), 256>>>(x, x2, e);
        int nSG = NG * NI;
        k_precS<<<(nSG + 255) / 256, 256>>>(S, St);
        int nB = (int)(NK2 * (long long)NI);
        k_precB<<<(nB + 255) / 256, 256>>>(Bm);
        int nE = (int)((long long)NI * NK2);
        k_precE<<<(nE + 255) / 256, 256>>>(Em);
        k_dinv<<<gInt, blk2>>>(coef, dinv);
        k_compose<<<NB, 64>>>(w1r, w1i, w2r, w2i, w3r, w3i, wf);
    }

    float* xa = x;
    float* xb = x2;

    for (int step = 0; step < KSTEPS; step++) {
        // ---- 10 Jacobi sweeps ----
        for (int it = 0; it < 10; it++) {
            k_jacobi2<<<gJac, blk2>>>(xa, xb, f, coef, dinv);
            float* tmp = xa; xa = xb; xb = tmp;
        }
        // ---- residual ----
        k_resid<<<gFull, blk2>>>(xa, f, coef, r);

        // ---- forward sine transform (odd symmetry fused in epilogue) ----
        {
            dim3 g((257 + 63) / 64, (NI + 63) / 64, NB);
            k_sgemm<1><<<g, 256>>>(r + NG + 1, NG, NN,
                                   St + 256, NG, 0,
                                   U, NG, NIG,
                                   NI, 257, NI, 1.f);
        }
        {
            dim3 g((NG + 63) / 64, (257 + 63) / 64, NB);
            k_sgemm<2><<<g, 256>>>(S + 256 * NI, NI, 0,
                                   U, NG, NIG,
                                   rh, NG, NN,
                                   257, NG, NI, -1.f / (512.f * 512.f));
        }

        // ---- forward conv chain: composed 7x7 + exact ring correction ----
        k_conv7f<<<gConv, blk2>>>(rh, cC, wf, wtr, wti);
        k_conv_strip<4, 1, 5, true,  false><<<gS5, 256>>>(rh, cA, w1r, w1i, 0, nullptr, nullptr);
        k_conv_strip<4, 4, 4, false, false><<<gS4, 256>>>(cA, cB, w2r, w2i, 0, nullptr, nullptr);
        k_conv_strip<1, 4, 3, false, true ><<<gS3, 256>>>(cB, cC, w3r, w3i, 0, wtr, wti);

        // ---- backward conv chain: composed conj(wf^T) + ring correction ----
        k_conv7b<<<gConv, blk2>>>(cC, cD, wf);
        k_conv_strip<4, 1, 5, false, false><<<gS5, 256>>>(cC, cA, w3r, w3i, 1, nullptr, nullptr);
        k_conv_strip<4, 4, 4, false, false><<<gS4, 256>>>(cA, cB, w2r, w2i, 1, nullptr, nullptr);
        k_conv_strip<1, 4, 3, false, false><<<gS3, 256>>>(cB, cD, w1r, w1i, 1, nullptr, nullptr);

        // ---- inverse transform via conjugate-fold: all REAL GEMMs ----
        // fold cD columns -> A1=[Pr|-Mi], A2=[Pi|Mr]
        k_fold1<<<gF1, blkF>>>(cD, A1, A2);
        // Wr = A1 * [C;S], Wi = A2 * [C;S]   (513 x 516 x 511)
        {
            dim3 g((NI + 63) / 64, (NG + 63) / 64, NB);
            k_sgemm<0><<<g, 256>>>(A1, NK2, NA, Bm, NI, 0, Wr, NI, NIG,
                                   NG, NI, NK2, 1.f);
            k_sgemm<0><<<g, 256>>>(A2, NK2, NA, Bm, NI, 0, Wi, NI, NIG,
                                   NG, NI, NK2, 1.f);
        }
        // fold W rows -> F = [Wr+ + Wr- ; Wi+ - Wi-]
        k_fold2<<<gF2, blkF>>>(Wr, Wi, F);
        // e_int = [Cos|Sin] * F   (511 x 516 x 511)
        {
            dim3 g((NI + 63) / 64, (NI + 63) / 64, NB);
            k_sgemm<0><<<g, 256>>>(Em, NK2, 0, F, NI, NF, e + NG + 1, NG, NN,
                                   NI, NI, NK2, 1.f);
        }

        // ---- alpha and update ----
        {
            dim3 g(NBLK_A, NB);
            k_alpha_part<<<g, 256>>>(r, e, coef, pd1, pd2);
            k_alpha_fin<<<NB, 256>>>(pd1, pd2, alph);
            k_update<<<gInt, blk2>>>(xa, e, alph);
        }
    }

    // ---- final relative residual norm ----
    k_resid<<<gFull, blk2>>>(xa, f, coef, r);
    k_norm_part<<<NBLK_N, 256>>>(r, f, pd1, pd2);
    k_norm_fin<<<1, 256>>>(pd1, pd2, (float*)d_out);
}